// round 7
// baseline (speedup 1.0000x reference)
#include <cuda_runtime.h>
#include <cuda_bf16.h>
#include <math_constants.h>
#include <cstdint>

// Problem constants
#define BB 4
#define TT 2048
#define EE 1024
#define HH 16
#define DD 64
#define BT (BB*TT)          // 8192
#define NQKV 3072

#define L2E 1.44269504f
#define SCALE_Q (0.125f * L2E)    // fold 1/sqrt(D) and log2(e) into q

// ---------------------------------------------------------------------------
// Scratch (allocation-free rule: __device__ globals)
// ---------------------------------------------------------------------------
__device__ __align__(16) float g_ctx[(size_t)BB*TT*EE];     // [B,T,H*D]

__device__ __align__(16) __nv_bfloat16 g_xhi[(size_t)BT*EE];
__device__ __align__(16) __nv_bfloat16 g_xlo[(size_t)BT*EE];
__device__ __align__(16) __nv_bfloat16 g_wth[(size_t)NQKV*EE];
__device__ __align__(16) __nv_bfloat16 g_wtl[(size_t)NQKV*EE];
__device__ __align__(16) __nv_bfloat16 g_woh[(size_t)EE*EE];
__device__ __align__(16) __nv_bfloat16 g_wol[(size_t)EE*EE];
__device__ __align__(16) __nv_bfloat16 g_chi[(size_t)BT*EE];
__device__ __align__(16) __nv_bfloat16 g_clo[(size_t)BT*EE];

// bf16 hi/lo q,k,v in [B,H,T,D]
__device__ __align__(16) __nv_bfloat16 g_qh[(size_t)BB*HH*TT*DD];
__device__ __align__(16) __nv_bfloat16 g_ql[(size_t)BB*HH*TT*DD];
__device__ __align__(16) __nv_bfloat16 g_kh[(size_t)BB*HH*TT*DD];
__device__ __align__(16) __nv_bfloat16 g_kl[(size_t)BB*HH*TT*DD];
__device__ __align__(16) __nv_bfloat16 g_vh[(size_t)BB*HH*TT*DD];
__device__ __align__(16) __nv_bfloat16 g_vl[(size_t)BB*HH*TT*DD];

// ---------------------------------------------------------------------------
// Helpers (base sm_103 ISA: mma.sync / ldmatrix / cp.async)
// ---------------------------------------------------------------------------
__device__ __forceinline__ uint32_t smem_u32(const void* p) {
    uint32_t a;
    asm("{ .reg .u64 t; cvta.to.shared.u64 t, %1; cvt.u32.u64 %0, t; }"
        : "=r"(a) : "l"(p));
    return a;
}

#define LDSM4(r, addr) \
    asm volatile("ldmatrix.sync.aligned.m8n8.x4.shared.b16 {%0,%1,%2,%3}, [%4];" \
        : "=r"((r)[0]), "=r"((r)[1]), "=r"((r)[2]), "=r"((r)[3]) : "r"(addr))

#define LDSM4T(r, addr) \
    asm volatile("ldmatrix.sync.aligned.m8n8.x4.trans.shared.b16 {%0,%1,%2,%3}, [%4];" \
        : "=r"((r)[0]), "=r"((r)[1]), "=r"((r)[2]), "=r"((r)[3]) : "r"(addr))

#define MMA16816(c, a, b0, b1) \
    asm volatile("mma.sync.aligned.m16n8k16.row.col.f32.bf16.bf16.f32 " \
        "{%0,%1,%2,%3}, {%4,%5,%6,%7}, {%8,%9}, {%0,%1,%2,%3};" \
        : "+f"((c)[0]), "+f"((c)[1]), "+f"((c)[2]), "+f"((c)[3]) \
        : "r"((a)[0]), "r"((a)[1]), "r"((a)[2]), "r"((a)[3]), "r"(b0), "r"(b1))

#define CP_ASYNC16(dst, src) \
    asm volatile("cp.async.cg.shared.global [%0], [%1], 16;" :: "r"(dst), "l"(src))
#define CP_COMMIT() asm volatile("cp.async.commit_group;" ::: "memory")
#define CP_WAIT(n)  asm volatile("cp.async.wait_group %0;" :: "n"(n) : "memory")

// split two floats into packed bf16x2 hi and lo residual
__device__ __forceinline__ void split2(float a, float b, uint32_t& hi, uint32_t& lo) {
    __nv_bfloat16 ha = __float2bfloat16(a), hb = __float2bfloat16(b);
    float ra = a - __bfloat162float(ha);
    float rb = b - __bfloat162float(hb);
    __nv_bfloat162 H; H.x = ha; H.y = hb;
    __nv_bfloat162 L; L.x = __float2bfloat16(ra); L.y = __float2bfloat16(rb);
    hi = *(uint32_t*)&H;
    lo = *(uint32_t*)&L;
}

// fast exp2 on the FMA pipe (degree-7, rel err ~1e-6)
__device__ __forceinline__ float exp2fast(float x) {
    x = fmaxf(x, -125.0f);
    int n = __float2int_rd(x);
    float f = x - (float)n;
    float p = 1.3570247e-5f;
    p = fmaf(p, f, 1.5353362e-4f);
    p = fmaf(p, f, 1.3398874e-3f);
    p = fmaf(p, f, 9.6184374e-3f);
    p = fmaf(p, f, 5.5503325e-2f);
    p = fmaf(p, f, 2.4022648e-1f);
    p = fmaf(p, f, 6.9314720e-1f);
    p = fmaf(p, f, 1.0f);
    return p * __int_as_float((n + 127) << 23);
}

// ---------------------------------------------------------------------------
// Prep: fp32 -> (bf16 hi, bf16 lo)
// ---------------------------------------------------------------------------
__global__ __launch_bounds__(256) void conv_hilo(
    const float* __restrict__ s, __nv_bfloat16* __restrict__ hi,
    __nv_bfloat16* __restrict__ lo, int n4)
{
    int i = blockIdx.x * 256 + threadIdx.x;
    if (i >= n4) return;
    float4 v = ((const float4*)s)[i];
    uint32_t h0, l0, h1, l1;
    split2(v.x, v.y, h0, l0);
    split2(v.z, v.w, h1, l1);
    ((uint32_t*)hi)[i * 2 + 0] = h0;
    ((uint32_t*)hi)[i * 2 + 1] = h1;
    ((uint32_t*)lo)[i * 2 + 0] = l0;
    ((uint32_t*)lo)[i * 2 + 1] = l1;
}

// ---------------------------------------------------------------------------
// Prep: transpose+split qkv weights. W[h][e][d] -> Wt[n][e]
// ---------------------------------------------------------------------------
__global__ __launch_bounds__(256) void prep_wt(
    const float* __restrict__ Wq, const float* __restrict__ Wk,
    const float* __restrict__ Wv,
    __nv_bfloat16* __restrict__ th, __nv_bfloat16* __restrict__ tl)
{
    __shared__ float ts[64][65];
    const int bx = blockIdx.x;
    const int mi = bx >> 8;
    const int rem = bx & 255;
    const int h = rem >> 4;
    const int e0 = (rem & 15) * 64;
    const float* src = (mi == 0 ? Wq : (mi == 1 ? Wk : Wv)) + (size_t)h * EE * DD;
    const int tid = threadIdx.x;

    #pragma unroll
    for (int i = 0; i < 4; ++i) {
        int idx = tid + i * 256;
        int ei = idx >> 4, d4 = idx & 15;
        float4 v = ((const float4*)(src + (size_t)(e0 + ei) * DD))[d4];
        ts[ei][d4 * 4 + 0] = v.x; ts[ei][d4 * 4 + 1] = v.y;
        ts[ei][d4 * 4 + 2] = v.z; ts[ei][d4 * 4 + 3] = v.w;
    }
    __syncthreads();

    const int d = tid >> 2, seg = tid & 3;
    const size_t row = ((size_t)mi * 1024 + h * 64 + d) * EE + e0 + seg * 16;
    alignas(16) __nv_bfloat16 hb[16], lb[16];
    #pragma unroll
    for (int i = 0; i < 16; ++i) {
        float v = ts[seg * 16 + i][d];
        __nv_bfloat16 hv = __float2bfloat16(v);
        hb[i] = hv;
        lb[i] = __float2bfloat16(v - __bfloat162float(hv));
    }
    *(uint4*)(th + row)     = *(const uint4*)(hb);
    *(uint4*)(th + row + 8) = *(const uint4*)(hb + 8);
    *(uint4*)(tl + row)     = *(const uint4*)(lb);
    *(uint4*)(tl + row + 8) = *(const uint4*)(lb + 8);
}

// ---------------------------------------------------------------------------
// HMMA split-bf16 GEMM, 128Mx64N block, warp 32x32, 2 CTAs/SM.
// 3-stage cp.async ring, loads issued BEFORE compute, ONE barrier per chunk.
// ---------------------------------------------------------------------------
#define PITCH 40
#define A_ELEMS (128 * PITCH)            // 5120
#define B_ELEMS (64 * PITCH)             // 2560
#define STAGE_ELEMS (2 * A_ELEMS + 2 * B_ELEMS)   // 15360
#define STAGE_BYTES (STAGE_ELEMS * 2)    // 30720
#define NSTAGE 3

__global__ __launch_bounds__(256, 2)
void mma_gemm(const __nv_bfloat16* __restrict__ Ah, const __nv_bfloat16* __restrict__ Al,
              const __nv_bfloat16* __restrict__ Bh, const __nv_bfloat16* __restrict__ Bl,
              const float* __restrict__ bias,
              __nv_bfloat16* __restrict__ qh, __nv_bfloat16* __restrict__ ql,
              __nv_bfloat16* __restrict__ kh, __nv_bfloat16* __restrict__ kl,
              __nv_bfloat16* __restrict__ vh, __nv_bfloat16* __restrict__ vl,
              float* __restrict__ oplain, int mode)
{
    extern __shared__ char sm[];
    const uint32_t sbase = smem_u32(sm);
    const int tid = threadIdx.x;
    const int wid = tid >> 5, lane = tid & 31;
    const int wm = wid & 3, wn = wid >> 2;       // 4 M-warps x 2 N-warps
    const int n0 = blockIdx.x * 64;
    const int m0 = blockIdx.y * 128;

    const int a_row = lane & 15;
    const int a_col = (lane >> 4) << 3;
    const int b_row = ((lane >> 4) << 3) + (lane & 7);
    const int b_col = ((lane >> 3) & 1) << 3;

    float c[2][4][4] = {};    // warp tile 32x32

    auto stage_load = [&](int buf, int k0) {
        #pragma unroll
        for (int t = 0; t < 6; ++t) {
            const int idx = t * 256 + tid;       // 0..1535
            if (idx < 1024) {                    // A arrays
                const int arr = idx >> 9;        // 0:Ah 1:Al
                const int local = idx & 511;
                const int r = local >> 2, seg = local & 3;
                const __nv_bfloat16* g = (arr ? Al : Ah)
                    + (size_t)(m0 + r) * EE + k0 + seg * 8;
                uint32_t dst = sbase + buf * STAGE_BYTES
                    + (uint32_t)(arr * A_ELEMS + r * PITCH + seg * 8) * 2;
                CP_ASYNC16(dst, g);
            } else {                             // B arrays
                const int j = idx - 1024;
                const int arr = j >> 8;          // 0:Bh 1:Bl
                const int local = j & 255;
                const int r = local >> 2, seg = local & 3;
                const __nv_bfloat16* g = (arr ? Bl : Bh)
                    + (size_t)(n0 + r) * EE + k0 + seg * 8;
                uint32_t dst = sbase + buf * STAGE_BYTES
                    + (uint32_t)(2 * A_ELEMS + arr * B_ELEMS + r * PITCH + seg * 8) * 2;
                CP_ASYNC16(dst, g);
            }
        }
        CP_COMMIT();
    };

    stage_load(0, 0);
    stage_load(1, 32);

    for (int ch = 0; ch < 32; ++ch) {
        if (ch < 31) CP_WAIT(1);
        else         CP_WAIT(0);
        __syncthreads();
        // issue loads for ch+2 NOW (overwrites buffer read in ch-1; safe after barrier)
        if (ch + 2 < 32) stage_load((ch + 2) % NSTAGE, (ch + 2) * 32);

        const uint32_t sAh = sbase + (ch % NSTAGE) * STAGE_BYTES;
        const uint32_t sAl = sAh + A_ELEMS * 2;
        const uint32_t sBh = sAh + 2 * A_ELEMS * 2;
        const uint32_t sBl = sBh + B_ELEMS * 2;

        #pragma unroll
        for (int ks = 0; ks < 2; ++ks) {
            uint32_t ah[2][4], alr[2][4], bh[2][4], bl[2][4];
            #pragma unroll
            for (int mi = 0; mi < 2; ++mi) {
                uint32_t off = (uint32_t)((wm * 32 + mi * 16 + a_row) * PITCH
                                          + ks * 16 + a_col) * 2;
                LDSM4(ah[mi],  sAh + off);
                LDSM4(alr[mi], sAl + off);
            }
            #pragma unroll
            for (int jp = 0; jp < 2; ++jp) {
                uint32_t off = (uint32_t)((wn * 32 + jp * 16 + b_row) * PITCH
                                          + ks * 16 + b_col) * 2;
                LDSM4(bh[jp], sBh + off);
                LDSM4(bl[jp], sBl + off);
            }
            #pragma unroll
            for (int p = 0; p < 3; ++p)
                #pragma unroll
                for (int mi = 0; mi < 2; ++mi)
                    #pragma unroll
                    for (int nt = 0; nt < 4; ++nt) {
                        const int jp = nt >> 1, q = (nt & 1) * 2;
                        if (p == 0)
                            MMA16816(c[mi][nt], ah[mi],  bh[jp][q], bh[jp][q + 1]);
                        else if (p == 1)
                            MMA16816(c[mi][nt], ah[mi],  bl[jp][q], bl[jp][q + 1]);
                        else
                            MMA16816(c[mi][nt], alr[mi], bh[jp][q], bh[jp][q + 1]);
                    }
        }
    }

    const int rbase = m0 + wm * 32 + (lane >> 2);
    const int cpair = (lane & 3) * 2;

    if (mode == 0) {
        const int which = n0 >> 10;              // 64-wide tile = exactly one head
        __nv_bfloat16 *dh, *dl;
        if (which == 0)      { dh = qh; dl = ql; }
        else if (which == 1) { dh = kh; dl = kl; }
        else                 { dh = vh; dl = vl; }
        const float sc = (which == 0) ? SCALE_Q : 1.0f;
        const int h = (n0 & 1023) >> 6;
        #pragma unroll
        for (int mi = 0; mi < 2; ++mi) {
            const int m1 = rbase + mi * 16;
            const int m2 = m1 + 8;
            const size_t base1 = (((size_t)(m1 >> 11) * HH + h) * TT + (m1 & 2047)) * DD;
            const size_t base2 = (((size_t)(m2 >> 11) * HH + h) * TT + (m2 & 2047)) * DD;
            #pragma unroll
            for (int nt = 0; nt < 4; ++nt) {
                const int d = wn * 32 + nt * 8 + cpair;
                uint32_t h1, l1, h2, l2;
                split2(c[mi][nt][0] * sc, c[mi][nt][1] * sc, h1, l1);
                split2(c[mi][nt][2] * sc, c[mi][nt][3] * sc, h2, l2);
                *(uint32_t*)(dh + base1 + d) = h1;
                *(uint32_t*)(dl + base1 + d) = l1;
                *(uint32_t*)(dh + base2 + d) = h2;
                *(uint32_t*)(dl + base2 + d) = l2;
            }
        }
    } else {
        #pragma unroll
        for (int mi = 0; mi < 2; ++mi) {
            const int m1 = rbase + mi * 16;
            float* r1 = oplain + (size_t)m1 * EE;
            float* r2 = oplain + (size_t)(m1 + 8) * EE;
            #pragma unroll
            for (int nt = 0; nt < 4; ++nt) {
                const int col = n0 + wn * 32 + nt * 8 + cpair;
                const float b0 = bias[col], b1v = bias[col + 1];
                float2 v1 = make_float2(c[mi][nt][0] + b0, c[mi][nt][1] + b1v);
                float2 v2 = make_float2(c[mi][nt][2] + b0, c[mi][nt][3] + b1v);
                *(float2*)(r1 + col) = v1;
                *(float2*)(r2 + col) = v2;
            }
        }
    }
}

// ---------------------------------------------------------------------------
// Tensor-core causal flash attention, 3-stage KV ring, one barrier per tile.
// ---------------------------------------------------------------------------
#define AP 72
#define SM_Q 0
#define QARR (128 * AP * 2)
#define SM_STAGE (2 * QARR)
#define KVARR (64 * AP * 2)
#define STAGE_SZ (4 * KVARR)
#define SM_MASK (SM_STAGE + 3 * STAGE_SZ)
#define SM_TOTAL (SM_MASK + 3 * 256 + 256)

__global__ __launch_bounds__(256, 1)
void attn_mma(const __nv_bfloat16* __restrict__ qh, const __nv_bfloat16* __restrict__ ql,
              const __nv_bfloat16* __restrict__ kh, const __nv_bfloat16* __restrict__ kl,
              const __nv_bfloat16* __restrict__ vh, const __nv_bfloat16* __restrict__ vl,
              const float* __restrict__ amask, float* __restrict__ ctx)
{
    extern __shared__ char sm[];
    const uint32_t sbase = smem_u32(sm);
    const int tid = threadIdx.x;
    const int w = tid >> 5, lane = tid & 31;
    const int bh = blockIdx.x;
    const int b_ = bh >> 4, h = bh & 15;
    const int qt = 15 - blockIdx.y;
    const int q0 = qt * 128;
    const int last = 2 * qt + 1;

    const int a_row = lane & 15;
    const int a_col = (lane >> 4) << 3;
    const int b_row = ((lane >> 4) << 3) + (lane & 7);
    const int b_col = ((lane >> 3) & 1) << 3;
    const int v_key = (lane & 7) + (((lane >> 3) & 1) << 3);
    const int v_d   = (lane >> 4) << 3;

    const size_t gbase = (size_t)bh * TT * DD;

    auto load_q = [&]() {
        #pragma unroll
        for (int arr = 0; arr < 2; ++arr) {
            const __nv_bfloat16* src0 = arr ? ql : qh;
            #pragma unroll
            for (int half = 0; half < 4; ++half) {
                int loc = half * 256 + tid;
                int r = loc >> 3, seg = loc & 7;
                const __nv_bfloat16* src = src0 + gbase + (size_t)(q0 + r) * DD + seg * 8;
                uint32_t dst = sbase + SM_Q + arr * QARR + (uint32_t)(r * AP + seg * 8) * 2;
                CP_ASYNC16(dst, src);
            }
        }
    };
    auto load_kv = [&](int buf, int kt) {
        const int s0 = kt * 64;
        #pragma unroll
        for (int arr = 0; arr < 4; ++arr) {
            const __nv_bfloat16* src0 = (arr == 0) ? kh : (arr == 1) ? kl
                                       : (arr == 2) ? vh : vl;
            #pragma unroll
            for (int half = 0; half < 2; ++half) {
                int loc = half * 256 + tid;
                int r = loc >> 3, seg = loc & 7;
                const __nv_bfloat16* src = src0 + gbase + (size_t)(s0 + r) * DD + seg * 8;
                uint32_t dst = sbase + SM_STAGE + buf * STAGE_SZ + arr * KVARR
                             + (uint32_t)(r * AP + seg * 8) * 2;
                CP_ASYNC16(dst, src);
            }
        }
        if (tid < 16) {
            const float* msrc = amask + (size_t)b_ * TT + s0 + tid * 4;
            uint32_t mdst = sbase + SM_MASK + buf * 256 + tid * 16;
            CP_ASYNC16(mdst, msrc);
        }
        CP_COMMIT();
    };

    load_q();
    load_kv(0, 0);      // group 0 = Q + KV0
    load_kv(1, 1);      // group 1
    CP_WAIT(1);
    __syncthreads();

    uint32_t qa_h[4][4], qa_l[4][4];
    #pragma unroll
    for (int ks = 0; ks < 4; ++ks) {
        uint32_t off = (uint32_t)((w * 16 + a_row) * AP + ks * 16 + a_col) * 2;
        LDSM4(qa_h[ks], sbase + SM_Q + off);
        LDSM4(qa_l[ks], sbase + SM_Q + QARR + off);
    }

    float o[8][4] = {};
    float m0r = -1e30f, m1r = -1e30f, l0 = 0.f, l1 = 0.f;
    const int row0 = q0 + w * 16 + (lane >> 2);
    const int wrow_hi = q0 + w * 16 + 15;

    for (int kt = 0; kt <= last; ++kt) {
        if (kt > 0) {
            if (kt < last) CP_WAIT(1);
            else           CP_WAIT(0);
            __syncthreads();
        }
        if (kt + 2 <= last) load_kv((kt + 2) % 3, kt + 2);

        const int buf = kt % 3;
        const int s0 = kt * 64;
        const bool active = (s0 <= wrow_hi);

        if (active) {
            const uint32_t kb = sbase + SM_STAGE + buf * STAGE_SZ;
            float c[8][4] = {};
            #pragma unroll
            for (int ks = 0; ks < 4; ++ks) {
                uint32_t kbh[4][4], kbl[4][4];
                #pragma unroll
                for (int jp = 0; jp < 4; ++jp) {
                    uint32_t off = (uint32_t)((jp * 16 + b_row) * AP + ks * 16 + b_col) * 2;
                    LDSM4(kbh[jp], kb + off);
                    LDSM4(kbl[jp], kb + KVARR + off);
                }
                #pragma unroll
                for (int p = 0; p < 3; ++p)
                    #pragma unroll
                    for (int nt = 0; nt < 8; ++nt) {
                        const int jp = nt >> 1, q = (nt & 1) * 2;
                        if (p == 0)
                            MMA16816(c[nt], qa_h[ks], kbh[jp][q], kbh[jp][q + 1]);
                        else if (p == 1)
                            MMA16816(c[nt], qa_h[ks], kbl[jp][q], kbl[jp][q + 1]);
                        else
                            MMA16816(c[nt], qa_l[ks], kbh[jp][q], kbh[jp][q + 1]);
                    }
            }
            const float* mk = (const float*)(sm + SM_MASK + buf * 256);
            const bool dg = (s0 + 63) > (q0 + w * 16);
            #pragma unroll
            for (int nt = 0; nt < 8; ++nt) {
                const int cl = nt * 8 + (lane & 3) * 2;
                const float mv0 = mk[cl], mv1 = mk[cl + 1];
                const float ma0 = (1.0f - mv0) * -1e30f;
                const float ma1 = (1.0f - mv1) * -1e30f;
                c[nt][0] += ma0; c[nt][1] += ma1;
                c[nt][2] += ma0; c[nt][3] += ma1;
                if (dg) {
                    const int cg = s0 + cl;
                    if (cg     > row0)     c[nt][0] = -1e30f;
                    if (cg + 1 > row0)     c[nt][1] = -1e30f;
                    if (cg     > row0 + 8) c[nt][2] = -1e30f;
                    if (cg + 1 > row0 + 8) c[nt][3] = -1e30f;
                }
            }
            float t0 = -1e30f, t1 = -1e30f;
            #pragma unroll
            for (int nt = 0; nt < 8; ++nt) {
                t0 = fmaxf(t0, fmaxf(c[nt][0], c[nt][1]));
                t1 = fmaxf(t1, fmaxf(c[nt][2], c[nt][3]));
            }
            t0 = fmaxf(t0, __shfl_xor_sync(0xffffffffu, t0, 1));
            t0 = fmaxf(t0, __shfl_xor_sync(0xffffffffu, t0, 2));
            t1 = fmaxf(t1, __shfl_xor_sync(0xffffffffu, t1, 1));
            t1 = fmaxf(t1, __shfl_xor_sync(0xffffffffu, t1, 2));
            const float mn0 = fmaxf(m0r, t0), mn1 = fmaxf(m1r, t1);
            const float cor0 = exp2fast(m0r - mn0), cor1 = exp2fast(m1r - mn1);
            m0r = mn0; m1r = mn1;
            l0 *= cor0; l1 *= cor1;
            #pragma unroll
            for (int nt = 0; nt < 8; ++nt) {
                o[nt][0] *= cor0; o[nt][1] *= cor0;
                o[nt][2] *= cor1; o[nt][3] *= cor1;
            }
            uint32_t pah[4][4], pal[4][4];
            float s0sum = 0.f, s1sum = 0.f;
            #pragma unroll
            for (int nt = 0; nt < 8; ++nt) {
                const float p0 = exp2fast(c[nt][0] - mn0);
                const float p1 = exp2fast(c[nt][1] - mn0);
                const float p2 = exp2fast(c[nt][2] - mn1);
                const float p3 = exp2fast(c[nt][3] - mn1);
                s0sum += p0 + p1; s1sum += p2 + p3;
                const int ks = nt >> 1;
                const int base = (nt & 1) * 2;
                split2(p0, p1, pah[ks][base], pal[ks][base]);
                split2(p2, p3, pah[ks][base + 1], pal[ks][base + 1]);
            }
            s0sum += __shfl_xor_sync(0xffffffffu, s0sum, 1);
            s0sum += __shfl_xor_sync(0xffffffffu, s0sum, 2);
            s1sum += __shfl_xor_sync(0xffffffffu, s1sum, 1);
            s1sum += __shfl_xor_sync(0xffffffffu, s1sum, 2);
            l0 += s0sum; l1 += s1sum;
            #pragma unroll
            for (int ks = 0; ks < 4; ++ks) {
                uint32_t vbh[4][4], vbl[4][4];
                #pragma unroll
                for (int jp = 0; jp < 4; ++jp) {
                    uint32_t off = (uint32_t)((ks * 16 + v_key) * AP + jp * 16 + v_d) * 2;
                    LDSM4T(vbh[jp], kb + 2 * KVARR + off);
                    LDSM4T(vbl[jp], kb + 3 * KVARR + off);
                }
                #pragma unroll
                for (int p = 0; p < 3; ++p)
                    #pragma unroll
                    for (int nt = 0; nt < 8; ++nt) {
                        const int jp = nt >> 1, q = (nt & 1) * 2;
                        if (p == 0)
                            MMA16816(o[nt], pah[ks], vbh[jp][q], vbh[jp][q + 1]);
                        else if (p == 1)
                            MMA16816(o[nt], pah[ks], vbl[jp][q], vbl[jp][q + 1]);
                        else
                            MMA16816(o[nt], pal[ks], vbh[jp][q], vbh[jp][q + 1]);
                    }
            }
        }
    }

    const float inv0 = 1.0f / l0, inv1 = 1.0f / l1;
    const int cpair = (lane & 3) * 2;
    float* r1 = ctx + ((size_t)b_ * TT + row0) * EE + h * 64;
    float* r2 = ctx + ((size_t)b_ * TT + row0 + 8) * EE + h * 64;
    #pragma unroll
    for (int nt = 0; nt < 8; ++nt) {
        const int d = nt * 8 + cpair;
        *(float2*)(r1 + d) = make_float2(o[nt][0] * inv0, o[nt][1] * inv0);
        *(float2*)(r2 + d) = make_float2(o[nt][2] * inv1, o[nt][3] * inv1);
    }
}

// ---------------------------------------------------------------------------
// Launch
// ---------------------------------------------------------------------------
extern "C" void kernel_launch(void* const* d_in, const int* in_sizes, int n_in,
                              void* d_out, int out_size)
{
    const float* x     = (const float*)d_in[0];
    const float* amask = (const float*)d_in[1];
    const float* Wq    = (const float*)d_in[2];
    const float* Wk    = (const float*)d_in[3];
    const float* Wv    = (const float*)d_in[4];
    const float* Wo    = (const float*)d_in[5];
    const float* bo    = (const float*)d_in[6];
    float* out = (float*)d_out;

    float* ctx;
    __nv_bfloat16 *xhi, *xlo, *wth, *wtl, *woh, *wol, *chi, *clo;
    __nv_bfloat16 *qh, *ql, *kh, *kl, *vh, *vl;
    cudaGetSymbolAddress((void**)&ctx, g_ctx);
    cudaGetSymbolAddress((void**)&xhi, g_xhi);
    cudaGetSymbolAddress((void**)&xlo, g_xlo);
    cudaGetSymbolAddress((void**)&wth, g_wth);
    cudaGetSymbolAddress((void**)&wtl, g_wtl);
    cudaGetSymbolAddress((void**)&woh, g_woh);
    cudaGetSymbolAddress((void**)&wol, g_wol);
    cudaGetSymbolAddress((void**)&chi, g_chi);
    cudaGetSymbolAddress((void**)&clo, g_clo);
    cudaGetSymbolAddress((void**)&qh,  g_qh);
    cudaGetSymbolAddress((void**)&ql,  g_ql);
    cudaGetSymbolAddress((void**)&kh,  g_kh);
    cudaGetSymbolAddress((void**)&kl,  g_kl);
    cudaGetSymbolAddress((void**)&vh,  g_vh);
    cudaGetSymbolAddress((void**)&vl,  g_vl);

    cudaFuncSetAttribute(mma_gemm, cudaFuncAttributeMaxDynamicSharedMemorySize,
                         NSTAGE * STAGE_BYTES);
    cudaFuncSetAttribute(attn_mma, cudaFuncAttributeMaxDynamicSharedMemorySize,
                         SM_TOTAL);

    conv_hilo<<<(BT * EE / 4) / 256, 256>>>(x, xhi, xlo, BT * EE / 4);
    prep_wt<<<768, 256>>>(Wq, Wk, Wv, wth, wtl);
    conv_hilo<<<(EE * EE / 4) / 256, 256>>>(Wo, woh, wol, EE * EE / 4);

    {   // QKV projection -> bf16 hi/lo q,k,v
        dim3 grid(NQKV / 64, BT / 128);
        mma_gemm<<<grid, 256, NSTAGE * STAGE_BYTES>>>(xhi, xlo, wth, wtl, nullptr,
                                                      qh, ql, kh, kl, vh, vl,
                                                      nullptr, 0);
    }
    {   // attention
        dim3 grid(BB * HH, TT / 128);
        attn_mma<<<grid, 256, SM_TOTAL>>>(qh, ql, kh, kl, vh, vl, amask, ctx);
    }
    conv_hilo<<<(BT * EE / 4) / 256, 256>>>(ctx, chi, clo, BT * EE / 4);
    {   // output projection
        dim3 grid(EE / 64, BT / 128);
        mma_gemm<<<grid, 256, NSTAGE * STAGE_BYTES>>>(chi, clo, woh, wol, bo,
                                                      nullptr, nullptr, nullptr,
                                                      nullptr, nullptr, nullptr,
                                                      out, 1);
    }
}

// round 8
// speedup vs baseline: 1.0842x; 1.0842x over previous
#include <cuda_runtime.h>
#include <cuda_bf16.h>
#include <math_constants.h>
#include <cstdint>

// Problem constants
#define BB 4
#define TT 2048
#define EE 1024
#define HH 16
#define DD 64
#define BT (BB*TT)          // 8192
#define NQKV 3072

#define L2E 1.44269504f
#define SCALE_Q (0.125f * L2E)    // fold 1/sqrt(D) and log2(e) into q

// ---------------------------------------------------------------------------
// Scratch (allocation-free rule: __device__ globals)
// ---------------------------------------------------------------------------
__device__ __align__(16) float g_ctx[(size_t)BB*TT*EE];     // [B,T,H*D]

__device__ __align__(16) __nv_bfloat16 g_xhi[(size_t)BT*EE];
__device__ __align__(16) __nv_bfloat16 g_xlo[(size_t)BT*EE];
__device__ __align__(16) __nv_bfloat16 g_wth[(size_t)NQKV*EE];
__device__ __align__(16) __nv_bfloat16 g_wtl[(size_t)NQKV*EE];
__device__ __align__(16) __nv_bfloat16 g_woh[(size_t)EE*EE];
__device__ __align__(16) __nv_bfloat16 g_wol[(size_t)EE*EE];
__device__ __align__(16) __nv_bfloat16 g_chi[(size_t)BT*EE];
__device__ __align__(16) __nv_bfloat16 g_clo[(size_t)BT*EE];

// bf16 hi/lo q,k,v in [B,H,T,D]
__device__ __align__(16) __nv_bfloat16 g_qh[(size_t)BB*HH*TT*DD];
__device__ __align__(16) __nv_bfloat16 g_ql[(size_t)BB*HH*TT*DD];
__device__ __align__(16) __nv_bfloat16 g_kh[(size_t)BB*HH*TT*DD];
__device__ __align__(16) __nv_bfloat16 g_kl[(size_t)BB*HH*TT*DD];
__device__ __align__(16) __nv_bfloat16 g_vh[(size_t)BB*HH*TT*DD];
__device__ __align__(16) __nv_bfloat16 g_vl[(size_t)BB*HH*TT*DD];

// ---------------------------------------------------------------------------
// Helpers (base sm_103 ISA: mma.sync / ldmatrix / cp.async)
// ---------------------------------------------------------------------------
__device__ __forceinline__ uint32_t smem_u32(const void* p) {
    uint32_t a;
    asm("{ .reg .u64 t; cvta.to.shared.u64 t, %1; cvt.u32.u64 %0, t; }"
        : "=r"(a) : "l"(p));
    return a;
}

#define LDSM4(r, addr) \
    asm volatile("ldmatrix.sync.aligned.m8n8.x4.shared.b16 {%0,%1,%2,%3}, [%4];" \
        : "=r"((r)[0]), "=r"((r)[1]), "=r"((r)[2]), "=r"((r)[3]) : "r"(addr))

#define LDSM4T(r, addr) \
    asm volatile("ldmatrix.sync.aligned.m8n8.x4.trans.shared.b16 {%0,%1,%2,%3}, [%4];" \
        : "=r"((r)[0]), "=r"((r)[1]), "=r"((r)[2]), "=r"((r)[3]) : "r"(addr))

#define MMA16816(c, a, b0, b1) \
    asm volatile("mma.sync.aligned.m16n8k16.row.col.f32.bf16.bf16.f32 " \
        "{%0,%1,%2,%3}, {%4,%5,%6,%7}, {%8,%9}, {%0,%1,%2,%3};" \
        : "+f"((c)[0]), "+f"((c)[1]), "+f"((c)[2]), "+f"((c)[3]) \
        : "r"((a)[0]), "r"((a)[1]), "r"((a)[2]), "r"((a)[3]), "r"(b0), "r"(b1))

#define CP_ASYNC16(dst, src) \
    asm volatile("cp.async.cg.shared.global [%0], [%1], 16;" :: "r"(dst), "l"(src))
#define CP_COMMIT() asm volatile("cp.async.commit_group;" ::: "memory")
#define CP_WAIT(n)  asm volatile("cp.async.wait_group %0;" :: "n"(n) : "memory")

// split two floats into packed bf16x2 hi and lo residual
__device__ __forceinline__ void split2(float a, float b, uint32_t& hi, uint32_t& lo) {
    __nv_bfloat16 ha = __float2bfloat16(a), hb = __float2bfloat16(b);
    float ra = a - __bfloat162float(ha);
    float rb = b - __bfloat162float(hb);
    __nv_bfloat162 H; H.x = ha; H.y = hb;
    __nv_bfloat162 L; L.x = __float2bfloat16(ra); L.y = __float2bfloat16(rb);
    hi = *(uint32_t*)&H;
    lo = *(uint32_t*)&L;
}

// fast exp2 on the FMA pipe (degree-7, rel err ~1e-6)
__device__ __forceinline__ float exp2fast(float x) {
    x = fmaxf(x, -125.0f);
    int n = __float2int_rd(x);
    float f = x - (float)n;
    float p = 1.3570247e-5f;
    p = fmaf(p, f, 1.5353362e-4f);
    p = fmaf(p, f, 1.3398874e-3f);
    p = fmaf(p, f, 9.6184374e-3f);
    p = fmaf(p, f, 5.5503325e-2f);
    p = fmaf(p, f, 2.4022648e-1f);
    p = fmaf(p, f, 6.9314720e-1f);
    p = fmaf(p, f, 1.0f);
    return p * __int_as_float((n + 127) << 23);
}

// ---------------------------------------------------------------------------
// Prep: fp32 -> (bf16 hi, bf16 lo)
// ---------------------------------------------------------------------------
__global__ __launch_bounds__(256) void conv_hilo(
    const float* __restrict__ s, __nv_bfloat16* __restrict__ hi,
    __nv_bfloat16* __restrict__ lo, int n4)
{
    int i = blockIdx.x * 256 + threadIdx.x;
    if (i >= n4) return;
    float4 v = ((const float4*)s)[i];
    uint32_t h0, l0, h1, l1;
    split2(v.x, v.y, h0, l0);
    split2(v.z, v.w, h1, l1);
    ((uint32_t*)hi)[i * 2 + 0] = h0;
    ((uint32_t*)hi)[i * 2 + 1] = h1;
    ((uint32_t*)lo)[i * 2 + 0] = l0;
    ((uint32_t*)lo)[i * 2 + 1] = l1;
}

// ---------------------------------------------------------------------------
// Prep: transpose+split qkv weights. W[h][e][d] -> Wt[n][e]
// ---------------------------------------------------------------------------
__global__ __launch_bounds__(256) void prep_wt(
    const float* __restrict__ Wq, const float* __restrict__ Wk,
    const float* __restrict__ Wv,
    __nv_bfloat16* __restrict__ th, __nv_bfloat16* __restrict__ tl)
{
    __shared__ float ts[64][65];
    const int bx = blockIdx.x;
    const int mi = bx >> 8;
    const int rem = bx & 255;
    const int h = rem >> 4;
    const int e0 = (rem & 15) * 64;
    const float* src = (mi == 0 ? Wq : (mi == 1 ? Wk : Wv)) + (size_t)h * EE * DD;
    const int tid = threadIdx.x;

    #pragma unroll
    for (int i = 0; i < 4; ++i) {
        int idx = tid + i * 256;
        int ei = idx >> 4, d4 = idx & 15;
        float4 v = ((const float4*)(src + (size_t)(e0 + ei) * DD))[d4];
        ts[ei][d4 * 4 + 0] = v.x; ts[ei][d4 * 4 + 1] = v.y;
        ts[ei][d4 * 4 + 2] = v.z; ts[ei][d4 * 4 + 3] = v.w;
    }
    __syncthreads();

    const int d = tid >> 2, seg = tid & 3;
    const size_t row = ((size_t)mi * 1024 + h * 64 + d) * EE + e0 + seg * 16;
    alignas(16) __nv_bfloat16 hb[16], lb[16];
    #pragma unroll
    for (int i = 0; i < 16; ++i) {
        float v = ts[seg * 16 + i][d];
        __nv_bfloat16 hv = __float2bfloat16(v);
        hb[i] = hv;
        lb[i] = __float2bfloat16(v - __bfloat162float(hv));
    }
    *(uint4*)(th + row)     = *(const uint4*)(hb);
    *(uint4*)(th + row + 8) = *(const uint4*)(hb + 8);
    *(uint4*)(tl + row)     = *(const uint4*)(lb);
    *(uint4*)(tl + row + 8) = *(const uint4*)(lb + 8);
}

// ---------------------------------------------------------------------------
// HMMA split-bf16 GEMM, 128Mx64N block, warp 32x32, 3 CTAs/SM (latency fix).
// 2-stage ring, pointer-increment loaders, Bh/Bl share fragment registers.
// ---------------------------------------------------------------------------
#define PITCH 40
#define A_ELEMS (128 * PITCH)            // 5120
#define B_ELEMS (64 * PITCH)             // 2560
#define STAGE_BYTES ((2 * A_ELEMS + 2 * B_ELEMS) * 2)   // 30720

__global__ __launch_bounds__(256, 3)
void mma_gemm(const __nv_bfloat16* __restrict__ Ah, const __nv_bfloat16* __restrict__ Al,
              const __nv_bfloat16* __restrict__ Bh, const __nv_bfloat16* __restrict__ Bl,
              const float* __restrict__ bias,
              __nv_bfloat16* __restrict__ qh, __nv_bfloat16* __restrict__ ql,
              __nv_bfloat16* __restrict__ kh, __nv_bfloat16* __restrict__ kl,
              __nv_bfloat16* __restrict__ vh, __nv_bfloat16* __restrict__ vl,
              float* __restrict__ oplain, int mode)
{
    extern __shared__ char sm[];
    const uint32_t sbase = smem_u32(sm);
    const int tid = threadIdx.x;
    const int wid = tid >> 5, lane = tid & 31;
    const int wm = wid & 3, wn = wid >> 2;       // 4 M-warps x 2 N-warps
    const int n0 = blockIdx.x * 64;
    const int m0 = blockIdx.y * 128;

    const int a_row = lane & 15;
    const int a_col = (lane >> 4) << 3;
    const int b_row = ((lane >> 4) << 3) + (lane & 7);
    const int b_col = ((lane >> 3) & 1) << 3;

    float c[2][4][4] = {};    // warp tile 32x32

    // pointer-increment loader state (each thread owns row lr, 16B segment lseg)
    const int lr = tid >> 2, lseg = tid & 3;     // lr: 0..63
    const __nv_bfloat16* pA0 = Ah + (size_t)(m0 + lr) * EE + lseg * 8;
    const __nv_bfloat16* pA1 = Al + (size_t)(m0 + lr) * EE + lseg * 8;
    const __nv_bfloat16* pB0 = Bh + (size_t)(n0 + lr) * EE + lseg * 8;
    const __nv_bfloat16* pB1 = Bl + (size_t)(n0 + lr) * EE + lseg * 8;
    const uint32_t doff = (uint32_t)(lr * PITCH + lseg * 8) * 2;

    auto stage_load = [&](uint32_t bufbase) {
        const uint32_t d0 = bufbase + doff;
        CP_ASYNC16(d0,                                   pA0);
        CP_ASYNC16(d0 + 64 * PITCH * 2,                  pA0 + (size_t)64 * EE);
        CP_ASYNC16(d0 + A_ELEMS * 2,                     pA1);
        CP_ASYNC16(d0 + A_ELEMS * 2 + 64 * PITCH * 2,    pA1 + (size_t)64 * EE);
        CP_ASYNC16(d0 + 2 * A_ELEMS * 2,                 pB0);
        CP_ASYNC16(d0 + 2 * A_ELEMS * 2 + B_ELEMS * 2,   pB1);
        CP_COMMIT();
        pA0 += 32; pA1 += 32; pB0 += 32; pB1 += 32;
    };

    stage_load(sbase);
    stage_load(sbase + STAGE_BYTES);

    for (int ch = 0; ch < 32; ++ch) {
        if (ch < 31) CP_WAIT(1);
        else         CP_WAIT(0);
        __syncthreads();

        const uint32_t sb  = sbase + (ch & 1) * STAGE_BYTES;
        const uint32_t sAh = sb;
        const uint32_t sAl = sb + A_ELEMS * 2;
        const uint32_t sBh = sb + 2 * A_ELEMS * 2;
        const uint32_t sBl = sBh + B_ELEMS * 2;

        #pragma unroll
        for (int ks = 0; ks < 2; ++ks) {
            uint32_t ah[2][4], alr[2][4], bb[2][4];
            #pragma unroll
            for (int mi = 0; mi < 2; ++mi) {
                uint32_t off = (uint32_t)((wm * 32 + mi * 16 + a_row) * PITCH
                                          + ks * 16 + a_col) * 2;
                LDSM4(ah[mi],  sAh + off);
                LDSM4(alr[mi], sAl + off);
            }
            #pragma unroll
            for (int jp = 0; jp < 2; ++jp) {
                uint32_t off = (uint32_t)((wn * 32 + jp * 16 + b_row) * PITCH
                                          + ks * 16 + b_col) * 2;
                LDSM4(bb[jp], sBh + off);
            }
            #pragma unroll
            for (int mi = 0; mi < 2; ++mi)
                #pragma unroll
                for (int nt = 0; nt < 4; ++nt) {
                    const int jp = nt >> 1, q = (nt & 1) * 2;
                    MMA16816(c[mi][nt], ah[mi], bb[jp][q], bb[jp][q + 1]);
                }
            #pragma unroll
            for (int mi = 0; mi < 2; ++mi)
                #pragma unroll
                for (int nt = 0; nt < 4; ++nt) {
                    const int jp = nt >> 1, q = (nt & 1) * 2;
                    MMA16816(c[mi][nt], alr[mi], bb[jp][q], bb[jp][q + 1]);
                }
            #pragma unroll
            for (int jp = 0; jp < 2; ++jp) {
                uint32_t off = (uint32_t)((wn * 32 + jp * 16 + b_row) * PITCH
                                          + ks * 16 + b_col) * 2;
                LDSM4(bb[jp], sBl + off);          // reuse regs for Bl
            }
            #pragma unroll
            for (int mi = 0; mi < 2; ++mi)
                #pragma unroll
                for (int nt = 0; nt < 4; ++nt) {
                    const int jp = nt >> 1, q = (nt & 1) * 2;
                    MMA16816(c[mi][nt], ah[mi], bb[jp][q], bb[jp][q + 1]);
                }
        }
        __syncthreads();
        if (ch + 2 < 32) stage_load(sb);
    }

    const int rbase = m0 + wm * 32 + (lane >> 2);
    const int cpair = (lane & 3) * 2;

    if (mode == 0) {
        const int which = n0 >> 10;              // 64-wide tile = exactly one head
        __nv_bfloat16 *dh, *dl;
        if (which == 0)      { dh = qh; dl = ql; }
        else if (which == 1) { dh = kh; dl = kl; }
        else                 { dh = vh; dl = vl; }
        const float sc = (which == 0) ? SCALE_Q : 1.0f;
        const int h = (n0 & 1023) >> 6;
        #pragma unroll
        for (int mi = 0; mi < 2; ++mi) {
            const int m1 = rbase + mi * 16;
            const int m2 = m1 + 8;
            const size_t base1 = (((size_t)(m1 >> 11) * HH + h) * TT + (m1 & 2047)) * DD;
            const size_t base2 = (((size_t)(m2 >> 11) * HH + h) * TT + (m2 & 2047)) * DD;
            #pragma unroll
            for (int nt = 0; nt < 4; ++nt) {
                const int d = wn * 32 + nt * 8 + cpair;
                uint32_t h1, l1, h2, l2;
                split2(c[mi][nt][0] * sc, c[mi][nt][1] * sc, h1, l1);
                split2(c[mi][nt][2] * sc, c[mi][nt][3] * sc, h2, l2);
                *(uint32_t*)(dh + base1 + d) = h1;
                *(uint32_t*)(dl + base1 + d) = l1;
                *(uint32_t*)(dh + base2 + d) = h2;
                *(uint32_t*)(dl + base2 + d) = l2;
            }
        }
    } else {
        #pragma unroll
        for (int mi = 0; mi < 2; ++mi) {
            const int m1 = rbase + mi * 16;
            float* r1 = oplain + (size_t)m1 * EE;
            float* r2 = oplain + (size_t)(m1 + 8) * EE;
            #pragma unroll
            for (int nt = 0; nt < 4; ++nt) {
                const int col = n0 + wn * 32 + nt * 8 + cpair;
                const float b0 = bias[col], b1v = bias[col + 1];
                float2 v1 = make_float2(c[mi][nt][0] + b0, c[mi][nt][1] + b1v);
                float2 v2 = make_float2(c[mi][nt][2] + b0, c[mi][nt][3] + b1v);
                *(float2*)(r1 + col) = v1;
                *(float2*)(r2 + col) = v2;
            }
        }
    }
}

// ---------------------------------------------------------------------------
// Tensor-core causal flash attention: 2 CTAs/SM.
// 2-stage KV ring; K/V fragments in 32-col halves; P conversion fused per-ks
// into PV (no pah/pal arrays) -> peak regs < 128.
// ---------------------------------------------------------------------------
#define AP 72
#define SM_Q 0
#define QARR (128 * AP * 2)
#define SM_STAGE (2 * QARR)
#define KVARR (64 * AP * 2)
#define STAGE_SZ (4 * KVARR)
#define SM_MASK (SM_STAGE + 2 * STAGE_SZ)
#define SM_TOTAL (SM_MASK + 2 * 256)

__global__ __launch_bounds__(256, 2)
void attn_mma(const __nv_bfloat16* __restrict__ qh, const __nv_bfloat16* __restrict__ ql,
              const __nv_bfloat16* __restrict__ kh, const __nv_bfloat16* __restrict__ kl,
              const __nv_bfloat16* __restrict__ vh, const __nv_bfloat16* __restrict__ vl,
              const float* __restrict__ amask, float* __restrict__ ctx)
{
    extern __shared__ char sm[];
    const uint32_t sbase = smem_u32(sm);
    const int tid = threadIdx.x;
    const int w = tid >> 5, lane = tid & 31;
    const int bh = blockIdx.x;
    const int b_ = bh >> 4, h = bh & 15;
    const int qt = 15 - blockIdx.y;
    const int q0 = qt * 128;
    const int last = 2 * qt + 1;

    const int a_row = lane & 15;
    const int a_col = (lane >> 4) << 3;
    const int b_row = ((lane >> 4) << 3) + (lane & 7);
    const int b_col = ((lane >> 3) & 1) << 3;
    const int v_key = (lane & 7) + (((lane >> 3) & 1) << 3);
    const int v_d   = (lane >> 4) << 3;

    const size_t gbase = (size_t)bh * TT * DD;

    auto load_q = [&]() {
        #pragma unroll
        for (int arr = 0; arr < 2; ++arr) {
            const __nv_bfloat16* src0 = arr ? ql : qh;
            #pragma unroll
            for (int half = 0; half < 4; ++half) {
                int loc = half * 256 + tid;
                int r = loc >> 3, seg = loc & 7;
                const __nv_bfloat16* src = src0 + gbase + (size_t)(q0 + r) * DD + seg * 8;
                uint32_t dst = sbase + SM_Q + arr * QARR + (uint32_t)(r * AP + seg * 8) * 2;
                CP_ASYNC16(dst, src);
            }
        }
    };
    auto load_kv = [&](int buf, int kt) {
        const int s0 = kt * 64;
        #pragma unroll
        for (int arr = 0; arr < 4; ++arr) {
            const __nv_bfloat16* src0 = (arr == 0) ? kh : (arr == 1) ? kl
                                       : (arr == 2) ? vh : vl;
            #pragma unroll
            for (int half = 0; half < 2; ++half) {
                int loc = half * 256 + tid;
                int r = loc >> 3, seg = loc & 7;
                const __nv_bfloat16* src = src0 + gbase + (size_t)(s0 + r) * DD + seg * 8;
                uint32_t dst = sbase + SM_STAGE + buf * STAGE_SZ + arr * KVARR
                             + (uint32_t)(r * AP + seg * 8) * 2;
                CP_ASYNC16(dst, src);
            }
        }
        if (tid < 16) {
            const float* msrc = amask + (size_t)b_ * TT + s0 + tid * 4;
            uint32_t mdst = sbase + SM_MASK + buf * 256 + tid * 16;
            CP_ASYNC16(mdst, msrc);
        }
        CP_COMMIT();
    };

    load_q();
    load_kv(0, 0);      // group 0 = Q + KV0
    load_kv(1, 1);      // group 1
    CP_WAIT(1);
    __syncthreads();

    uint32_t qa_h[4][4], qa_l[4][4];
    #pragma unroll
    for (int ks = 0; ks < 4; ++ks) {
        uint32_t off = (uint32_t)((w * 16 + a_row) * AP + ks * 16 + a_col) * 2;
        LDSM4(qa_h[ks], sbase + SM_Q + off);
        LDSM4(qa_l[ks], sbase + SM_Q + QARR + off);
    }

    float o[8][4] = {};
    float m0r = -1e30f, m1r = -1e30f, l0 = 0.f, l1 = 0.f;
    const int row0 = q0 + w * 16 + (lane >> 2);
    const int wrow_hi = q0 + w * 16 + 15;

    for (int kt = 0; kt <= last; ++kt) {
        if (kt < last) CP_WAIT(1);
        else           CP_WAIT(0);
        __syncthreads();

        const int buf = kt & 1;
        const int s0 = kt * 64;
        const bool active = (s0 <= wrow_hi);

        if (active) {
            const uint32_t kb = sbase + SM_STAGE + buf * STAGE_SZ;
            // ---- S = Q.K^T, K frags in 32-col halves, Kh/Kl share regs ----
            float c[8][4] = {};
            #pragma unroll
            for (int ks = 0; ks < 4; ++ks) {
                #pragma unroll
                for (int hf = 0; hf < 2; ++hf) {
                    uint32_t kf[2][4];
                    #pragma unroll
                    for (int j = 0; j < 2; ++j) {
                        uint32_t off = (uint32_t)(((hf * 2 + j) * 16 + b_row) * AP
                                                  + ks * 16 + b_col) * 2;
                        LDSM4(kf[j], kb + off);
                    }
                    #pragma unroll
                    for (int t = 0; t < 4; ++t) {
                        const int nt = hf * 4 + t;
                        const int j = t >> 1, q = (t & 1) * 2;
                        MMA16816(c[nt], qa_h[ks], kf[j][q], kf[j][q + 1]);
                    }
                    #pragma unroll
                    for (int t = 0; t < 4; ++t) {
                        const int nt = hf * 4 + t;
                        const int j = t >> 1, q = (t & 1) * 2;
                        MMA16816(c[nt], qa_l[ks], kf[j][q], kf[j][q + 1]);
                    }
                    #pragma unroll
                    for (int j = 0; j < 2; ++j) {
                        uint32_t off = (uint32_t)(((hf * 2 + j) * 16 + b_row) * AP
                                                  + ks * 16 + b_col) * 2;
                        LDSM4(kf[j], kb + KVARR + off);   // reload as K-lo
                    }
                    #pragma unroll
                    for (int t = 0; t < 4; ++t) {
                        const int nt = hf * 4 + t;
                        const int j = t >> 1, q = (t & 1) * 2;
                        MMA16816(c[nt], qa_h[ks], kf[j][q], kf[j][q + 1]);
                    }
                }
            }
            // ---- mask + causal ----
            const float* mk = (const float*)(sm + SM_MASK + buf * 256);
            const bool dg = (s0 + 63) > (q0 + w * 16);
            #pragma unroll
            for (int nt = 0; nt < 8; ++nt) {
                const int cl = nt * 8 + (lane & 3) * 2;
                const float mv0 = mk[cl], mv1 = mk[cl + 1];
                const float ma0 = (1.0f - mv0) * -1e30f;
                const float ma1 = (1.0f - mv1) * -1e30f;
                c[nt][0] += ma0; c[nt][1] += ma1;
                c[nt][2] += ma0; c[nt][3] += ma1;
                if (dg) {
                    const int cg = s0 + cl;
                    if (cg     > row0)     c[nt][0] = -1e30f;
                    if (cg + 1 > row0)     c[nt][1] = -1e30f;
                    if (cg     > row0 + 8) c[nt][2] = -1e30f;
                    if (cg + 1 > row0 + 8) c[nt][3] = -1e30f;
                }
            }
            // ---- online softmax ----
            float t0 = -1e30f, t1 = -1e30f;
            #pragma unroll
            for (int nt = 0; nt < 8; ++nt) {
                t0 = fmaxf(t0, fmaxf(c[nt][0], c[nt][1]));
                t1 = fmaxf(t1, fmaxf(c[nt][2], c[nt][3]));
            }
            t0 = fmaxf(t0, __shfl_xor_sync(0xffffffffu, t0, 1));
            t0 = fmaxf(t0, __shfl_xor_sync(0xffffffffu, t0, 2));
            t1 = fmaxf(t1, __shfl_xor_sync(0xffffffffu, t1, 1));
            t1 = fmaxf(t1, __shfl_xor_sync(0xffffffffu, t1, 2));
            const float mn0 = fmaxf(m0r, t0), mn1 = fmaxf(m1r, t1);
            const float cor0 = exp2fast(m0r - mn0), cor1 = exp2fast(m1r - mn1);
            m0r = mn0; m1r = mn1;
            l0 *= cor0; l1 *= cor1;
            #pragma unroll
            for (int nt = 0; nt < 8; ++nt) {
                o[nt][0] *= cor0; o[nt][1] *= cor0;
                o[nt][2] *= cor1; o[nt][3] *= cor1;
            }
            // ---- fused P conversion + O += P.V (per ks, V halves, Vh/Vl share regs) ----
            float s0sum = 0.f, s1sum = 0.f;
            #pragma unroll
            for (int ks = 0; ks < 4; ++ks) {
                uint32_t pa_h[4], pa_l[4];
                #pragma unroll
                for (int t = 0; t < 2; ++t) {
                    const int nt = ks * 2 + t;
                    const float p0 = exp2fast(c[nt][0] - mn0);
                    const float p1 = exp2fast(c[nt][1] - mn0);
                    const float p2 = exp2fast(c[nt][2] - mn1);
                    const float p3 = exp2fast(c[nt][3] - mn1);
                    s0sum += p0 + p1; s1sum += p2 + p3;
                    split2(p0, p1, pa_h[t * 2], pa_l[t * 2]);
                    split2(p2, p3, pa_h[t * 2 + 1], pa_l[t * 2 + 1]);
                }
                #pragma unroll
                for (int hf = 0; hf < 2; ++hf) {
                    uint32_t vf[2][4];
                    #pragma unroll
                    for (int j = 0; j < 2; ++j) {
                        uint32_t off = (uint32_t)((ks * 16 + v_key) * AP
                                                  + (hf * 2 + j) * 16 + v_d) * 2;
                        LDSM4T(vf[j], kb + 2 * KVARR + off);
                    }
                    #pragma unroll
                    for (int t = 0; t < 4; ++t) {
                        const int nt = hf * 4 + t;
                        const int j = t >> 1, q = (t & 1) * 2;
                        MMA16816(o[nt], pa_h, vf[j][q], vf[j][q + 1]);
                    }
                    #pragma unroll
                    for (int t = 0; t < 4; ++t) {
                        const int nt = hf * 4 + t;
                        const int j = t >> 1, q = (t & 1) * 2;
                        MMA16816(o[nt], pa_l, vf[j][q], vf[j][q + 1]);
                    }
                    #pragma unroll
                    for (int j = 0; j < 2; ++j) {
                        uint32_t off = (uint32_t)((ks * 16 + v_key) * AP
                                                  + (hf * 2 + j) * 16 + v_d) * 2;
                        LDSM4T(vf[j], kb + 3 * KVARR + off);   // reload as V-lo
                    }
                    #pragma unroll
                    for (int t = 0; t < 4; ++t) {
                        const int nt = hf * 4 + t;
                        const int j = t >> 1, q = (t & 1) * 2;
                        MMA16816(o[nt], pa_h, vf[j][q], vf[j][q + 1]);
                    }
                }
            }
            s0sum += __shfl_xor_sync(0xffffffffu, s0sum, 1);
            s0sum += __shfl_xor_sync(0xffffffffu, s0sum, 2);
            s1sum += __shfl_xor_sync(0xffffffffu, s1sum, 1);
            s1sum += __shfl_xor_sync(0xffffffffu, s1sum, 2);
            l0 += s0sum; l1 += s1sum;
        }
        __syncthreads();
        if (kt + 2 <= last) load_kv(buf, kt + 2);
    }

    const float inv0 = 1.0f / l0, inv1 = 1.0f / l1;
    const int cpair = (lane & 3) * 2;
    float* r1 = ctx + ((size_t)b_ * TT + row0) * EE + h * 64;
    float* r2 = ctx + ((size_t)b_ * TT + row0 + 8) * EE + h * 64;
    #pragma unroll
    for (int nt = 0; nt < 8; ++nt) {
        const int d = nt * 8 + cpair;
        *(float2*)(r1 + d) = make_float2(o[nt][0] * inv0, o[nt][1] * inv0);
        *(float2*)(r2 + d) = make_float2(o[nt][2] * inv1, o[nt][3] * inv1);
    }
}

// ---------------------------------------------------------------------------
// Launch
// ---------------------------------------------------------------------------
extern "C" void kernel_launch(void* const* d_in, const int* in_sizes, int n_in,
                              void* d_out, int out_size)
{
    const float* x     = (const float*)d_in[0];
    const float* amask = (const float*)d_in[1];
    const float* Wq    = (const float*)d_in[2];
    const float* Wk    = (const float*)d_in[3];
    const float* Wv    = (const float*)d_in[4];
    const float* Wo    = (const float*)d_in[5];
    const float* bo    = (const float*)d_in[6];
    float* out = (float*)d_out;

    float* ctx;
    __nv_bfloat16 *xhi, *xlo, *wth, *wtl, *woh, *wol, *chi, *clo;
    __nv_bfloat16 *qh, *ql, *kh, *kl, *vh, *vl;
    cudaGetSymbolAddress((void**)&ctx, g_ctx);
    cudaGetSymbolAddress((void**)&xhi, g_xhi);
    cudaGetSymbolAddress((void**)&xlo, g_xlo);
    cudaGetSymbolAddress((void**)&wth, g_wth);
    cudaGetSymbolAddress((void**)&wtl, g_wtl);
    cudaGetSymbolAddress((void**)&woh, g_woh);
    cudaGetSymbolAddress((void**)&wol, g_wol);
    cudaGetSymbolAddress((void**)&chi, g_chi);
    cudaGetSymbolAddress((void**)&clo, g_clo);
    cudaGetSymbolAddress((void**)&qh,  g_qh);
    cudaGetSymbolAddress((void**)&ql,  g_ql);
    cudaGetSymbolAddress((void**)&kh,  g_kh);
    cudaGetSymbolAddress((void**)&kl,  g_kl);
    cudaGetSymbolAddress((void**)&vh,  g_vh);
    cudaGetSymbolAddress((void**)&vl,  g_vl);

    cudaFuncSetAttribute(mma_gemm, cudaFuncAttributeMaxDynamicSharedMemorySize,
                         2 * STAGE_BYTES);
    cudaFuncSetAttribute(attn_mma, cudaFuncAttributeMaxDynamicSharedMemorySize,
                         SM_TOTAL);

    conv_hilo<<<(BT * EE / 4) / 256, 256>>>(x, xhi, xlo, BT * EE / 4);
    prep_wt<<<768, 256>>>(Wq, Wk, Wv, wth, wtl);
    conv_hilo<<<(EE * EE / 4) / 256, 256>>>(Wo, woh, wol, EE * EE / 4);

    {   // QKV projection -> bf16 hi/lo q,k,v
        dim3 grid(NQKV / 64, BT / 128);
        mma_gemm<<<grid, 256, 2 * STAGE_BYTES>>>(xhi, xlo, wth, wtl, nullptr,
                                                 qh, ql, kh, kl, vh, vl,
                                                 nullptr, 0);
    }
    {   // attention
        dim3 grid(BB * HH, TT / 128);
        attn_mma<<<grid, 256, SM_TOTAL>>>(qh, ql, kh, kl, vh, vl, amask, ctx);
    }
    conv_hilo<<<(BT * EE / 4) / 256, 256>>>(ctx, chi, clo, BT * EE / 4);
    {   // output projection
        dim3 grid(EE / 64, BT / 128);
        mma_gemm<<<grid, 256, 2 * STAGE_BYTES>>>(chi, clo, woh, wol, bo,
                                                 nullptr, nullptr, nullptr,
                                                 nullptr, nullptr, nullptr,
                                                 out, 1);
    }
}

// round 9
// speedup vs baseline: 1.0947x; 1.0097x over previous
#include <cuda_runtime.h>
#include <cuda_bf16.h>
#include <math_constants.h>
#include <cstdint>

// Problem constants
#define BB 4
#define TT 2048
#define EE 1024
#define HH 16
#define DD 64
#define BT (BB*TT)          // 8192
#define NQKV 3072

#define L2E 1.44269504f
#define SCALE_Q (0.125f * L2E)    // fold 1/sqrt(D) and log2(e) into q

// ---------------------------------------------------------------------------
// Scratch (allocation-free rule: __device__ globals)
// ---------------------------------------------------------------------------
__device__ __align__(16) __nv_bfloat16 g_xhi[(size_t)BT*EE];
__device__ __align__(16) __nv_bfloat16 g_xlo[(size_t)BT*EE];
__device__ __align__(16) __nv_bfloat16 g_wth[(size_t)NQKV*EE];
__device__ __align__(16) __nv_bfloat16 g_wtl[(size_t)NQKV*EE];
__device__ __align__(16) __nv_bfloat16 g_woh[(size_t)EE*EE];
__device__ __align__(16) __nv_bfloat16 g_wol[(size_t)EE*EE];
__device__ __align__(16) __nv_bfloat16 g_chi[(size_t)BT*EE];   // attn out hi
__device__ __align__(16) __nv_bfloat16 g_clo[(size_t)BT*EE];   // attn out lo

// bf16 hi/lo q,k,v in [B,H,T,D]
__device__ __align__(16) __nv_bfloat16 g_qh[(size_t)BB*HH*TT*DD];
__device__ __align__(16) __nv_bfloat16 g_ql[(size_t)BB*HH*TT*DD];
__device__ __align__(16) __nv_bfloat16 g_kh[(size_t)BB*HH*TT*DD];
__device__ __align__(16) __nv_bfloat16 g_kl[(size_t)BB*HH*TT*DD];
__device__ __align__(16) __nv_bfloat16 g_vh[(size_t)BB*HH*TT*DD];
__device__ __align__(16) __nv_bfloat16 g_vl[(size_t)BB*HH*TT*DD];

// ---------------------------------------------------------------------------
// Helpers (base sm_103 ISA: mma.sync / ldmatrix / cp.async)
// ---------------------------------------------------------------------------
__device__ __forceinline__ uint32_t smem_u32(const void* p) {
    uint32_t a;
    asm("{ .reg .u64 t; cvta.to.shared.u64 t, %1; cvt.u32.u64 %0, t; }"
        : "=r"(a) : "l"(p));
    return a;
}

#define LDSM4(r, addr) \
    asm volatile("ldmatrix.sync.aligned.m8n8.x4.shared.b16 {%0,%1,%2,%3}, [%4];" \
        : "=r"((r)[0]), "=r"((r)[1]), "=r"((r)[2]), "=r"((r)[3]) : "r"(addr))

#define LDSM4T(r, addr) \
    asm volatile("ldmatrix.sync.aligned.m8n8.x4.trans.shared.b16 {%0,%1,%2,%3}, [%4];" \
        : "=r"((r)[0]), "=r"((r)[1]), "=r"((r)[2]), "=r"((r)[3]) : "r"(addr))

#define MMA16816(c, a, b0, b1) \
    asm volatile("mma.sync.aligned.m16n8k16.row.col.f32.bf16.bf16.f32 " \
        "{%0,%1,%2,%3}, {%4,%5,%6,%7}, {%8,%9}, {%0,%1,%2,%3};" \
        : "+f"((c)[0]), "+f"((c)[1]), "+f"((c)[2]), "+f"((c)[3]) \
        : "r"((a)[0]), "r"((a)[1]), "r"((a)[2]), "r"((a)[3]), "r"(b0), "r"(b1))

#define CP_ASYNC16(dst, src) \
    asm volatile("cp.async.cg.shared.global [%0], [%1], 16;" :: "r"(dst), "l"(src))
#define CP_COMMIT() asm volatile("cp.async.commit_group;" ::: "memory")
#define CP_WAIT(n)  asm volatile("cp.async.wait_group %0;" :: "n"(n) : "memory")

// split two floats into packed bf16x2 hi and lo residual
__device__ __forceinline__ void split2(float a, float b, uint32_t& hi, uint32_t& lo) {
    __nv_bfloat16 ha = __float2bfloat16(a), hb = __float2bfloat16(b);
    float ra = a - __bfloat162float(ha);
    float rb = b - __bfloat162float(hb);
    __nv_bfloat162 H; H.x = ha; H.y = hb;
    __nv_bfloat162 L; L.x = __float2bfloat16(ra); L.y = __float2bfloat16(rb);
    hi = *(uint32_t*)&H;
    lo = *(uint32_t*)&L;
}

// fast exp2 on the FMA pipe (degree-7, rel err ~1e-6)
__device__ __forceinline__ float exp2fast(float x) {
    x = fmaxf(x, -125.0f);
    int n = __float2int_rd(x);
    float f = x - (float)n;
    float p = 1.3570247e-5f;
    p = fmaf(p, f, 1.5353362e-4f);
    p = fmaf(p, f, 1.3398874e-3f);
    p = fmaf(p, f, 9.6184374e-3f);
    p = fmaf(p, f, 5.5503325e-2f);
    p = fmaf(p, f, 2.4022648e-1f);
    p = fmaf(p, f, 6.9314720e-1f);
    p = fmaf(p, f, 1.0f);
    return p * __int_as_float((n + 127) << 23);
}

// ---------------------------------------------------------------------------
// Prep: fp32 -> (bf16 hi, bf16 lo)
// ---------------------------------------------------------------------------
__global__ __launch_bounds__(256) void conv_hilo(
    const float* __restrict__ s, __nv_bfloat16* __restrict__ hi,
    __nv_bfloat16* __restrict__ lo, int n4)
{
    int i = blockIdx.x * 256 + threadIdx.x;
    if (i >= n4) return;
    float4 v = ((const float4*)s)[i];
    uint32_t h0, l0, h1, l1;
    split2(v.x, v.y, h0, l0);
    split2(v.z, v.w, h1, l1);
    ((uint32_t*)hi)[i * 2 + 0] = h0;
    ((uint32_t*)hi)[i * 2 + 1] = h1;
    ((uint32_t*)lo)[i * 2 + 0] = l0;
    ((uint32_t*)lo)[i * 2 + 1] = l1;
}

// ---------------------------------------------------------------------------
// Prep: transpose+split qkv weights. W[h][e][d] -> Wt[n][e]
// ---------------------------------------------------------------------------
__global__ __launch_bounds__(256) void prep_wt(
    const float* __restrict__ Wq, const float* __restrict__ Wk,
    const float* __restrict__ Wv,
    __nv_bfloat16* __restrict__ th, __nv_bfloat16* __restrict__ tl)
{
    __shared__ float ts[64][65];
    const int bx = blockIdx.x;
    const int mi = bx >> 8;
    const int rem = bx & 255;
    const int h = rem >> 4;
    const int e0 = (rem & 15) * 64;
    const float* src = (mi == 0 ? Wq : (mi == 1 ? Wk : Wv)) + (size_t)h * EE * DD;
    const int tid = threadIdx.x;

    #pragma unroll
    for (int i = 0; i < 4; ++i) {
        int idx = tid + i * 256;
        int ei = idx >> 4, d4 = idx & 15;
        float4 v = ((const float4*)(src + (size_t)(e0 + ei) * DD))[d4];
        ts[ei][d4 * 4 + 0] = v.x; ts[ei][d4 * 4 + 1] = v.y;
        ts[ei][d4 * 4 + 2] = v.z; ts[ei][d4 * 4 + 3] = v.w;
    }
    __syncthreads();

    const int d = tid >> 2, seg = tid & 3;
    const size_t row = ((size_t)mi * 1024 + h * 64 + d) * EE + e0 + seg * 16;
    alignas(16) __nv_bfloat16 hb[16], lb[16];
    #pragma unroll
    for (int i = 0; i < 16; ++i) {
        float v = ts[seg * 16 + i][d];
        __nv_bfloat16 hv = __float2bfloat16(v);
        hb[i] = hv;
        lb[i] = __float2bfloat16(v - __bfloat162float(hv));
    }
    *(uint4*)(th + row)     = *(const uint4*)(hb);
    *(uint4*)(th + row + 8) = *(const uint4*)(hb + 8);
    *(uint4*)(tl + row)     = *(const uint4*)(lb);
    *(uint4*)(tl + row + 8) = *(const uint4*)(lb + 8);
}

// ---------------------------------------------------------------------------
// HMMA split-bf16 GEMM, 128Mx128N block, warp 32x64, 2 CTAs/SM.
// 2-stage ring, pointer-increment loaders, Bh/Bl share fragment registers.
// Halved n-grid vs R8 -> 33% less L2 traffic; 8-tile per-warp ILP.
// ---------------------------------------------------------------------------
#define PITCH 40
#define A_ELEMS (128 * PITCH)            // 5120
#define B_ELEMS (128 * PITCH)            // 5120
#define STAGE_BYTES ((2 * A_ELEMS + 2 * B_ELEMS) * 2)   // 40960

__global__ __launch_bounds__(256, 2)
void mma_gemm(const __nv_bfloat16* __restrict__ Ah, const __nv_bfloat16* __restrict__ Al,
              const __nv_bfloat16* __restrict__ Bh, const __nv_bfloat16* __restrict__ Bl,
              const float* __restrict__ bias,
              __nv_bfloat16* __restrict__ qh, __nv_bfloat16* __restrict__ ql,
              __nv_bfloat16* __restrict__ kh, __nv_bfloat16* __restrict__ kl,
              __nv_bfloat16* __restrict__ vh, __nv_bfloat16* __restrict__ vl,
              float* __restrict__ oplain, int mode)
{
    extern __shared__ char sm[];
    const uint32_t sbase = smem_u32(sm);
    const int tid = threadIdx.x;
    const int wid = tid >> 5, lane = tid & 31;
    const int wm = wid & 3, wn = wid >> 2;       // 4 M-warps x 2 N-warps
    const int n0 = blockIdx.x * 128;
    const int m0 = blockIdx.y * 128;

    const int a_row = lane & 15;
    const int a_col = (lane >> 4) << 3;
    const int b_row = ((lane >> 4) << 3) + (lane & 7);
    const int b_col = ((lane >> 3) & 1) << 3;

    float c[2][8][4] = {};    // warp tile 32x64: 8 independent accum tiles

    // pointer-increment loader (each thread: row lr & lr+64, 16B segment lseg)
    const int lr = tid >> 2, lseg = tid & 3;     // lr: 0..63
    const __nv_bfloat16* pA0 = Ah + (size_t)(m0 + lr) * EE + lseg * 8;
    const __nv_bfloat16* pA1 = Al + (size_t)(m0 + lr) * EE + lseg * 8;
    const __nv_bfloat16* pB0 = Bh + (size_t)(n0 + lr) * EE + lseg * 8;
    const __nv_bfloat16* pB1 = Bl + (size_t)(n0 + lr) * EE + lseg * 8;
    const uint32_t doff = (uint32_t)(lr * PITCH + lseg * 8) * 2;

    auto stage_load = [&](uint32_t bufbase) {
        const uint32_t d0 = bufbase + doff;
        CP_ASYNC16(d0,                                  pA0);
        CP_ASYNC16(d0 + 64 * PITCH * 2,                 pA0 + (size_t)64 * EE);
        CP_ASYNC16(d0 + A_ELEMS * 2,                    pA1);
        CP_ASYNC16(d0 + A_ELEMS * 2 + 64 * PITCH * 2,   pA1 + (size_t)64 * EE);
        const uint32_t b0 = d0 + 2 * A_ELEMS * 2;
        CP_ASYNC16(b0,                                  pB0);
        CP_ASYNC16(b0 + 64 * PITCH * 2,                 pB0 + (size_t)64 * EE);
        CP_ASYNC16(b0 + B_ELEMS * 2,                    pB1);
        CP_ASYNC16(b0 + B_ELEMS * 2 + 64 * PITCH * 2,   pB1 + (size_t)64 * EE);
        CP_COMMIT();
        pA0 += 32; pA1 += 32; pB0 += 32; pB1 += 32;
    };

    stage_load(sbase);
    stage_load(sbase + STAGE_BYTES);

    for (int ch = 0; ch < 32; ++ch) {
        if (ch < 31) CP_WAIT(1);
        else         CP_WAIT(0);
        __syncthreads();

        const uint32_t sb  = sbase + (ch & 1) * STAGE_BYTES;
        const uint32_t sAh = sb;
        const uint32_t sAl = sb + A_ELEMS * 2;
        const uint32_t sBh = sb + 2 * A_ELEMS * 2;
        const uint32_t sBl = sBh + B_ELEMS * 2;

        #pragma unroll
        for (int ks = 0; ks < 2; ++ks) {
            uint32_t ah[2][4], alr[2][4];
            #pragma unroll
            for (int mi = 0; mi < 2; ++mi) {
                uint32_t off = (uint32_t)((wm * 32 + mi * 16 + a_row) * PITCH
                                          + ks * 16 + a_col) * 2;
                LDSM4(ah[mi],  sAh + off);
                LDSM4(alr[mi], sAl + off);
            }
            #pragma unroll
            for (int jp = 0; jp < 4; ++jp) {      // 4 x 16-col B groups
                uint32_t bb[4];
                uint32_t off = (uint32_t)((wn * 64 + jp * 16 + b_row) * PITCH
                                          + ks * 16 + b_col) * 2;
                LDSM4(bb, sBh + off);
                #pragma unroll
                for (int mi = 0; mi < 2; ++mi)
                    #pragma unroll
                    for (int t = 0; t < 2; ++t)
                        MMA16816(c[mi][jp * 2 + t], ah[mi],  bb[t * 2], bb[t * 2 + 1]);
                #pragma unroll
                for (int mi = 0; mi < 2; ++mi)
                    #pragma unroll
                    for (int t = 0; t < 2; ++t)
                        MMA16816(c[mi][jp * 2 + t], alr[mi], bb[t * 2], bb[t * 2 + 1]);
                LDSM4(bb, sBl + off);             // reuse regs for Bl
                #pragma unroll
                for (int mi = 0; mi < 2; ++mi)
                    #pragma unroll
                    for (int t = 0; t < 2; ++t)
                        MMA16816(c[mi][jp * 2 + t], ah[mi],  bb[t * 2], bb[t * 2 + 1]);
            }
        }
        __syncthreads();
        if (ch + 2 < 32) stage_load(sb);
    }

    const int rbase = m0 + wm * 32 + (lane >> 2);
    const int cpair = (lane & 3) * 2;

    if (mode == 0) {
        const int which = n0 >> 10;
        __nv_bfloat16 *dh, *dl;
        if (which == 0)      { dh = qh; dl = ql; }
        else if (which == 1) { dh = kh; dl = kl; }
        else                 { dh = vh; dl = vl; }
        const float sc = (which == 0) ? SCALE_Q : 1.0f;
        const int h = ((n0 & 1023) >> 6) + wn;
        #pragma unroll
        for (int mi = 0; mi < 2; ++mi) {
            const int m1 = rbase + mi * 16;
            const int m2 = m1 + 8;
            const size_t base1 = (((size_t)(m1 >> 11) * HH + h) * TT + (m1 & 2047)) * DD;
            const size_t base2 = (((size_t)(m2 >> 11) * HH + h) * TT + (m2 & 2047)) * DD;
            #pragma unroll
            for (int nt = 0; nt < 8; ++nt) {
                const int d = nt * 8 + cpair;
                uint32_t h1, l1, h2, l2;
                split2(c[mi][nt][0] * sc, c[mi][nt][1] * sc, h1, l1);
                split2(c[mi][nt][2] * sc, c[mi][nt][3] * sc, h2, l2);
                *(uint32_t*)(dh + base1 + d) = h1;
                *(uint32_t*)(dl + base1 + d) = l1;
                *(uint32_t*)(dh + base2 + d) = h2;
                *(uint32_t*)(dl + base2 + d) = l2;
            }
        }
    } else {
        #pragma unroll
        for (int mi = 0; mi < 2; ++mi) {
            const int m1 = rbase + mi * 16;
            float* r1 = oplain + (size_t)m1 * EE;
            float* r2 = oplain + (size_t)(m1 + 8) * EE;
            #pragma unroll
            for (int nt = 0; nt < 8; ++nt) {
                const int col = n0 + wn * 64 + nt * 8 + cpair;
                const float b0 = bias[col], b1v = bias[col + 1];
                float2 v1 = make_float2(c[mi][nt][0] + b0, c[mi][nt][1] + b1v);
                float2 v2 = make_float2(c[mi][nt][2] + b0, c[mi][nt][3] + b1v);
                *(float2*)(r1 + col) = v1;
                *(float2*)(r2 + col) = v2;
            }
        }
    }
}

// ---------------------------------------------------------------------------
// Tensor-core causal flash attention: 2 CTAs/SM, 2-stage KV ring.
// Epilogue writes bf16 hi/lo ctx directly (fused conv).
// ---------------------------------------------------------------------------
#define AP 72
#define SM_Q 0
#define QARR (128 * AP * 2)
#define SM_STAGE (2 * QARR)
#define KVARR (64 * AP * 2)
#define STAGE_SZ (4 * KVARR)
#define SM_MASK (SM_STAGE + 2 * STAGE_SZ)
#define SM_TOTAL (SM_MASK + 2 * 256)

__global__ __launch_bounds__(256, 2)
void attn_mma(const __nv_bfloat16* __restrict__ qh, const __nv_bfloat16* __restrict__ ql,
              const __nv_bfloat16* __restrict__ kh, const __nv_bfloat16* __restrict__ kl,
              const __nv_bfloat16* __restrict__ vh, const __nv_bfloat16* __restrict__ vl,
              const float* __restrict__ amask,
              __nv_bfloat16* __restrict__ chi, __nv_bfloat16* __restrict__ clo)
{
    extern __shared__ char sm[];
    const uint32_t sbase = smem_u32(sm);
    const int tid = threadIdx.x;
    const int w = tid >> 5, lane = tid & 31;
    const int bh = blockIdx.x;
    const int b_ = bh >> 4, h = bh & 15;
    const int qt = 15 - blockIdx.y;
    const int q0 = qt * 128;
    const int last = 2 * qt + 1;

    const int a_row = lane & 15;
    const int a_col = (lane >> 4) << 3;
    const int b_row = ((lane >> 4) << 3) + (lane & 7);
    const int b_col = ((lane >> 3) & 1) << 3;
    const int v_key = (lane & 7) + (((lane >> 3) & 1) << 3);
    const int v_d   = (lane >> 4) << 3;

    const size_t gbase = (size_t)bh * TT * DD;

    auto load_q = [&]() {
        #pragma unroll
        for (int arr = 0; arr < 2; ++arr) {
            const __nv_bfloat16* src0 = arr ? ql : qh;
            #pragma unroll
            for (int half = 0; half < 4; ++half) {
                int loc = half * 256 + tid;
                int r = loc >> 3, seg = loc & 7;
                const __nv_bfloat16* src = src0 + gbase + (size_t)(q0 + r) * DD + seg * 8;
                uint32_t dst = sbase + SM_Q + arr * QARR + (uint32_t)(r * AP + seg * 8) * 2;
                CP_ASYNC16(dst, src);
            }
        }
    };
    auto load_kv = [&](int buf, int kt) {
        const int s0 = kt * 64;
        #pragma unroll
        for (int arr = 0; arr < 4; ++arr) {
            const __nv_bfloat16* src0 = (arr == 0) ? kh : (arr == 1) ? kl
                                       : (arr == 2) ? vh : vl;
            #pragma unroll
            for (int half = 0; half < 2; ++half) {
                int loc = half * 256 + tid;
                int r = loc >> 3, seg = loc & 7;
                const __nv_bfloat16* src = src0 + gbase + (size_t)(s0 + r) * DD + seg * 8;
                uint32_t dst = sbase + SM_STAGE + buf * STAGE_SZ + arr * KVARR
                             + (uint32_t)(r * AP + seg * 8) * 2;
                CP_ASYNC16(dst, src);
            }
        }
        if (tid < 16) {
            const float* msrc = amask + (size_t)b_ * TT + s0 + tid * 4;
            uint32_t mdst = sbase + SM_MASK + buf * 256 + tid * 16;
            CP_ASYNC16(mdst, msrc);
        }
        CP_COMMIT();
    };

    load_q();
    load_kv(0, 0);      // group 0 = Q + KV0
    load_kv(1, 1);      // group 1
    CP_WAIT(1);
    __syncthreads();

    uint32_t qa_h[4][4], qa_l[4][4];
    #pragma unroll
    for (int ks = 0; ks < 4; ++ks) {
        uint32_t off = (uint32_t)((w * 16 + a_row) * AP + ks * 16 + a_col) * 2;
        LDSM4(qa_h[ks], sbase + SM_Q + off);
        LDSM4(qa_l[ks], sbase + SM_Q + QARR + off);
    }

    float o[8][4] = {};
    float m0r = -1e30f, m1r = -1e30f, l0 = 0.f, l1 = 0.f;
    const int row0 = q0 + w * 16 + (lane >> 2);
    const int wrow_hi = q0 + w * 16 + 15;

    for (int kt = 0; kt <= last; ++kt) {
        if (kt < last) CP_WAIT(1);
        else           CP_WAIT(0);
        __syncthreads();

        const int buf = kt & 1;
        const int s0 = kt * 64;
        const bool active = (s0 <= wrow_hi);

        if (active) {
            const uint32_t kb = sbase + SM_STAGE + buf * STAGE_SZ;
            // ---- S = Q.K^T, K frags in 32-col halves, Kh/Kl share regs ----
            float c[8][4] = {};
            #pragma unroll
            for (int ks = 0; ks < 4; ++ks) {
                #pragma unroll
                for (int hf = 0; hf < 2; ++hf) {
                    uint32_t kf[2][4];
                    #pragma unroll
                    for (int j = 0; j < 2; ++j) {
                        uint32_t off = (uint32_t)(((hf * 2 + j) * 16 + b_row) * AP
                                                  + ks * 16 + b_col) * 2;
                        LDSM4(kf[j], kb + off);
                    }
                    #pragma unroll
                    for (int t = 0; t < 4; ++t) {
                        const int nt = hf * 4 + t;
                        const int j = t >> 1, q = (t & 1) * 2;
                        MMA16816(c[nt], qa_h[ks], kf[j][q], kf[j][q + 1]);
                    }
                    #pragma unroll
                    for (int t = 0; t < 4; ++t) {
                        const int nt = hf * 4 + t;
                        const int j = t >> 1, q = (t & 1) * 2;
                        MMA16816(c[nt], qa_l[ks], kf[j][q], kf[j][q + 1]);
                    }
                    #pragma unroll
                    for (int j = 0; j < 2; ++j) {
                        uint32_t off = (uint32_t)(((hf * 2 + j) * 16 + b_row) * AP
                                                  + ks * 16 + b_col) * 2;
                        LDSM4(kf[j], kb + KVARR + off);   // reload as K-lo
                    }
                    #pragma unroll
                    for (int t = 0; t < 4; ++t) {
                        const int nt = hf * 4 + t;
                        const int j = t >> 1, q = (t & 1) * 2;
                        MMA16816(c[nt], qa_h[ks], kf[j][q], kf[j][q + 1]);
                    }
                }
            }
            // ---- mask + causal ----
            const float* mk = (const float*)(sm + SM_MASK + buf * 256);
            const bool dg = (s0 + 63) > (q0 + w * 16);
            #pragma unroll
            for (int nt = 0; nt < 8; ++nt) {
                const int cl = nt * 8 + (lane & 3) * 2;
                const float mv0 = mk[cl], mv1 = mk[cl + 1];
                const float ma0 = (1.0f - mv0) * -1e30f;
                const float ma1 = (1.0f - mv1) * -1e30f;
                c[nt][0] += ma0; c[nt][1] += ma1;
                c[nt][2] += ma0; c[nt][3] += ma1;
                if (dg) {
                    const int cg = s0 + cl;
                    if (cg     > row0)     c[nt][0] = -1e30f;
                    if (cg + 1 > row0)     c[nt][1] = -1e30f;
                    if (cg     > row0 + 8) c[nt][2] = -1e30f;
                    if (cg + 1 > row0 + 8) c[nt][3] = -1e30f;
                }
            }
            // ---- online softmax ----
            float t0 = -1e30f, t1 = -1e30f;
            #pragma unroll
            for (int nt = 0; nt < 8; ++nt) {
                t0 = fmaxf(t0, fmaxf(c[nt][0], c[nt][1]));
                t1 = fmaxf(t1, fmaxf(c[nt][2], c[nt][3]));
            }
            t0 = fmaxf(t0, __shfl_xor_sync(0xffffffffu, t0, 1));
            t0 = fmaxf(t0, __shfl_xor_sync(0xffffffffu, t0, 2));
            t1 = fmaxf(t1, __shfl_xor_sync(0xffffffffu, t1, 1));
            t1 = fmaxf(t1, __shfl_xor_sync(0xffffffffu, t1, 2));
            const float mn0 = fmaxf(m0r, t0), mn1 = fmaxf(m1r, t1);
            const float cor0 = exp2fast(m0r - mn0), cor1 = exp2fast(m1r - mn1);
            m0r = mn0; m1r = mn1;
            l0 *= cor0; l1 *= cor1;
            #pragma unroll
            for (int nt = 0; nt < 8; ++nt) {
                o[nt][0] *= cor0; o[nt][1] *= cor0;
                o[nt][2] *= cor1; o[nt][3] *= cor1;
            }
            // ---- fused P conversion + O += P.V ----
            float s0sum = 0.f, s1sum = 0.f;
            #pragma unroll
            for (int ks = 0; ks < 4; ++ks) {
                uint32_t pa_h[4], pa_l[4];
                #pragma unroll
                for (int t = 0; t < 2; ++t) {
                    const int nt = ks * 2 + t;
                    const float p0 = exp2fast(c[nt][0] - mn0);
                    const float p1 = exp2fast(c[nt][1] - mn0);
                    const float p2 = exp2fast(c[nt][2] - mn1);
                    const float p3 = exp2fast(c[nt][3] - mn1);
                    s0sum += p0 + p1; s1sum += p2 + p3;
                    split2(p0, p1, pa_h[t * 2], pa_l[t * 2]);
                    split2(p2, p3, pa_h[t * 2 + 1], pa_l[t * 2 + 1]);
                }
                #pragma unroll
                for (int hf = 0; hf < 2; ++hf) {
                    uint32_t vf[2][4];
                    #pragma unroll
                    for (int j = 0; j < 2; ++j) {
                        uint32_t off = (uint32_t)((ks * 16 + v_key) * AP
                                                  + (hf * 2 + j) * 16 + v_d) * 2;
                        LDSM4T(vf[j], kb + 2 * KVARR + off);
                    }
                    #pragma unroll
                    for (int t = 0; t < 4; ++t) {
                        const int nt = hf * 4 + t;
                        const int j = t >> 1, q = (t & 1) * 2;
                        MMA16816(o[nt], pa_h, vf[j][q], vf[j][q + 1]);
                    }
                    #pragma unroll
                    for (int t = 0; t < 4; ++t) {
                        const int nt = hf * 4 + t;
                        const int j = t >> 1, q = (t & 1) * 2;
                        MMA16816(o[nt], pa_l, vf[j][q], vf[j][q + 1]);
                    }
                    #pragma unroll
                    for (int j = 0; j < 2; ++j) {
                        uint32_t off = (uint32_t)((ks * 16 + v_key) * AP
                                                  + (hf * 2 + j) * 16 + v_d) * 2;
                        LDSM4T(vf[j], kb + 3 * KVARR + off);   // reload as V-lo
                    }
                    #pragma unroll
                    for (int t = 0; t < 4; ++t) {
                        const int nt = hf * 4 + t;
                        const int j = t >> 1, q = (t & 1) * 2;
                        MMA16816(o[nt], pa_h, vf[j][q], vf[j][q + 1]);
                    }
                }
            }
            s0sum += __shfl_xor_sync(0xffffffffu, s0sum, 1);
            s0sum += __shfl_xor_sync(0xffffffffu, s0sum, 2);
            s1sum += __shfl_xor_sync(0xffffffffu, s1sum, 1);
            s1sum += __shfl_xor_sync(0xffffffffu, s1sum, 2);
            l0 += s0sum; l1 += s1sum;
        }
        __syncthreads();
        if (kt + 2 <= last) load_kv(buf, kt + 2);
    }

    // ---- normalize + split + store bf16 hi/lo ctx [B,T,E] (fused conv) ----
    const float inv0 = 1.0f / l0, inv1 = 1.0f / l1;
    const int cpair = (lane & 3) * 2;
    const size_t r1 = ((size_t)b_ * TT + row0) * EE + h * 64;
    const size_t r2 = ((size_t)b_ * TT + row0 + 8) * EE + h * 64;
    #pragma unroll
    for (int nt = 0; nt < 8; ++nt) {
        const int d = nt * 8 + cpair;
        uint32_t h1, l1w, h2, l2;
        split2(o[nt][0] * inv0, o[nt][1] * inv0, h1, l1w);
        split2(o[nt][2] * inv1, o[nt][3] * inv1, h2, l2);
        *(uint32_t*)(chi + r1 + d) = h1;
        *(uint32_t*)(clo + r1 + d) = l1w;
        *(uint32_t*)(chi + r2 + d) = h2;
        *(uint32_t*)(clo + r2 + d) = l2;
    }
}

// ---------------------------------------------------------------------------
// Launch
// ---------------------------------------------------------------------------
extern "C" void kernel_launch(void* const* d_in, const int* in_sizes, int n_in,
                              void* d_out, int out_size)
{
    const float* x     = (const float*)d_in[0];
    const float* amask = (const float*)d_in[1];
    const float* Wq    = (const float*)d_in[2];
    const float* Wk    = (const float*)d_in[3];
    const float* Wv    = (const float*)d_in[4];
    const float* Wo    = (const float*)d_in[5];
    const float* bo    = (const float*)d_in[6];
    float* out = (float*)d_out;

    __nv_bfloat16 *xhi, *xlo, *wth, *wtl, *woh, *wol, *chi, *clo;
    __nv_bfloat16 *qh, *ql, *kh, *kl, *vh, *vl;
    cudaGetSymbolAddress((void**)&xhi, g_xhi);
    cudaGetSymbolAddress((void**)&xlo, g_xlo);
    cudaGetSymbolAddress((void**)&wth, g_wth);
    cudaGetSymbolAddress((void**)&wtl, g_wtl);
    cudaGetSymbolAddress((void**)&woh, g_woh);
    cudaGetSymbolAddress((void**)&wol, g_wol);
    cudaGetSymbolAddress((void**)&chi, g_chi);
    cudaGetSymbolAddress((void**)&clo, g_clo);
    cudaGetSymbolAddress((void**)&qh,  g_qh);
    cudaGetSymbolAddress((void**)&ql,  g_ql);
    cudaGetSymbolAddress((void**)&kh,  g_kh);
    cudaGetSymbolAddress((void**)&kl,  g_kl);
    cudaGetSymbolAddress((void**)&vh,  g_vh);
    cudaGetSymbolAddress((void**)&vl,  g_vl);

    cudaFuncSetAttribute(mma_gemm, cudaFuncAttributeMaxDynamicSharedMemorySize,
                         2 * STAGE_BYTES);
    cudaFuncSetAttribute(attn_mma, cudaFuncAttributeMaxDynamicSharedMemorySize,
                         SM_TOTAL);

    conv_hilo<<<(BT * EE / 4) / 256, 256>>>(x, xhi, xlo, BT * EE / 4);
    prep_wt<<<768, 256>>>(Wq, Wk, Wv, wth, wtl);
    conv_hilo<<<(EE * EE / 4) / 256, 256>>>(Wo, woh, wol, EE * EE / 4);

    {   // QKV projection -> bf16 hi/lo q,k,v
        dim3 grid(NQKV / 128, BT / 128);
        mma_gemm<<<grid, 256, 2 * STAGE_BYTES>>>(xhi, xlo, wth, wtl, nullptr,
                                                 qh, ql, kh, kl, vh, vl,
                                                 nullptr, 0);
    }
    {   // attention -> bf16 hi/lo ctx (fused split)
        dim3 grid(BB * HH, TT / 128);
        attn_mma<<<grid, 256, SM_TOTAL>>>(qh, ql, kh, kl, vh, vl, amask, chi, clo);
    }
    {   // output projection
        dim3 grid(EE / 128, BT / 128);
        mma_gemm<<<grid, 256, 2 * STAGE_BYTES>>>(chi, clo, woh, wol, bo,
                                                 nullptr, nullptr, nullptr,
                                                 nullptr, nullptr, nullptr,
                                                 out, 1);
    }
}

// round 10
// speedup vs baseline: 1.2440x; 1.1364x over previous
#include <cuda_runtime.h>
#include <cuda_fp16.h>
#include <math_constants.h>
#include <cstdint>

// Problem constants
#define BB 4
#define TT 2048
#define EE 1024
#define HH 16
#define DD 64
#define BT (BB*TT)          // 8192
#define NQKV 3072

#define L2E 1.44269504f
#define SCALE_Q (0.125f * L2E)    // fold 1/sqrt(D) and log2(e) into q

// ---------------------------------------------------------------------------
// Scratch (allocation-free rule: __device__ globals)  — all fp16 hi/lo now
// ---------------------------------------------------------------------------
__device__ __align__(16) __half g_xhi[(size_t)BT*EE];
__device__ __align__(16) __half g_xlo[(size_t)BT*EE];
__device__ __align__(16) __half g_wth[(size_t)NQKV*EE];
__device__ __align__(16) __half g_wtl[(size_t)NQKV*EE];   // generated; unused by 2-pass qkv
__device__ __align__(16) __half g_woh[(size_t)EE*EE];
__device__ __align__(16) __half g_wol[(size_t)EE*EE];
__device__ __align__(16) __half g_chi[(size_t)BT*EE];     // attn out hi
__device__ __align__(16) __half g_clo[(size_t)BT*EE];     // attn out lo

// fp16 hi/lo q,k,v in [B,H,T,D]
__device__ __align__(16) __half g_qh[(size_t)BB*HH*TT*DD];
__device__ __align__(16) __half g_ql[(size_t)BB*HH*TT*DD];
__device__ __align__(16) __half g_kh[(size_t)BB*HH*TT*DD];
__device__ __align__(16) __half g_kl[(size_t)BB*HH*TT*DD];
__device__ __align__(16) __half g_vh[(size_t)BB*HH*TT*DD];
__device__ __align__(16) __half g_vl[(size_t)BB*HH*TT*DD];

// ---------------------------------------------------------------------------
// Helpers (base sm_103 ISA: mma.sync / ldmatrix / cp.async)
// ---------------------------------------------------------------------------
__device__ __forceinline__ uint32_t smem_u32(const void* p) {
    uint32_t a;
    asm("{ .reg .u64 t; cvta.to.shared.u64 t, %1; cvt.u32.u64 %0, t; }"
        : "=r"(a) : "l"(p));
    return a;
}

#define LDSM4(r, addr) \
    asm volatile("ldmatrix.sync.aligned.m8n8.x4.shared.b16 {%0,%1,%2,%3}, [%4];" \
        : "=r"((r)[0]), "=r"((r)[1]), "=r"((r)[2]), "=r"((r)[3]) : "r"(addr))

#define LDSM4T(r, addr) \
    asm volatile("ldmatrix.sync.aligned.m8n8.x4.trans.shared.b16 {%0,%1,%2,%3}, [%4];" \
        : "=r"((r)[0]), "=r"((r)[1]), "=r"((r)[2]), "=r"((r)[3]) : "r"(addr))

#define MMA16816(c, a, b0, b1) \
    asm volatile("mma.sync.aligned.m16n8k16.row.col.f32.f16.f16.f32 " \
        "{%0,%1,%2,%3}, {%4,%5,%6,%7}, {%8,%9}, {%0,%1,%2,%3};" \
        : "+f"((c)[0]), "+f"((c)[1]), "+f"((c)[2]), "+f"((c)[3]) \
        : "r"((a)[0]), "r"((a)[1]), "r"((a)[2]), "r"((a)[3]), "r"(b0), "r"(b1))

#define CP_ASYNC16(dst, src) \
    asm volatile("cp.async.cg.shared.global [%0], [%1], 16;" :: "r"(dst), "l"(src))
#define CP_COMMIT() asm volatile("cp.async.commit_group;" ::: "memory")
#define CP_WAIT(n)  asm volatile("cp.async.wait_group %0;" :: "n"(n) : "memory")

// split two floats into packed fp16x2 hi and lo residual (11-bit mantissas)
__device__ __forceinline__ void split2(float a, float b, uint32_t& hi, uint32_t& lo) {
    __half ha = __float2half_rn(a), hb = __float2half_rn(b);
    float ra = a - __half2float(ha);
    float rb = b - __half2float(hb);
    __half2 H = __halves2half2(ha, hb);
    __half2 L = __halves2half2(__float2half_rn(ra), __float2half_rn(rb));
    hi = *(uint32_t*)&H;
    lo = *(uint32_t*)&L;
}

// fast exp2 on the FMA pipe (degree-7, rel err ~1e-6)
__device__ __forceinline__ float exp2fast(float x) {
    x = fmaxf(x, -125.0f);
    int n = __float2int_rd(x);
    float f = x - (float)n;
    float p = 1.3570247e-5f;
    p = fmaf(p, f, 1.5353362e-4f);
    p = fmaf(p, f, 1.3398874e-3f);
    p = fmaf(p, f, 9.6184374e-3f);
    p = fmaf(p, f, 5.5503325e-2f);
    p = fmaf(p, f, 2.4022648e-1f);
    p = fmaf(p, f, 6.9314720e-1f);
    p = fmaf(p, f, 1.0f);
    return p * __int_as_float((n + 127) << 23);
}

// ---------------------------------------------------------------------------
// Prep: fp32 -> (fp16 hi, fp16 lo)
// ---------------------------------------------------------------------------
__global__ __launch_bounds__(256) void conv_hilo(
    const float* __restrict__ s, __half* __restrict__ hi,
    __half* __restrict__ lo, int n4)
{
    int i = blockIdx.x * 256 + threadIdx.x;
    if (i >= n4) return;
    float4 v = ((const float4*)s)[i];
    uint32_t h0, l0, h1, l1;
    split2(v.x, v.y, h0, l0);
    split2(v.z, v.w, h1, l1);
    ((uint32_t*)hi)[i * 2 + 0] = h0;
    ((uint32_t*)hi)[i * 2 + 1] = h1;
    ((uint32_t*)lo)[i * 2 + 0] = l0;
    ((uint32_t*)lo)[i * 2 + 1] = l1;
}

// ---------------------------------------------------------------------------
// Prep: transpose+split qkv weights. W[h][e][d] -> Wt[n][e]
// ---------------------------------------------------------------------------
__global__ __launch_bounds__(256) void prep_wt(
    const float* __restrict__ Wq, const float* __restrict__ Wk,
    const float* __restrict__ Wv,
    __half* __restrict__ th, __half* __restrict__ tl)
{
    __shared__ float ts[64][65];
    const int bx = blockIdx.x;
    const int mi = bx >> 8;
    const int rem = bx & 255;
    const int h = rem >> 4;
    const int e0 = (rem & 15) * 64;
    const float* src = (mi == 0 ? Wq : (mi == 1 ? Wk : Wv)) + (size_t)h * EE * DD;
    const int tid = threadIdx.x;

    #pragma unroll
    for (int i = 0; i < 4; ++i) {
        int idx = tid + i * 256;
        int ei = idx >> 4, d4 = idx & 15;
        float4 v = ((const float4*)(src + (size_t)(e0 + ei) * DD))[d4];
        ts[ei][d4 * 4 + 0] = v.x; ts[ei][d4 * 4 + 1] = v.y;
        ts[ei][d4 * 4 + 2] = v.z; ts[ei][d4 * 4 + 3] = v.w;
    }
    __syncthreads();

    const int d = tid >> 2, seg = tid & 3;
    const size_t row = ((size_t)mi * 1024 + h * 64 + d) * EE + e0 + seg * 16;
    alignas(16) __half hb[16], lb[16];
    #pragma unroll
    for (int i = 0; i < 16; ++i) {
        float v = ts[seg * 16 + i][d];
        __half hv = __float2half_rn(v);
        hb[i] = hv;
        lb[i] = __float2half_rn(v - __half2float(hv));
    }
    *(uint4*)(th + row)     = *(const uint4*)(hb);
    *(uint4*)(th + row + 8) = *(const uint4*)(hb + 8);
    *(uint4*)(tl + row)     = *(const uint4*)(lb);
    *(uint4*)(tl + row + 8) = *(const uint4*)(lb + 8);
}

// ---------------------------------------------------------------------------
// HMMA split-fp16 GEMM, 128Mx128N block, warp 32x64, 2 CTAs/SM.
// MODE 0 (qkv): 2-pass  C = Ah.Bh + Al.Bh (weight-lo dropped; err ~2^-11)
// MODE 1 (out): 3-pass  C = Ah.Bh + Al.Bh + Ah.Bl
// ---------------------------------------------------------------------------
#define PITCH 40
#define A_ELEMS (128 * PITCH)            // 5120
#define B_ELEMS (128 * PITCH)            // 5120
#define STB0 ((2 * A_ELEMS + 1 * B_ELEMS) * 2)   // 30720 (mode 0)
#define STB1 ((2 * A_ELEMS + 2 * B_ELEMS) * 2)   // 40960 (mode 1)

template <int MODE>
__global__ __launch_bounds__(256, 2)
void mma_gemm(const __half* __restrict__ Ah, const __half* __restrict__ Al,
              const __half* __restrict__ Bh, const __half* __restrict__ Bl,
              const float* __restrict__ bias,
              __half* __restrict__ qh, __half* __restrict__ ql,
              __half* __restrict__ kh, __half* __restrict__ kl,
              __half* __restrict__ vh, __half* __restrict__ vl,
              float* __restrict__ oplain)
{
    constexpr uint32_t STAGE_BYTES = (MODE == 0) ? STB0 : STB1;
    extern __shared__ char sm[];
    const uint32_t sbase = smem_u32(sm);
    const int tid = threadIdx.x;
    const int wid = tid >> 5, lane = tid & 31;
    const int wm = wid & 3, wn = wid >> 2;       // 4 M-warps x 2 N-warps
    const int n0 = blockIdx.x * 128;
    const int m0 = blockIdx.y * 128;

    const int a_row = lane & 15;
    const int a_col = (lane >> 4) << 3;
    const int b_row = ((lane >> 4) << 3) + (lane & 7);
    const int b_col = ((lane >> 3) & 1) << 3;

    float c[2][8][4] = {};    // warp tile 32x64: 8 independent accum tiles

    // pointer-increment loader (each thread: rows lr & lr+64, 16B segment lseg)
    const int lr = tid >> 2, lseg = tid & 3;     // lr: 0..63
    const __half* pA0 = Ah + (size_t)(m0 + lr) * EE + lseg * 8;
    const __half* pA1 = Al + (size_t)(m0 + lr) * EE + lseg * 8;
    const __half* pB0 = Bh + (size_t)(n0 + lr) * EE + lseg * 8;
    const __half* pB1 = (MODE == 1) ? Bl + (size_t)(n0 + lr) * EE + lseg * 8 : nullptr;
    const uint32_t doff = (uint32_t)(lr * PITCH + lseg * 8) * 2;

    auto stage_load = [&](uint32_t bufbase) {
        const uint32_t d0 = bufbase + doff;
        CP_ASYNC16(d0,                                  pA0);
        CP_ASYNC16(d0 + 64 * PITCH * 2,                 pA0 + (size_t)64 * EE);
        CP_ASYNC16(d0 + A_ELEMS * 2,                    pA1);
        CP_ASYNC16(d0 + A_ELEMS * 2 + 64 * PITCH * 2,   pA1 + (size_t)64 * EE);
        const uint32_t b0 = d0 + 2 * A_ELEMS * 2;
        CP_ASYNC16(b0,                                  pB0);
        CP_ASYNC16(b0 + 64 * PITCH * 2,                 pB0 + (size_t)64 * EE);
        if (MODE == 1) {
            CP_ASYNC16(b0 + B_ELEMS * 2,                  pB1);
            CP_ASYNC16(b0 + B_ELEMS * 2 + 64 * PITCH * 2, pB1 + (size_t)64 * EE);
            pB1 += 32;
        }
        CP_COMMIT();
        pA0 += 32; pA1 += 32; pB0 += 32;
    };

    stage_load(sbase);
    stage_load(sbase + STAGE_BYTES);

    for (int ch = 0; ch < 32; ++ch) {
        if (ch < 31) CP_WAIT(1);
        else         CP_WAIT(0);
        __syncthreads();

        const uint32_t sb  = sbase + (ch & 1) * STAGE_BYTES;
        const uint32_t sAh = sb;
        const uint32_t sAl = sb + A_ELEMS * 2;
        const uint32_t sBh = sb + 2 * A_ELEMS * 2;
        const uint32_t sBl = sBh + B_ELEMS * 2;   // valid only MODE 1

        #pragma unroll
        for (int ks = 0; ks < 2; ++ks) {
            uint32_t ah[2][4], alr[2][4];
            #pragma unroll
            for (int mi = 0; mi < 2; ++mi) {
                uint32_t off = (uint32_t)((wm * 32 + mi * 16 + a_row) * PITCH
                                          + ks * 16 + a_col) * 2;
                LDSM4(ah[mi],  sAh + off);
                LDSM4(alr[mi], sAl + off);
            }
            #pragma unroll
            for (int jp = 0; jp < 4; ++jp) {      // 4 x 16-col B groups
                uint32_t bb[4];
                uint32_t off = (uint32_t)((wn * 64 + jp * 16 + b_row) * PITCH
                                          + ks * 16 + b_col) * 2;
                LDSM4(bb, sBh + off);
                #pragma unroll
                for (int mi = 0; mi < 2; ++mi)
                    #pragma unroll
                    for (int t = 0; t < 2; ++t)
                        MMA16816(c[mi][jp * 2 + t], ah[mi],  bb[t * 2], bb[t * 2 + 1]);
                #pragma unroll
                for (int mi = 0; mi < 2; ++mi)
                    #pragma unroll
                    for (int t = 0; t < 2; ++t)
                        MMA16816(c[mi][jp * 2 + t], alr[mi], bb[t * 2], bb[t * 2 + 1]);
                if (MODE == 1) {
                    LDSM4(bb, sBl + off);         // reuse regs for Bl
                    #pragma unroll
                    for (int mi = 0; mi < 2; ++mi)
                        #pragma unroll
                        for (int t = 0; t < 2; ++t)
                            MMA16816(c[mi][jp * 2 + t], ah[mi], bb[t * 2], bb[t * 2 + 1]);
                }
            }
        }
        __syncthreads();
        if (ch + 2 < 32) stage_load(sb);
    }

    const int rbase = m0 + wm * 32 + (lane >> 2);
    const int cpair = (lane & 3) * 2;

    if (MODE == 0) {
        const int which = n0 >> 10;
        __half *dh, *dl;
        if (which == 0)      { dh = qh; dl = ql; }
        else if (which == 1) { dh = kh; dl = kl; }
        else                 { dh = vh; dl = vl; }
        const float sc = (which == 0) ? SCALE_Q : 1.0f;
        const int h = ((n0 & 1023) >> 6) + wn;
        #pragma unroll
        for (int mi = 0; mi < 2; ++mi) {
            const int m1 = rbase + mi * 16;
            const int m2 = m1 + 8;
            const size_t base1 = (((size_t)(m1 >> 11) * HH + h) * TT + (m1 & 2047)) * DD;
            const size_t base2 = (((size_t)(m2 >> 11) * HH + h) * TT + (m2 & 2047)) * DD;
            #pragma unroll
            for (int nt = 0; nt < 8; ++nt) {
                const int d = nt * 8 + cpair;
                uint32_t h1, l1, h2, l2;
                split2(c[mi][nt][0] * sc, c[mi][nt][1] * sc, h1, l1);
                split2(c[mi][nt][2] * sc, c[mi][nt][3] * sc, h2, l2);
                *(uint32_t*)(dh + base1 + d) = h1;
                *(uint32_t*)(dl + base1 + d) = l1;
                *(uint32_t*)(dh + base2 + d) = h2;
                *(uint32_t*)(dl + base2 + d) = l2;
            }
        }
    } else {
        #pragma unroll
        for (int mi = 0; mi < 2; ++mi) {
            const int m1 = rbase + mi * 16;
            float* r1 = oplain + (size_t)m1 * EE;
            float* r2 = oplain + (size_t)(m1 + 8) * EE;
            #pragma unroll
            for (int nt = 0; nt < 8; ++nt) {
                const int col = n0 + wn * 64 + nt * 8 + cpair;
                const float b0 = bias[col], b1v = bias[col + 1];
                float2 v1 = make_float2(c[mi][nt][0] + b0, c[mi][nt][1] + b1v);
                float2 v2 = make_float2(c[mi][nt][2] + b0, c[mi][nt][3] + b1v);
                *(float2*)(r1 + col) = v1;
                *(float2*)(r2 + col) = v2;
            }
        }
    }
}

// ---------------------------------------------------------------------------
// Tensor-core causal flash attention: 2 CTAs/SM, 2-stage KV ring, fp16 3-pass.
// Epilogue writes fp16 hi/lo ctx directly.
// ---------------------------------------------------------------------------
#define AP 72
#define SM_Q 0
#define QARR (128 * AP * 2)
#define SM_STAGE (2 * QARR)
#define KVARR (64 * AP * 2)
#define STAGE_SZ (4 * KVARR)
#define SM_MASK (SM_STAGE + 2 * STAGE_SZ)
#define SM_TOTAL (SM_MASK + 2 * 256)

__global__ __launch_bounds__(256, 2)
void attn_mma(const __half* __restrict__ qh, const __half* __restrict__ ql,
              const __half* __restrict__ kh, const __half* __restrict__ kl,
              const __half* __restrict__ vh, const __half* __restrict__ vl,
              const float* __restrict__ amask,
              __half* __restrict__ chi, __half* __restrict__ clo)
{
    extern __shared__ char sm[];
    const uint32_t sbase = smem_u32(sm);
    const int tid = threadIdx.x;
    const int w = tid >> 5, lane = tid & 31;
    const int bh = blockIdx.x;
    const int b_ = bh >> 4, h = bh & 15;
    const int qt = 15 - blockIdx.y;
    const int q0 = qt * 128;
    const int last = 2 * qt + 1;

    const int a_row = lane & 15;
    const int a_col = (lane >> 4) << 3;
    const int b_row = ((lane >> 4) << 3) + (lane & 7);
    const int b_col = ((lane >> 3) & 1) << 3;
    const int v_key = (lane & 7) + (((lane >> 3) & 1) << 3);
    const int v_d   = (lane >> 4) << 3;

    const size_t gbase = (size_t)bh * TT * DD;

    auto load_q = [&]() {
        #pragma unroll
        for (int arr = 0; arr < 2; ++arr) {
            const __half* src0 = arr ? ql : qh;
            #pragma unroll
            for (int half = 0; half < 4; ++half) {
                int loc = half * 256 + tid;
                int r = loc >> 3, seg = loc & 7;
                const __half* src = src0 + gbase + (size_t)(q0 + r) * DD + seg * 8;
                uint32_t dst = sbase + SM_Q + arr * QARR + (uint32_t)(r * AP + seg * 8) * 2;
                CP_ASYNC16(dst, src);
            }
        }
    };
    auto load_kv = [&](int buf, int kt) {
        const int s0 = kt * 64;
        #pragma unroll
        for (int arr = 0; arr < 4; ++arr) {
            const __half* src0 = (arr == 0) ? kh : (arr == 1) ? kl
                                : (arr == 2) ? vh : vl;
            #pragma unroll
            for (int half = 0; half < 2; ++half) {
                int loc = half * 256 + tid;
                int r = loc >> 3, seg = loc & 7;
                const __half* src = src0 + gbase + (size_t)(s0 + r) * DD + seg * 8;
                uint32_t dst = sbase + SM_STAGE + buf * STAGE_SZ + arr * KVARR
                             + (uint32_t)(r * AP + seg * 8) * 2;
                CP_ASYNC16(dst, src);
            }
        }
        if (tid < 16) {
            const float* msrc = amask + (size_t)b_ * TT + s0 + tid * 4;
            uint32_t mdst = sbase + SM_MASK + buf * 256 + tid * 16;
            CP_ASYNC16(mdst, msrc);
        }
        CP_COMMIT();
    };

    load_q();
    load_kv(0, 0);
    load_kv(1, 1);
    CP_WAIT(1);
    __syncthreads();

    uint32_t qa_h[4][4], qa_l[4][4];
    #pragma unroll
    for (int ks = 0; ks < 4; ++ks) {
        uint32_t off = (uint32_t)((w * 16 + a_row) * AP + ks * 16 + a_col) * 2;
        LDSM4(qa_h[ks], sbase + SM_Q + off);
        LDSM4(qa_l[ks], sbase + SM_Q + QARR + off);
    }

    float o[8][4] = {};
    float m0r = -1e30f, m1r = -1e30f, l0 = 0.f, l1 = 0.f;
    const int row0 = q0 + w * 16 + (lane >> 2);
    const int wrow_hi = q0 + w * 16 + 15;

    for (int kt = 0; kt <= last; ++kt) {
        if (kt < last) CP_WAIT(1);
        else           CP_WAIT(0);
        __syncthreads();

        const int buf = kt & 1;
        const int s0 = kt * 64;
        const bool active = (s0 <= wrow_hi);

        if (active) {
            const uint32_t kb = sbase + SM_STAGE + buf * STAGE_SZ;
            // ---- S = Q.K^T, 3-pass, K frags in 32-col halves ----
            float c[8][4] = {};
            #pragma unroll
            for (int ks = 0; ks < 4; ++ks) {
                #pragma unroll
                for (int hf = 0; hf < 2; ++hf) {
                    uint32_t kf[2][4];
                    #pragma unroll
                    for (int j = 0; j < 2; ++j) {
                        uint32_t off = (uint32_t)(((hf * 2 + j) * 16 + b_row) * AP
                                                  + ks * 16 + b_col) * 2;
                        LDSM4(kf[j], kb + off);
                    }
                    #pragma unroll
                    for (int t = 0; t < 4; ++t) {
                        const int nt = hf * 4 + t;
                        const int j = t >> 1, q = (t & 1) * 2;
                        MMA16816(c[nt], qa_h[ks], kf[j][q], kf[j][q + 1]);
                    }
                    #pragma unroll
                    for (int t = 0; t < 4; ++t) {
                        const int nt = hf * 4 + t;
                        const int j = t >> 1, q = (t & 1) * 2;
                        MMA16816(c[nt], qa_l[ks], kf[j][q], kf[j][q + 1]);
                    }
                    #pragma unroll
                    for (int j = 0; j < 2; ++j) {
                        uint32_t off = (uint32_t)(((hf * 2 + j) * 16 + b_row) * AP
                                                  + ks * 16 + b_col) * 2;
                        LDSM4(kf[j], kb + KVARR + off);   // reload as K-lo
                    }
                    #pragma unroll
                    for (int t = 0; t < 4; ++t) {
                        const int nt = hf * 4 + t;
                        const int j = t >> 1, q = (t & 1) * 2;
                        MMA16816(c[nt], qa_h[ks], kf[j][q], kf[j][q + 1]);
                    }
                }
            }
            // ---- mask + causal ----
            const float* mk = (const float*)(sm + SM_MASK + buf * 256);
            const bool dg = (s0 + 63) > (q0 + w * 16);
            #pragma unroll
            for (int nt = 0; nt < 8; ++nt) {
                const int cl = nt * 8 + (lane & 3) * 2;
                const float mv0 = mk[cl], mv1 = mk[cl + 1];
                const float ma0 = (1.0f - mv0) * -1e30f;
                const float ma1 = (1.0f - mv1) * -1e30f;
                c[nt][0] += ma0; c[nt][1] += ma1;
                c[nt][2] += ma0; c[nt][3] += ma1;
                if (dg) {
                    const int cg = s0 + cl;
                    if (cg     > row0)     c[nt][0] = -1e30f;
                    if (cg + 1 > row0)     c[nt][1] = -1e30f;
                    if (cg     > row0 + 8) c[nt][2] = -1e30f;
                    if (cg + 1 > row0 + 8) c[nt][3] = -1e30f;
                }
            }
            // ---- online softmax ----
            float t0 = -1e30f, t1 = -1e30f;
            #pragma unroll
            for (int nt = 0; nt < 8; ++nt) {
                t0 = fmaxf(t0, fmaxf(c[nt][0], c[nt][1]));
                t1 = fmaxf(t1, fmaxf(c[nt][2], c[nt][3]));
            }
            t0 = fmaxf(t0, __shfl_xor_sync(0xffffffffu, t0, 1));
            t0 = fmaxf(t0, __shfl_xor_sync(0xffffffffu, t0, 2));
            t1 = fmaxf(t1, __shfl_xor_sync(0xffffffffu, t1, 1));
            t1 = fmaxf(t1, __shfl_xor_sync(0xffffffffu, t1, 2));
            const float mn0 = fmaxf(m0r, t0), mn1 = fmaxf(m1r, t1);
            const float cor0 = exp2fast(m0r - mn0), cor1 = exp2fast(m1r - mn1);
            m0r = mn0; m1r = mn1;
            l0 *= cor0; l1 *= cor1;
            #pragma unroll
            for (int nt = 0; nt < 8; ++nt) {
                o[nt][0] *= cor0; o[nt][1] *= cor0;
                o[nt][2] *= cor1; o[nt][3] *= cor1;
            }
            // ---- fused P conversion + O += P.V (3-pass) ----
            float s0sum = 0.f, s1sum = 0.f;
            #pragma unroll
            for (int ks = 0; ks < 4; ++ks) {
                uint32_t pa_h[4], pa_l[4];
                #pragma unroll
                for (int t = 0; t < 2; ++t) {
                    const int nt = ks * 2 + t;
                    const float p0 = exp2fast(c[nt][0] - mn0);
                    const float p1 = exp2fast(c[nt][1] - mn0);
                    const float p2 = exp2fast(c[nt][2] - mn1);
                    const float p3 = exp2fast(c[nt][3] - mn1);
                    s0sum += p0 + p1; s1sum += p2 + p3;
                    split2(p0, p1, pa_h[t * 2], pa_l[t * 2]);
                    split2(p2, p3, pa_h[t * 2 + 1], pa_l[t * 2 + 1]);
                }
                #pragma unroll
                for (int hf = 0; hf < 2; ++hf) {
                    uint32_t vf[2][4];
                    #pragma unroll
                    for (int j = 0; j < 2; ++j) {
                        uint32_t off = (uint32_t)((ks * 16 + v_key) * AP
                                                  + (hf * 2 + j) * 16 + v_d) * 2;
                        LDSM4T(vf[j], kb + 2 * KVARR + off);
                    }
                    #pragma unroll
                    for (int t = 0; t < 4; ++t) {
                        const int nt = hf * 4 + t;
                        const int j = t >> 1, q = (t & 1) * 2;
                        MMA16816(o[nt], pa_h, vf[j][q], vf[j][q + 1]);
                    }
                    #pragma unroll
                    for (int t = 0; t < 4; ++t) {
                        const int nt = hf * 4 + t;
                        const int j = t >> 1, q = (t & 1) * 2;
                        MMA16816(o[nt], pa_l, vf[j][q], vf[j][q + 1]);
                    }
                    #pragma unroll
                    for (int j = 0; j < 2; ++j) {
                        uint32_t off = (uint32_t)((ks * 16 + v_key) * AP
                                                  + (hf * 2 + j) * 16 + v_d) * 2;
                        LDSM4T(vf[j], kb + 3 * KVARR + off);   // reload as V-lo
                    }
                    #pragma unroll
                    for (int t = 0; t < 4; ++t) {
                        const int nt = hf * 4 + t;
                        const int j = t >> 1, q = (t & 1) * 2;
                        MMA16816(o[nt], pa_h, vf[j][q], vf[j][q + 1]);
                    }
                }
            }
            s0sum += __shfl_xor_sync(0xffffffffu, s0sum, 1);
            s0sum += __shfl_xor_sync(0xffffffffu, s0sum, 2);
            s1sum += __shfl_xor_sync(0xffffffffu, s1sum, 1);
            s1sum += __shfl_xor_sync(0xffffffffu, s1sum, 2);
            l0 += s0sum; l1 += s1sum;
        }
        __syncthreads();
        if (kt + 2 <= last) load_kv(buf, kt + 2);
    }

    // ---- normalize + split + store fp16 hi/lo ctx [B,T,E] ----
    const float inv0 = 1.0f / l0, inv1 = 1.0f / l1;
    const int cpair = (lane & 3) * 2;
    const size_t r1 = ((size_t)b_ * TT + row0) * EE + h * 64;
    const size_t r2 = ((size_t)b_ * TT + row0 + 8) * EE + h * 64;
    #pragma unroll
    for (int nt = 0; nt < 8; ++nt) {
        const int d = nt * 8 + cpair;
        uint32_t h1, l1w, h2, l2;
        split2(o[nt][0] * inv0, o[nt][1] * inv0, h1, l1w);
        split2(o[nt][2] * inv1, o[nt][3] * inv1, h2, l2);
        *(uint32_t*)(chi + r1 + d) = h1;
        *(uint32_t*)(clo + r1 + d) = l1w;
        *(uint32_t*)(chi + r2 + d) = h2;
        *(uint32_t*)(clo + r2 + d) = l2;
    }
}

// ---------------------------------------------------------------------------
// Launch
// ---------------------------------------------------------------------------
extern "C" void kernel_launch(void* const* d_in, const int* in_sizes, int n_in,
                              void* d_out, int out_size)
{
    const float* x     = (const float*)d_in[0];
    const float* amask = (const float*)d_in[1];
    const float* Wq    = (const float*)d_in[2];
    const float* Wk    = (const float*)d_in[3];
    const float* Wv    = (const float*)d_in[4];
    const float* Wo    = (const float*)d_in[5];
    const float* bo    = (const float*)d_in[6];
    float* out = (float*)d_out;

    __half *xhi, *xlo, *wth, *wtl, *woh, *wol, *chi, *clo;
    __half *qh, *ql, *kh, *kl, *vh, *vl;
    cudaGetSymbolAddress((void**)&xhi, g_xhi);
    cudaGetSymbolAddress((void**)&xlo, g_xlo);
    cudaGetSymbolAddress((void**)&wth, g_wth);
    cudaGetSymbolAddress((void**)&wtl, g_wtl);
    cudaGetSymbolAddress((void**)&woh, g_woh);
    cudaGetSymbolAddress((void**)&wol, g_wol);
    cudaGetSymbolAddress((void**)&chi, g_chi);
    cudaGetSymbolAddress((void**)&clo, g_clo);
    cudaGetSymbolAddress((void**)&qh,  g_qh);
    cudaGetSymbolAddress((void**)&ql,  g_ql);
    cudaGetSymbolAddress((void**)&kh,  g_kh);
    cudaGetSymbolAddress((void**)&kl,  g_kl);
    cudaGetSymbolAddress((void**)&vh,  g_vh);
    cudaGetSymbolAddress((void**)&vl,  g_vl);

    cudaFuncSetAttribute(mma_gemm<0>, cudaFuncAttributeMaxDynamicSharedMemorySize,
                         2 * STB0);
    cudaFuncSetAttribute(mma_gemm<1>, cudaFuncAttributeMaxDynamicSharedMemorySize,
                         2 * STB1);
    cudaFuncSetAttribute(attn_mma, cudaFuncAttributeMaxDynamicSharedMemorySize,
                         SM_TOTAL);

    conv_hilo<<<(BT * EE / 4) / 256, 256>>>(x, xhi, xlo, BT * EE / 4);
    prep_wt<<<768, 256>>>(Wq, Wk, Wv, wth, wtl);
    conv_hilo<<<(EE * EE / 4) / 256, 256>>>(Wo, woh, wol, EE * EE / 4);

    {   // QKV projection -> fp16 hi/lo q,k,v (2-pass)
        dim3 grid(NQKV / 128, BT / 128);
        mma_gemm<0><<<grid, 256, 2 * STB0>>>(xhi, xlo, wth, wtl, nullptr,
                                             qh, ql, kh, kl, vh, vl, nullptr);
    }
    {   // attention -> fp16 hi/lo ctx (3-pass)
        dim3 grid(BB * HH, TT / 128);
        attn_mma<<<grid, 256, SM_TOTAL>>>(qh, ql, kh, kl, vh, vl, amask, chi, clo);
    }
    {   // output projection (3-pass)
        dim3 grid(EE / 128, BT / 128);
        mma_gemm<1><<<grid, 256, 2 * STB1>>>(chi, clo, woh, wol, bo,
                                             nullptr, nullptr, nullptr,
                                             nullptr, nullptr, nullptr, out);
    }
}

// round 11
// speedup vs baseline: 1.4376x; 1.1556x over previous
#include <cuda_runtime.h>
#include <cuda_fp16.h>
#include <math_constants.h>
#include <cstdint>

// Problem constants
#define BB 4
#define TT 2048
#define EE 1024
#define HH 16
#define DD 64
#define BT (BB*TT)          // 8192
#define NQKV 3072

#define L2E 1.44269504f
#define SCALE_Q (0.125f * L2E)    // fold 1/sqrt(D) and log2(e) into q

// ---------------------------------------------------------------------------
// Scratch (allocation-free rule: __device__ globals)  — fp16 hi/lo
// ---------------------------------------------------------------------------
__device__ __align__(16) __half g_xhi[(size_t)BT*EE];
__device__ __align__(16) __half g_xlo[(size_t)BT*EE];
__device__ __align__(16) __half g_wth[(size_t)NQKV*EE];
__device__ __align__(16) __half g_wtl[(size_t)NQKV*EE];   // unused by 2-pass qkv
__device__ __align__(16) __half g_woh[(size_t)EE*EE];
__device__ __align__(16) __half g_wol[(size_t)EE*EE];
__device__ __align__(16) __half g_chi[(size_t)BT*EE];     // attn out hi
__device__ __align__(16) __half g_clo[(size_t)BT*EE];     // attn out lo

// fp16 q (hi+lo), k/v (hi only) in [B,H,T,D]
__device__ __align__(16) __half g_qh[(size_t)BB*HH*TT*DD];
__device__ __align__(16) __half g_ql[(size_t)BB*HH*TT*DD];
__device__ __align__(16) __half g_kh[(size_t)BB*HH*TT*DD];
__device__ __align__(16) __half g_vh[(size_t)BB*HH*TT*DD];

// ---------------------------------------------------------------------------
// Helpers (base sm_103 ISA: mma.sync / ldmatrix / cp.async)
// ---------------------------------------------------------------------------
__device__ __forceinline__ uint32_t smem_u32(const void* p) {
    uint32_t a;
    asm("{ .reg .u64 t; cvta.to.shared.u64 t, %1; cvt.u32.u64 %0, t; }"
        : "=r"(a) : "l"(p));
    return a;
}

#define LDSM4(r, addr) \
    asm volatile("ldmatrix.sync.aligned.m8n8.x4.shared.b16 {%0,%1,%2,%3}, [%4];" \
        : "=r"((r)[0]), "=r"((r)[1]), "=r"((r)[2]), "=r"((r)[3]) : "r"(addr))

#define LDSM4T(r, addr) \
    asm volatile("ldmatrix.sync.aligned.m8n8.x4.trans.shared.b16 {%0,%1,%2,%3}, [%4];" \
        : "=r"((r)[0]), "=r"((r)[1]), "=r"((r)[2]), "=r"((r)[3]) : "r"(addr))

#define MMA16816(c, a, b0, b1) \
    asm volatile("mma.sync.aligned.m16n8k16.row.col.f32.f16.f16.f32 " \
        "{%0,%1,%2,%3}, {%4,%5,%6,%7}, {%8,%9}, {%0,%1,%2,%3};" \
        : "+f"((c)[0]), "+f"((c)[1]), "+f"((c)[2]), "+f"((c)[3]) \
        : "r"((a)[0]), "r"((a)[1]), "r"((a)[2]), "r"((a)[3]), "r"(b0), "r"(b1))

#define CP_ASYNC16(dst, src) \
    asm volatile("cp.async.cg.shared.global [%0], [%1], 16;" :: "r"(dst), "l"(src))
#define CP_COMMIT() asm volatile("cp.async.commit_group;" ::: "memory")
#define CP_WAIT(n)  asm volatile("cp.async.wait_group %0;" :: "n"(n) : "memory")

// split two floats into packed fp16x2 hi and lo residual
__device__ __forceinline__ void split2(float a, float b, uint32_t& hi, uint32_t& lo) {
    __half ha = __float2half_rn(a), hb = __float2half_rn(b);
    float ra = a - __half2float(ha);
    float rb = b - __half2float(hb);
    __half2 H = __halves2half2(ha, hb);
    __half2 L = __halves2half2(__float2half_rn(ra), __float2half_rn(rb));
    hi = *(uint32_t*)&H;
    lo = *(uint32_t*)&L;
}

__device__ __forceinline__ uint32_t pack_h2(float a, float b) {
    __half2 H = __halves2half2(__float2half_rn(a), __float2half_rn(b));
    return *(uint32_t*)&H;
}

// fast exp2 on the FMA pipe (degree-7, rel err ~1e-6)
__device__ __forceinline__ float exp2fast(float x) {
    x = fmaxf(x, -125.0f);
    int n = __float2int_rd(x);
    float f = x - (float)n;
    float p = 1.3570247e-5f;
    p = fmaf(p, f, 1.5353362e-4f);
    p = fmaf(p, f, 1.3398874e-3f);
    p = fmaf(p, f, 9.6184374e-3f);
    p = fmaf(p, f, 5.5503325e-2f);
    p = fmaf(p, f, 2.4022648e-1f);
    p = fmaf(p, f, 6.9314720e-1f);
    p = fmaf(p, f, 1.0f);
    return p * __int_as_float((n + 127) << 23);
}

// ---------------------------------------------------------------------------
// Prep: fp32 -> (fp16 hi, fp16 lo)
// ---------------------------------------------------------------------------
__global__ __launch_bounds__(256) void conv_hilo(
    const float* __restrict__ s, __half* __restrict__ hi,
    __half* __restrict__ lo, int n4)
{
    int i = blockIdx.x * 256 + threadIdx.x;
    if (i >= n4) return;
    float4 v = ((const float4*)s)[i];
    uint32_t h0, l0, h1, l1;
    split2(v.x, v.y, h0, l0);
    split2(v.z, v.w, h1, l1);
    ((uint32_t*)hi)[i * 2 + 0] = h0;
    ((uint32_t*)hi)[i * 2 + 1] = h1;
    ((uint32_t*)lo)[i * 2 + 0] = l0;
    ((uint32_t*)lo)[i * 2 + 1] = l1;
}

// ---------------------------------------------------------------------------
// Prep: transpose+split qkv weights. W[h][e][d] -> Wt[n][e]
// ---------------------------------------------------------------------------
__global__ __launch_bounds__(256) void prep_wt(
    const float* __restrict__ Wq, const float* __restrict__ Wk,
    const float* __restrict__ Wv,
    __half* __restrict__ th, __half* __restrict__ tl)
{
    __shared__ float ts[64][65];
    const int bx = blockIdx.x;
    const int mi = bx >> 8;
    const int rem = bx & 255;
    const int h = rem >> 4;
    const int e0 = (rem & 15) * 64;
    const float* src = (mi == 0 ? Wq : (mi == 1 ? Wk : Wv)) + (size_t)h * EE * DD;
    const int tid = threadIdx.x;

    #pragma unroll
    for (int i = 0; i < 4; ++i) {
        int idx = tid + i * 256;
        int ei = idx >> 4, d4 = idx & 15;
        float4 v = ((const float4*)(src + (size_t)(e0 + ei) * DD))[d4];
        ts[ei][d4 * 4 + 0] = v.x; ts[ei][d4 * 4 + 1] = v.y;
        ts[ei][d4 * 4 + 2] = v.z; ts[ei][d4 * 4 + 3] = v.w;
    }
    __syncthreads();

    const int d = tid >> 2, seg = tid & 3;
    const size_t row = ((size_t)mi * 1024 + h * 64 + d) * EE + e0 + seg * 16;
    alignas(16) __half hb[16], lb[16];
    #pragma unroll
    for (int i = 0; i < 16; ++i) {
        float v = ts[seg * 16 + i][d];
        __half hv = __float2half_rn(v);
        hb[i] = hv;
        lb[i] = __float2half_rn(v - __half2float(hv));
    }
    *(uint4*)(th + row)     = *(const uint4*)(hb);
    *(uint4*)(th + row + 8) = *(const uint4*)(hb + 8);
    *(uint4*)(tl + row)     = *(const uint4*)(lb);
    *(uint4*)(tl + row + 8) = *(const uint4*)(lb + 8);
}

// ---------------------------------------------------------------------------
// HMMA split-fp16 GEMM, 128Mx128N block, warp 32x64, 2 CTAs/SM.
// MODE 0 (qkv): 2-pass  C = Ah.Bh + Al.Bh   -> q hi+lo, k/v hi only
// MODE 1 (out): 3-pass  C = Ah.Bh + Al.Bh + Ah.Bl -> fp32 + bias
// ---------------------------------------------------------------------------
#define PITCH 40
#define A_ELEMS (128 * PITCH)            // 5120
#define B_ELEMS (128 * PITCH)            // 5120
#define STB0 ((2 * A_ELEMS + 1 * B_ELEMS) * 2)   // 30720 (mode 0)
#define STB1 ((2 * A_ELEMS + 2 * B_ELEMS) * 2)   // 40960 (mode 1)

template <int MODE>
__global__ __launch_bounds__(256, 2)
void mma_gemm(const __half* __restrict__ Ah, const __half* __restrict__ Al,
              const __half* __restrict__ Bh, const __half* __restrict__ Bl,
              const float* __restrict__ bias,
              __half* __restrict__ qh, __half* __restrict__ ql,
              __half* __restrict__ kh, __half* __restrict__ vh,
              float* __restrict__ oplain)
{
    constexpr uint32_t STAGE_BYTES = (MODE == 0) ? STB0 : STB1;
    extern __shared__ char sm[];
    const uint32_t sbase = smem_u32(sm);
    const int tid = threadIdx.x;
    const int wid = tid >> 5, lane = tid & 31;
    const int wm = wid & 3, wn = wid >> 2;       // 4 M-warps x 2 N-warps
    const int n0 = blockIdx.x * 128;
    const int m0 = blockIdx.y * 128;

    const int a_row = lane & 15;
    const int a_col = (lane >> 4) << 3;
    const int b_row = ((lane >> 4) << 3) + (lane & 7);
    const int b_col = ((lane >> 3) & 1) << 3;

    float c[2][8][4] = {};    // warp tile 32x64

    const int lr = tid >> 2, lseg = tid & 3;
    const __half* pA0 = Ah + (size_t)(m0 + lr) * EE + lseg * 8;
    const __half* pA1 = Al + (size_t)(m0 + lr) * EE + lseg * 8;
    const __half* pB0 = Bh + (size_t)(n0 + lr) * EE + lseg * 8;
    const __half* pB1 = (MODE == 1) ? Bl + (size_t)(n0 + lr) * EE + lseg * 8 : nullptr;
    const uint32_t doff = (uint32_t)(lr * PITCH + lseg * 8) * 2;

    auto stage_load = [&](uint32_t bufbase) {
        const uint32_t d0 = bufbase + doff;
        CP_ASYNC16(d0,                                  pA0);
        CP_ASYNC16(d0 + 64 * PITCH * 2,                 pA0 + (size_t)64 * EE);
        CP_ASYNC16(d0 + A_ELEMS * 2,                    pA1);
        CP_ASYNC16(d0 + A_ELEMS * 2 + 64 * PITCH * 2,   pA1 + (size_t)64 * EE);
        const uint32_t b0 = d0 + 2 * A_ELEMS * 2;
        CP_ASYNC16(b0,                                  pB0);
        CP_ASYNC16(b0 + 64 * PITCH * 2,                 pB0 + (size_t)64 * EE);
        if (MODE == 1) {
            CP_ASYNC16(b0 + B_ELEMS * 2,                  pB1);
            CP_ASYNC16(b0 + B_ELEMS * 2 + 64 * PITCH * 2, pB1 + (size_t)64 * EE);
            pB1 += 32;
        }
        CP_COMMIT();
        pA0 += 32; pA1 += 32; pB0 += 32;
    };

    stage_load(sbase);
    stage_load(sbase + STAGE_BYTES);

    for (int ch = 0; ch < 32; ++ch) {
        if (ch < 31) CP_WAIT(1);
        else         CP_WAIT(0);
        __syncthreads();

        const uint32_t sb  = sbase + (ch & 1) * STAGE_BYTES;
        const uint32_t sAh = sb;
        const uint32_t sAl = sb + A_ELEMS * 2;
        const uint32_t sBh = sb + 2 * A_ELEMS * 2;
        const uint32_t sBl = sBh + B_ELEMS * 2;   // MODE 1 only

        #pragma unroll
        for (int ks = 0; ks < 2; ++ks) {
            uint32_t ah[2][4], alr[2][4];
            #pragma unroll
            for (int mi = 0; mi < 2; ++mi) {
                uint32_t off = (uint32_t)((wm * 32 + mi * 16 + a_row) * PITCH
                                          + ks * 16 + a_col) * 2;
                LDSM4(ah[mi],  sAh + off);
                LDSM4(alr[mi], sAl + off);
            }
            #pragma unroll
            for (int jp = 0; jp < 4; ++jp) {
                uint32_t bb[4];
                uint32_t off = (uint32_t)((wn * 64 + jp * 16 + b_row) * PITCH
                                          + ks * 16 + b_col) * 2;
                LDSM4(bb, sBh + off);
                #pragma unroll
                for (int mi = 0; mi < 2; ++mi)
                    #pragma unroll
                    for (int t = 0; t < 2; ++t)
                        MMA16816(c[mi][jp * 2 + t], ah[mi],  bb[t * 2], bb[t * 2 + 1]);
                #pragma unroll
                for (int mi = 0; mi < 2; ++mi)
                    #pragma unroll
                    for (int t = 0; t < 2; ++t)
                        MMA16816(c[mi][jp * 2 + t], alr[mi], bb[t * 2], bb[t * 2 + 1]);
                if (MODE == 1) {
                    LDSM4(bb, sBl + off);
                    #pragma unroll
                    for (int mi = 0; mi < 2; ++mi)
                        #pragma unroll
                        for (int t = 0; t < 2; ++t)
                            MMA16816(c[mi][jp * 2 + t], ah[mi], bb[t * 2], bb[t * 2 + 1]);
                }
            }
        }
        __syncthreads();
        if (ch + 2 < 32) stage_load(sb);
    }

    const int rbase = m0 + wm * 32 + (lane >> 2);
    const int cpair = (lane & 3) * 2;

    if (MODE == 0) {
        const int which = n0 >> 10;
        const float sc = (which == 0) ? SCALE_Q : 1.0f;
        const int h = ((n0 & 1023) >> 6) + wn;
        #pragma unroll
        for (int mi = 0; mi < 2; ++mi) {
            const int m1 = rbase + mi * 16;
            const int m2 = m1 + 8;
            const size_t base1 = (((size_t)(m1 >> 11) * HH + h) * TT + (m1 & 2047)) * DD;
            const size_t base2 = (((size_t)(m2 >> 11) * HH + h) * TT + (m2 & 2047)) * DD;
            #pragma unroll
            for (int nt = 0; nt < 8; ++nt) {
                const int d = nt * 8 + cpair;
                if (which == 0) {       // q: hi + lo
                    uint32_t h1, l1, h2, l2;
                    split2(c[mi][nt][0] * sc, c[mi][nt][1] * sc, h1, l1);
                    split2(c[mi][nt][2] * sc, c[mi][nt][3] * sc, h2, l2);
                    *(uint32_t*)(qh + base1 + d) = h1;
                    *(uint32_t*)(ql + base1 + d) = l1;
                    *(uint32_t*)(qh + base2 + d) = h2;
                    *(uint32_t*)(ql + base2 + d) = l2;
                } else {                // k/v: hi only
                    __half* dst = (which == 1) ? kh : vh;
                    *(uint32_t*)(dst + base1 + d) = pack_h2(c[mi][nt][0], c[mi][nt][1]);
                    *(uint32_t*)(dst + base2 + d) = pack_h2(c[mi][nt][2], c[mi][nt][3]);
                }
            }
        }
    } else {
        #pragma unroll
        for (int mi = 0; mi < 2; ++mi) {
            const int m1 = rbase + mi * 16;
            float* r1 = oplain + (size_t)m1 * EE;
            float* r2 = oplain + (size_t)(m1 + 8) * EE;
            #pragma unroll
            for (int nt = 0; nt < 8; ++nt) {
                const int col = n0 + wn * 64 + nt * 8 + cpair;
                const float b0 = bias[col], b1v = bias[col + 1];
                float2 v1 = make_float2(c[mi][nt][0] + b0, c[mi][nt][1] + b1v);
                float2 v2 = make_float2(c[mi][nt][2] + b0, c[mi][nt][3] + b1v);
                *(float2*)(r1 + col) = v1;
                *(float2*)(r2 + col) = v2;
            }
        }
    }
}

// ---------------------------------------------------------------------------
// Tensor-core causal flash attention: 2 CTAs/SM, 2-stage KV ring (kh+vh only).
// S = Qh.Kh + Ql.Kh (2-pass); O = Ph.Vh + Pl.Vh (2-pass).
// Epilogue writes fp16 hi/lo ctx directly.
// ---------------------------------------------------------------------------
#define AP 72
#define SM_Q 0
#define QARR (128 * AP * 2)
#define SM_STAGE (2 * QARR)
#define KVARR (64 * AP * 2)
#define STAGE_SZ (2 * KVARR)               // kh + vh only
#define SM_MASK (SM_STAGE + 2 * STAGE_SZ)
#define SM_TOTAL (SM_MASK + 2 * 256)

__global__ __launch_bounds__(256, 2)
void attn_mma(const __half* __restrict__ qh, const __half* __restrict__ ql,
              const __half* __restrict__ kh, const __half* __restrict__ vh,
              const float* __restrict__ amask,
              __half* __restrict__ chi, __half* __restrict__ clo)
{
    extern __shared__ char sm[];
    const uint32_t sbase = smem_u32(sm);
    const int tid = threadIdx.x;
    const int w = tid >> 5, lane = tid & 31;
    const int bh = blockIdx.x;
    const int b_ = bh >> 4, h = bh & 15;
    const int qt = 15 - blockIdx.y;
    const int q0 = qt * 128;
    const int last = 2 * qt + 1;

    const int a_row = lane & 15;
    const int a_col = (lane >> 4) << 3;
    const int b_row = ((lane >> 4) << 3) + (lane & 7);
    const int b_col = ((lane >> 3) & 1) << 3;
    const int v_key = (lane & 7) + (((lane >> 3) & 1) << 3);
    const int v_d   = (lane >> 4) << 3;

    const size_t gbase = (size_t)bh * TT * DD;

    auto load_q = [&]() {
        #pragma unroll
        for (int arr = 0; arr < 2; ++arr) {
            const __half* src0 = arr ? ql : qh;
            #pragma unroll
            for (int half = 0; half < 4; ++half) {
                int loc = half * 256 + tid;
                int r = loc >> 3, seg = loc & 7;
                const __half* src = src0 + gbase + (size_t)(q0 + r) * DD + seg * 8;
                uint32_t dst = sbase + SM_Q + arr * QARR + (uint32_t)(r * AP + seg * 8) * 2;
                CP_ASYNC16(dst, src);
            }
        }
    };
    auto load_kv = [&](int buf, int kt) {
        const int s0 = kt * 64;
        #pragma unroll
        for (int arr = 0; arr < 2; ++arr) {
            const __half* src0 = arr ? vh : kh;
            #pragma unroll
            for (int half = 0; half < 2; ++half) {
                int loc = half * 256 + tid;
                int r = loc >> 3, seg = loc & 7;
                const __half* src = src0 + gbase + (size_t)(s0 + r) * DD + seg * 8;
                uint32_t dst = sbase + SM_STAGE + buf * STAGE_SZ + arr * KVARR
                             + (uint32_t)(r * AP + seg * 8) * 2;
                CP_ASYNC16(dst, src);
            }
        }
        if (tid < 16) {
            const float* msrc = amask + (size_t)b_ * TT + s0 + tid * 4;
            uint32_t mdst = sbase + SM_MASK + buf * 256 + tid * 16;
            CP_ASYNC16(mdst, msrc);
        }
        CP_COMMIT();
    };

    load_q();
    load_kv(0, 0);
    load_kv(1, 1);
    CP_WAIT(1);
    __syncthreads();

    uint32_t qa_h[4][4], qa_l[4][4];
    #pragma unroll
    for (int ks = 0; ks < 4; ++ks) {
        uint32_t off = (uint32_t)((w * 16 + a_row) * AP + ks * 16 + a_col) * 2;
        LDSM4(qa_h[ks], sbase + SM_Q + off);
        LDSM4(qa_l[ks], sbase + SM_Q + QARR + off);
    }

    float o[8][4] = {};
    float m0r = -1e30f, m1r = -1e30f, l0 = 0.f, l1 = 0.f;
    const int row0 = q0 + w * 16 + (lane >> 2);
    const int wrow_hi = q0 + w * 16 + 15;

    for (int kt = 0; kt <= last; ++kt) {
        if (kt < last) CP_WAIT(1);
        else           CP_WAIT(0);
        __syncthreads();

        const int buf = kt & 1;
        const int s0 = kt * 64;
        const bool active = (s0 <= wrow_hi);

        if (active) {
            const uint32_t kb = sbase + SM_STAGE + buf * STAGE_SZ;
            // ---- S = Qh.Kh + Ql.Kh (2-pass) ----
            float c[8][4] = {};
            #pragma unroll
            for (int ks = 0; ks < 4; ++ks) {
                #pragma unroll
                for (int hf = 0; hf < 2; ++hf) {
                    uint32_t kf[2][4];
                    #pragma unroll
                    for (int j = 0; j < 2; ++j) {
                        uint32_t off = (uint32_t)(((hf * 2 + j) * 16 + b_row) * AP
                                                  + ks * 16 + b_col) * 2;
                        LDSM4(kf[j], kb + off);
                    }
                    #pragma unroll
                    for (int t = 0; t < 4; ++t) {
                        const int nt = hf * 4 + t;
                        const int j = t >> 1, q = (t & 1) * 2;
                        MMA16816(c[nt], qa_h[ks], kf[j][q], kf[j][q + 1]);
                    }
                    #pragma unroll
                    for (int t = 0; t < 4; ++t) {
                        const int nt = hf * 4 + t;
                        const int j = t >> 1, q = (t & 1) * 2;
                        MMA16816(c[nt], qa_l[ks], kf[j][q], kf[j][q + 1]);
                    }
                }
            }
            // ---- mask + causal ----
            const float* mk = (const float*)(sm + SM_MASK + buf * 256);
            const bool dg = (s0 + 63) > (q0 + w * 16);
            #pragma unroll
            for (int nt = 0; nt < 8; ++nt) {
                const int cl = nt * 8 + (lane & 3) * 2;
                const float mv0 = mk[cl], mv1 = mk[cl + 1];
                const float ma0 = (1.0f - mv0) * -1e30f;
                const float ma1 = (1.0f - mv1) * -1e30f;
                c[nt][0] += ma0; c[nt][1] += ma1;
                c[nt][2] += ma0; c[nt][3] += ma1;
                if (dg) {
                    const int cg = s0 + cl;
                    if (cg     > row0)     c[nt][0] = -1e30f;
                    if (cg + 1 > row0)     c[nt][1] = -1e30f;
                    if (cg     > row0 + 8) c[nt][2] = -1e30f;
                    if (cg + 1 > row0 + 8) c[nt][3] = -1e30f;
                }
            }
            // ---- online softmax ----
            float t0 = -1e30f, t1 = -1e30f;
            #pragma unroll
            for (int nt = 0; nt < 8; ++nt) {
                t0 = fmaxf(t0, fmaxf(c[nt][0], c[nt][1]));
                t1 = fmaxf(t1, fmaxf(c[nt][2], c[nt][3]));
            }
            t0 = fmaxf(t0, __shfl_xor_sync(0xffffffffu, t0, 1));
            t0 = fmaxf(t0, __shfl_xor_sync(0xffffffffu, t0, 2));
            t1 = fmaxf(t1, __shfl_xor_sync(0xffffffffu, t1, 1));
            t1 = fmaxf(t1, __shfl_xor_sync(0xffffffffu, t1, 2));
            const float mn0 = fmaxf(m0r, t0), mn1 = fmaxf(m1r, t1);
            const float cor0 = exp2fast(m0r - mn0), cor1 = exp2fast(m1r - mn1);
            m0r = mn0; m1r = mn1;
            l0 *= cor0; l1 *= cor1;
            #pragma unroll
            for (int nt = 0; nt < 8; ++nt) {
                o[nt][0] *= cor0; o[nt][1] *= cor0;
                o[nt][2] *= cor1; o[nt][3] *= cor1;
            }
            // ---- fused P conversion + O += Ph.Vh + Pl.Vh (2-pass) ----
            float s0sum = 0.f, s1sum = 0.f;
            #pragma unroll
            for (int ks = 0; ks < 4; ++ks) {
                uint32_t pa_h[4], pa_l[4];
                #pragma unroll
                for (int t = 0; t < 2; ++t) {
                    const int nt = ks * 2 + t;
                    const float p0 = exp2fast(c[nt][0] - mn0);
                    const float p1 = exp2fast(c[nt][1] - mn0);
                    const float p2 = exp2fast(c[nt][2] - mn1);
                    const float p3 = exp2fast(c[nt][3] - mn1);
                    s0sum += p0 + p1; s1sum += p2 + p3;
                    split2(p0, p1, pa_h[t * 2], pa_l[t * 2]);
                    split2(p2, p3, pa_h[t * 2 + 1], pa_l[t * 2 + 1]);
                }
                #pragma unroll
                for (int hf = 0; hf < 2; ++hf) {
                    uint32_t vf[2][4];
                    #pragma unroll
                    for (int j = 0; j < 2; ++j) {
                        uint32_t off = (uint32_t)((ks * 16 + v_key) * AP
                                                  + (hf * 2 + j) * 16 + v_d) * 2;
                        LDSM4T(vf[j], kb + KVARR + off);
                    }
                    #pragma unroll
                    for (int t = 0; t < 4; ++t) {
                        const int nt = hf * 4 + t;
                        const int j = t >> 1, q = (t & 1) * 2;
                        MMA16816(o[nt], pa_h, vf[j][q], vf[j][q + 1]);
                    }
                    #pragma unroll
                    for (int t = 0; t < 4; ++t) {
                        const int nt = hf * 4 + t;
                        const int j = t >> 1, q = (t & 1) * 2;
                        MMA16816(o[nt], pa_l, vf[j][q], vf[j][q + 1]);
                    }
                }
            }
            s0sum += __shfl_xor_sync(0xffffffffu, s0sum, 1);
            s0sum += __shfl_xor_sync(0xffffffffu, s0sum, 2);
            s1sum += __shfl_xor_sync(0xffffffffu, s1sum, 1);
            s1sum += __shfl_xor_sync(0xffffffffu, s1sum, 2);
            l0 += s0sum; l1 += s1sum;
        }
        __syncthreads();
        if (kt + 2 <= last) load_kv(buf, kt + 2);
    }

    // ---- normalize + split + store fp16 hi/lo ctx [B,T,E] ----
    const float inv0 = 1.0f / l0, inv1 = 1.0f / l1;
    const int cpair = (lane & 3) * 2;
    const size_t r1 = ((size_t)b_ * TT + row0) * EE + h * 64;
    const size_t r2 = ((size_t)b_ * TT + row0 + 8) * EE + h * 64;
    #pragma unroll
    for (int nt = 0; nt < 8; ++nt) {
        const int d = nt * 8 + cpair;
        uint32_t h1, l1w, h2, l2;
        split2(o[nt][0] * inv0, o[nt][1] * inv0, h1, l1w);
        split2(o[nt][2] * inv1, o[nt][3] * inv1, h2, l2);
        *(uint32_t*)(chi + r1 + d) = h1;
        *(uint32_t*)(clo + r1 + d) = l1w;
        *(uint32_t*)(chi + r2 + d) = h2;
        *(uint32_t*)(clo + r2 + d) = l2;
    }
}

// ---------------------------------------------------------------------------
// Launch
// ---------------------------------------------------------------------------
extern "C" void kernel_launch(void* const* d_in, const int* in_sizes, int n_in,
                              void* d_out, int out_size)
{
    const float* x     = (const float*)d_in[0];
    const float* amask = (const float*)d_in[1];
    const float* Wq    = (const float*)d_in[2];
    const float* Wk    = (const float*)d_in[3];
    const float* Wv    = (const float*)d_in[4];
    const float* Wo    = (const float*)d_in[5];
    const float* bo    = (const float*)d_in[6];
    float* out = (float*)d_out;

    __half *xhi, *xlo, *wth, *wtl, *woh, *wol, *chi, *clo;
    __half *qh, *ql, *kh, *vh;
    cudaGetSymbolAddress((void**)&xhi, g_xhi);
    cudaGetSymbolAddress((void**)&xlo, g_xlo);
    cudaGetSymbolAddress((void**)&wth, g_wth);
    cudaGetSymbolAddress((void**)&wtl, g_wtl);
    cudaGetSymbolAddress((void**)&woh, g_woh);
    cudaGetSymbolAddress((void**)&wol, g_wol);
    cudaGetSymbolAddress((void**)&chi, g_chi);
    cudaGetSymbolAddress((void**)&clo, g_clo);
    cudaGetSymbolAddress((void**)&qh,  g_qh);
    cudaGetSymbolAddress((void**)&ql,  g_ql);
    cudaGetSymbolAddress((void**)&kh,  g_kh);
    cudaGetSymbolAddress((void**)&vh,  g_vh);

    cudaFuncSetAttribute(mma_gemm<0>, cudaFuncAttributeMaxDynamicSharedMemorySize,
                         2 * STB0);
    cudaFuncSetAttribute(mma_gemm<1>, cudaFuncAttributeMaxDynamicSharedMemorySize,
                         2 * STB1);
    cudaFuncSetAttribute(attn_mma, cudaFuncAttributeMaxDynamicSharedMemorySize,
                         SM_TOTAL);

    conv_hilo<<<(BT * EE / 4) / 256, 256>>>(x, xhi, xlo, BT * EE / 4);
    prep_wt<<<768, 256>>>(Wq, Wk, Wv, wth, wtl);
    conv_hilo<<<(EE * EE / 4) / 256, 256>>>(Wo, woh, wol, EE * EE / 4);

    {   // QKV projection (2-pass) -> q hi/lo, k/v hi
        dim3 grid(NQKV / 128, BT / 128);
        mma_gemm<0><<<grid, 256, 2 * STB0>>>(xhi, xlo, wth, wtl, nullptr,
                                             qh, ql, kh, vh, nullptr);
    }
    {   // attention (2-pass S, 2-pass PV) -> fp16 hi/lo ctx
        dim3 grid(BB * HH, TT / 128);
        attn_mma<<<grid, 256, SM_TOTAL>>>(qh, ql, kh, vh, amask, chi, clo);
    }
    {   // output projection (3-pass)
        dim3 grid(EE / 128, BT / 128);
        mma_gemm<1><<<grid, 256, 2 * STB1>>>(chi, clo, woh, wol, bo,
                                             nullptr, nullptr, nullptr,
                                             nullptr, out);
    }
}

// round 12
// speedup vs baseline: 1.5634x; 1.0875x over previous
#include <cuda_runtime.h>
#include <cuda_fp16.h>
#include <math_constants.h>
#include <cstdint>

// Problem constants
#define BB 4
#define TT 2048
#define EE 1024
#define HH 16
#define DD 64
#define BT (BB*TT)          // 8192
#define NQKV 3072

#define L2E 1.44269504f
#define SCALE_Q (0.125f * L2E)    // fold 1/sqrt(D) and log2(e) into q

// ---------------------------------------------------------------------------
// Scratch (allocation-free rule: __device__ globals)  — fp16 hi/lo
// ---------------------------------------------------------------------------
__device__ __align__(16) __half g_xhi[(size_t)BT*EE];
__device__ __align__(16) __half g_xlo[(size_t)BT*EE];
__device__ __align__(16) __half g_wth[(size_t)NQKV*EE];
__device__ __align__(16) __half g_woh[(size_t)EE*EE];
__device__ __align__(16) __half g_chi[(size_t)BT*EE];     // attn out hi
__device__ __align__(16) __half g_clo[(size_t)BT*EE];     // attn out lo

// fp16 q (hi+lo), k/v (hi only) in [B,H,T,D]
__device__ __align__(16) __half g_qh[(size_t)BB*HH*TT*DD];
__device__ __align__(16) __half g_ql[(size_t)BB*HH*TT*DD];
__device__ __align__(16) __half g_kh[(size_t)BB*HH*TT*DD];
__device__ __align__(16) __half g_vh[(size_t)BB*HH*TT*DD];

// ---------------------------------------------------------------------------
// Helpers (base sm_103 ISA: mma.sync / ldmatrix / cp.async)
// ---------------------------------------------------------------------------
__device__ __forceinline__ uint32_t smem_u32(const void* p) {
    uint32_t a;
    asm("{ .reg .u64 t; cvta.to.shared.u64 t, %1; cvt.u32.u64 %0, t; }"
        : "=r"(a) : "l"(p));
    return a;
}

#define LDSM4(r, addr) \
    asm volatile("ldmatrix.sync.aligned.m8n8.x4.shared.b16 {%0,%1,%2,%3}, [%4];" \
        : "=r"((r)[0]), "=r"((r)[1]), "=r"((r)[2]), "=r"((r)[3]) : "r"(addr))

#define LDSM4T(r, addr) \
    asm volatile("ldmatrix.sync.aligned.m8n8.x4.trans.shared.b16 {%0,%1,%2,%3}, [%4];" \
        : "=r"((r)[0]), "=r"((r)[1]), "=r"((r)[2]), "=r"((r)[3]) : "r"(addr))

#define MMA16816(c, a, b0, b1) \
    asm volatile("mma.sync.aligned.m16n8k16.row.col.f32.f16.f16.f32 " \
        "{%0,%1,%2,%3}, {%4,%5,%6,%7}, {%8,%9}, {%0,%1,%2,%3};" \
        : "+f"((c)[0]), "+f"((c)[1]), "+f"((c)[2]), "+f"((c)[3]) \
        : "r"((a)[0]), "r"((a)[1]), "r"((a)[2]), "r"((a)[3]), "r"(b0), "r"(b1))

#define CP_ASYNC16(dst, src) \
    asm volatile("cp.async.cg.shared.global [%0], [%1], 16;" :: "r"(dst), "l"(src))
#define CP_COMMIT() asm volatile("cp.async.commit_group;" ::: "memory")
#define CP_WAIT(n)  asm volatile("cp.async.wait_group %0;" :: "n"(n) : "memory")

// split two floats into packed fp16x2 hi and lo residual
__device__ __forceinline__ void split2(float a, float b, uint32_t& hi, uint32_t& lo) {
    __half ha = __float2half_rn(a), hb = __float2half_rn(b);
    float ra = a - __half2float(ha);
    float rb = b - __half2float(hb);
    __half2 H = __halves2half2(ha, hb);
    __half2 L = __halves2half2(__float2half_rn(ra), __float2half_rn(rb));
    hi = *(uint32_t*)&H;
    lo = *(uint32_t*)&L;
}

__device__ __forceinline__ uint32_t pack_h2(float a, float b) {
    __half2 H = __halves2half2(__float2half_rn(a), __float2half_rn(b));
    return *(uint32_t*)&H;
}

// fast exp2 on the FMA pipe (degree-7, rel err ~1e-6)
__device__ __forceinline__ float exp2fast(float x) {
    x = fmaxf(x, -125.0f);
    int n = __float2int_rd(x);
    float f = x - (float)n;
    float p = 1.3570247e-5f;
    p = fmaf(p, f, 1.5353362e-4f);
    p = fmaf(p, f, 1.3398874e-3f);
    p = fmaf(p, f, 9.6184374e-3f);
    p = fmaf(p, f, 5.5503325e-2f);
    p = fmaf(p, f, 2.4022648e-1f);
    p = fmaf(p, f, 6.9314720e-1f);
    p = fmaf(p, f, 1.0f);
    return p * __int_as_float((n + 127) << 23);
}

// ---------------------------------------------------------------------------
// Prep: fp32 -> (fp16 hi, fp16 lo)
// ---------------------------------------------------------------------------
__global__ __launch_bounds__(256) void conv_hilo(
    const float* __restrict__ s, __half* __restrict__ hi,
    __half* __restrict__ lo, int n4)
{
    int i = blockIdx.x * 256 + threadIdx.x;
    if (i >= n4) return;
    float4 v = ((const float4*)s)[i];
    uint32_t h0, l0, h1, l1;
    split2(v.x, v.y, h0, l0);
    split2(v.z, v.w, h1, l1);
    ((uint32_t*)hi)[i * 2 + 0] = h0;
    ((uint32_t*)hi)[i * 2 + 1] = h1;
    if (lo) {
        ((uint32_t*)lo)[i * 2 + 0] = l0;
        ((uint32_t*)lo)[i * 2 + 1] = l1;
    }
}

// ---------------------------------------------------------------------------
// Prep: transpose qkv weights (hi only). W[h][e][d] -> Wt[n][e]
// ---------------------------------------------------------------------------
__global__ __launch_bounds__(256) void prep_wt(
    const float* __restrict__ Wq, const float* __restrict__ Wk,
    const float* __restrict__ Wv, __half* __restrict__ th)
{
    __shared__ float ts[64][65];
    const int bx = blockIdx.x;
    const int mi = bx >> 8;
    const int rem = bx & 255;
    const int h = rem >> 4;
    const int e0 = (rem & 15) * 64;
    const float* src = (mi == 0 ? Wq : (mi == 1 ? Wk : Wv)) + (size_t)h * EE * DD;
    const int tid = threadIdx.x;

    #pragma unroll
    for (int i = 0; i < 4; ++i) {
        int idx = tid + i * 256;
        int ei = idx >> 4, d4 = idx & 15;
        float4 v = ((const float4*)(src + (size_t)(e0 + ei) * DD))[d4];
        ts[ei][d4 * 4 + 0] = v.x; ts[ei][d4 * 4 + 1] = v.y;
        ts[ei][d4 * 4 + 2] = v.z; ts[ei][d4 * 4 + 3] = v.w;
    }
    __syncthreads();

    const int d = tid >> 2, seg = tid & 3;
    const size_t row = ((size_t)mi * 1024 + h * 64 + d) * EE + e0 + seg * 16;
    alignas(16) __half hb[16];
    #pragma unroll
    for (int i = 0; i < 16; ++i)
        hb[i] = __float2half_rn(ts[seg * 16 + i][d]);
    *(uint4*)(th + row)     = *(const uint4*)(hb);
    *(uint4*)(th + row + 8) = *(const uint4*)(hb + 8);
}

// ---------------------------------------------------------------------------
// HMMA split-fp16 GEMM, 128Mx128N block, warp 32x64, 2 CTAs/SM.
// 2-pass: C = Ah.Bh + Al.Bh.  MODE 0 (qkv): the Al pass runs ONLY for the Q
// head range (n0 < 1024); K/V are 1-pass (their fp16 store rounding dominates).
// MODE 1 (out-proj): always 2-pass, fp32 + bias epilogue.
// ---------------------------------------------------------------------------
#define PITCH 40
#define A_ELEMS (128 * PITCH)            // 5120
#define B_ELEMS (128 * PITCH)            // 5120
#define STAGE_BYTES ((2 * A_ELEMS + B_ELEMS) * 2)   // 30720

template <int MODE>
__global__ __launch_bounds__(256, 2)
void mma_gemm(const __half* __restrict__ Ah, const __half* __restrict__ Al,
              const __half* __restrict__ Bh,
              const float* __restrict__ bias,
              __half* __restrict__ qh, __half* __restrict__ ql,
              __half* __restrict__ kh, __half* __restrict__ vh,
              float* __restrict__ oplain)
{
    extern __shared__ char sm[];
    const uint32_t sbase = smem_u32(sm);
    const int tid = threadIdx.x;
    const int wid = tid >> 5, lane = tid & 31;
    const int wm = wid & 3, wn = wid >> 2;       // 4 M-warps x 2 N-warps
    const int n0 = blockIdx.x * 128;
    const int m0 = blockIdx.y * 128;
    const bool need_lo = (MODE == 1) || (n0 < 1024);   // Q range only in mode 0

    const int a_row = lane & 15;
    const int a_col = (lane >> 4) << 3;
    const int b_row = ((lane >> 4) << 3) + (lane & 7);
    const int b_col = ((lane >> 3) & 1) << 3;

    float c[2][8][4] = {};    // warp tile 32x64

    const int lr = tid >> 2, lseg = tid & 3;
    const __half* pA0 = Ah + (size_t)(m0 + lr) * EE + lseg * 8;
    const __half* pA1 = Al + (size_t)(m0 + lr) * EE + lseg * 8;
    const __half* pB0 = Bh + (size_t)(n0 + lr) * EE + lseg * 8;
    const uint32_t doff = (uint32_t)(lr * PITCH + lseg * 8) * 2;

    auto stage_load = [&](uint32_t bufbase) {
        const uint32_t d0 = bufbase + doff;
        CP_ASYNC16(d0,                                  pA0);
        CP_ASYNC16(d0 + 64 * PITCH * 2,                 pA0 + (size_t)64 * EE);
        if (need_lo) {
            CP_ASYNC16(d0 + A_ELEMS * 2,                  pA1);
            CP_ASYNC16(d0 + A_ELEMS * 2 + 64 * PITCH * 2, pA1 + (size_t)64 * EE);
            pA1 += 32;
        }
        const uint32_t b0 = d0 + 2 * A_ELEMS * 2;
        CP_ASYNC16(b0,                                  pB0);
        CP_ASYNC16(b0 + 64 * PITCH * 2,                 pB0 + (size_t)64 * EE);
        CP_COMMIT();
        pA0 += 32; pB0 += 32;
    };

    stage_load(sbase);
    stage_load(sbase + STAGE_BYTES);

    for (int ch = 0; ch < 32; ++ch) {
        if (ch < 31) CP_WAIT(1);
        else         CP_WAIT(0);
        __syncthreads();

        const uint32_t sb  = sbase + (ch & 1) * STAGE_BYTES;
        const uint32_t sAh = sb;
        const uint32_t sAl = sb + A_ELEMS * 2;
        const uint32_t sBh = sb + 2 * A_ELEMS * 2;

        #pragma unroll
        for (int ks = 0; ks < 2; ++ks) {
            uint32_t ah[2][4], alr[2][4];
            #pragma unroll
            for (int mi = 0; mi < 2; ++mi) {
                uint32_t off = (uint32_t)((wm * 32 + mi * 16 + a_row) * PITCH
                                          + ks * 16 + a_col) * 2;
                LDSM4(ah[mi], sAh + off);
                if (need_lo) LDSM4(alr[mi], sAl + off);
            }
            #pragma unroll
            for (int jp = 0; jp < 4; ++jp) {
                uint32_t bb[4];
                uint32_t off = (uint32_t)((wn * 64 + jp * 16 + b_row) * PITCH
                                          + ks * 16 + b_col) * 2;
                LDSM4(bb, sBh + off);
                #pragma unroll
                for (int mi = 0; mi < 2; ++mi)
                    #pragma unroll
                    for (int t = 0; t < 2; ++t)
                        MMA16816(c[mi][jp * 2 + t], ah[mi],  bb[t * 2], bb[t * 2 + 1]);
                if (need_lo) {
                    #pragma unroll
                    for (int mi = 0; mi < 2; ++mi)
                        #pragma unroll
                        for (int t = 0; t < 2; ++t)
                            MMA16816(c[mi][jp * 2 + t], alr[mi], bb[t * 2], bb[t * 2 + 1]);
                }
            }
        }
        __syncthreads();
        if (ch + 2 < 32) stage_load(sb);
    }

    const int rbase = m0 + wm * 32 + (lane >> 2);
    const int cpair = (lane & 3) * 2;

    if (MODE == 0) {
        const int which = n0 >> 10;
        const float sc = (which == 0) ? SCALE_Q : 1.0f;
        const int h = ((n0 & 1023) >> 6) + wn;
        #pragma unroll
        for (int mi = 0; mi < 2; ++mi) {
            const int m1 = rbase + mi * 16;
            const int m2 = m1 + 8;
            const size_t base1 = (((size_t)(m1 >> 11) * HH + h) * TT + (m1 & 2047)) * DD;
            const size_t base2 = (((size_t)(m2 >> 11) * HH + h) * TT + (m2 & 2047)) * DD;
            #pragma unroll
            for (int nt = 0; nt < 8; ++nt) {
                const int d = nt * 8 + cpair;
                if (which == 0) {       // q: hi + lo
                    uint32_t h1, l1, h2, l2;
                    split2(c[mi][nt][0] * sc, c[mi][nt][1] * sc, h1, l1);
                    split2(c[mi][nt][2] * sc, c[mi][nt][3] * sc, h2, l2);
                    *(uint32_t*)(qh + base1 + d) = h1;
                    *(uint32_t*)(ql + base1 + d) = l1;
                    *(uint32_t*)(qh + base2 + d) = h2;
                    *(uint32_t*)(ql + base2 + d) = l2;
                } else {                // k/v: hi only
                    __half* dst = (which == 1) ? kh : vh;
                    *(uint32_t*)(dst + base1 + d) = pack_h2(c[mi][nt][0], c[mi][nt][1]);
                    *(uint32_t*)(dst + base2 + d) = pack_h2(c[mi][nt][2], c[mi][nt][3]);
                }
            }
        }
    } else {
        #pragma unroll
        for (int mi = 0; mi < 2; ++mi) {
            const int m1 = rbase + mi * 16;
            float* r1 = oplain + (size_t)m1 * EE;
            float* r2 = oplain + (size_t)(m1 + 8) * EE;
            #pragma unroll
            for (int nt = 0; nt < 8; ++nt) {
                const int col = n0 + wn * 64 + nt * 8 + cpair;
                const float b0 = bias[col], b1v = bias[col + 1];
                float2 v1 = make_float2(c[mi][nt][0] + b0, c[mi][nt][1] + b1v);
                float2 v2 = make_float2(c[mi][nt][2] + b0, c[mi][nt][3] + b1v);
                *(float2*)(r1 + col) = v1;
                *(float2*)(r2 + col) = v2;
            }
        }
    }
}

// ---------------------------------------------------------------------------
// Tensor-core causal flash attention: 2 CTAs/SM, 2-stage KV ring (kh+vh only).
// S = Qh.Kh + Ql.Kh (2-pass); O = Ph.Vh + Pl.Vh (2-pass).
// Epilogue writes fp16 hi/lo ctx directly.
// ---------------------------------------------------------------------------
#define AP 72
#define SM_Q 0
#define QARR (128 * AP * 2)
#define SM_STAGE (2 * QARR)
#define KVARR (64 * AP * 2)
#define STAGE_SZ (2 * KVARR)               // kh + vh only
#define SM_MASK (SM_STAGE + 2 * STAGE_SZ)
#define SM_TOTAL (SM_MASK + 2 * 256)

__global__ __launch_bounds__(256, 2)
void attn_mma(const __half* __restrict__ qh, const __half* __restrict__ ql,
              const __half* __restrict__ kh, const __half* __restrict__ vh,
              const float* __restrict__ amask,
              __half* __restrict__ chi, __half* __restrict__ clo)
{
    extern __shared__ char sm[];
    const uint32_t sbase = smem_u32(sm);
    const int tid = threadIdx.x;
    const int w = tid >> 5, lane = tid & 31;
    const int bh = blockIdx.x;
    const int b_ = bh >> 4, h = bh & 15;
    const int qt = 15 - blockIdx.y;
    const int q0 = qt * 128;
    const int last = 2 * qt + 1;

    const int a_row = lane & 15;
    const int a_col = (lane >> 4) << 3;
    const int b_row = ((lane >> 4) << 3) + (lane & 7);
    const int b_col = ((lane >> 3) & 1) << 3;
    const int v_key = (lane & 7) + (((lane >> 3) & 1) << 3);
    const int v_d   = (lane >> 4) << 3;

    const size_t gbase = (size_t)bh * TT * DD;

    auto load_q = [&]() {
        #pragma unroll
        for (int arr = 0; arr < 2; ++arr) {
            const __half* src0 = arr ? ql : qh;
            #pragma unroll
            for (int half = 0; half < 4; ++half) {
                int loc = half * 256 + tid;
                int r = loc >> 3, seg = loc & 7;
                const __half* src = src0 + gbase + (size_t)(q0 + r) * DD + seg * 8;
                uint32_t dst = sbase + SM_Q + arr * QARR + (uint32_t)(r * AP + seg * 8) * 2;
                CP_ASYNC16(dst, src);
            }
        }
    };
    auto load_kv = [&](int buf, int kt) {
        const int s0 = kt * 64;
        #pragma unroll
        for (int arr = 0; arr < 2; ++arr) {
            const __half* src0 = arr ? vh : kh;
            #pragma unroll
            for (int half = 0; half < 2; ++half) {
                int loc = half * 256 + tid;
                int r = loc >> 3, seg = loc & 7;
                const __half* src = src0 + gbase + (size_t)(s0 + r) * DD + seg * 8;
                uint32_t dst = sbase + SM_STAGE + buf * STAGE_SZ + arr * KVARR
                             + (uint32_t)(r * AP + seg * 8) * 2;
                CP_ASYNC16(dst, src);
            }
        }
        if (tid < 16) {
            const float* msrc = amask + (size_t)b_ * TT + s0 + tid * 4;
            uint32_t mdst = sbase + SM_MASK + buf * 256 + tid * 16;
            CP_ASYNC16(mdst, msrc);
        }
        CP_COMMIT();
    };

    load_q();
    load_kv(0, 0);
    load_kv(1, 1);
    CP_WAIT(1);
    __syncthreads();

    uint32_t qa_h[4][4], qa_l[4][4];
    #pragma unroll
    for (int ks = 0; ks < 4; ++ks) {
        uint32_t off = (uint32_t)((w * 16 + a_row) * AP + ks * 16 + a_col) * 2;
        LDSM4(qa_h[ks], sbase + SM_Q + off);
        LDSM4(qa_l[ks], sbase + SM_Q + QARR + off);
    }

    float o[8][4] = {};
    float m0r = -1e30f, m1r = -1e30f, l0 = 0.f, l1 = 0.f;
    const int row0 = q0 + w * 16 + (lane >> 2);
    const int wrow_hi = q0 + w * 16 + 15;

    for (int kt = 0; kt <= last; ++kt) {
        if (kt < last) CP_WAIT(1);
        else           CP_WAIT(0);
        __syncthreads();

        const int buf = kt & 1;
        const int s0 = kt * 64;
        const bool active = (s0 <= wrow_hi);

        if (active) {
            const uint32_t kb = sbase + SM_STAGE + buf * STAGE_SZ;
            // ---- S = Qh.Kh + Ql.Kh (2-pass) ----
            float c[8][4] = {};
            #pragma unroll
            for (int ks = 0; ks < 4; ++ks) {
                #pragma unroll
                for (int hf = 0; hf < 2; ++hf) {
                    uint32_t kf[2][4];
                    #pragma unroll
                    for (int j = 0; j < 2; ++j) {
                        uint32_t off = (uint32_t)(((hf * 2 + j) * 16 + b_row) * AP
                                                  + ks * 16 + b_col) * 2;
                        LDSM4(kf[j], kb + off);
                    }
                    #pragma unroll
                    for (int t = 0; t < 4; ++t) {
                        const int nt = hf * 4 + t;
                        const int j = t >> 1, q = (t & 1) * 2;
                        MMA16816(c[nt], qa_h[ks], kf[j][q], kf[j][q + 1]);
                    }
                    #pragma unroll
                    for (int t = 0; t < 4; ++t) {
                        const int nt = hf * 4 + t;
                        const int j = t >> 1, q = (t & 1) * 2;
                        MMA16816(c[nt], qa_l[ks], kf[j][q], kf[j][q + 1]);
                    }
                }
            }
            // ---- mask + causal ----
            const float* mk = (const float*)(sm + SM_MASK + buf * 256);
            const bool dg = (s0 + 63) > (q0 + w * 16);
            #pragma unroll
            for (int nt = 0; nt < 8; ++nt) {
                const int cl = nt * 8 + (lane & 3) * 2;
                const float mv0 = mk[cl], mv1 = mk[cl + 1];
                const float ma0 = (1.0f - mv0) * -1e30f;
                const float ma1 = (1.0f - mv1) * -1e30f;
                c[nt][0] += ma0; c[nt][1] += ma1;
                c[nt][2] += ma0; c[nt][3] += ma1;
                if (dg) {
                    const int cg = s0 + cl;
                    if (cg     > row0)     c[nt][0] = -1e30f;
                    if (cg + 1 > row0)     c[nt][1] = -1e30f;
                    if (cg     > row0 + 8) c[nt][2] = -1e30f;
                    if (cg + 1 > row0 + 8) c[nt][3] = -1e30f;
                }
            }
            // ---- online softmax ----
            float t0 = -1e30f, t1 = -1e30f;
            #pragma unroll
            for (int nt = 0; nt < 8; ++nt) {
                t0 = fmaxf(t0, fmaxf(c[nt][0], c[nt][1]));
                t1 = fmaxf(t1, fmaxf(c[nt][2], c[nt][3]));
            }
            t0 = fmaxf(t0, __shfl_xor_sync(0xffffffffu, t0, 1));
            t0 = fmaxf(t0, __shfl_xor_sync(0xffffffffu, t0, 2));
            t1 = fmaxf(t1, __shfl_xor_sync(0xffffffffu, t1, 1));
            t1 = fmaxf(t1, __shfl_xor_sync(0xffffffffu, t1, 2));
            const float mn0 = fmaxf(m0r, t0), mn1 = fmaxf(m1r, t1);
            const float cor0 = exp2fast(m0r - mn0), cor1 = exp2fast(m1r - mn1);
            m0r = mn0; m1r = mn1;
            l0 *= cor0; l1 *= cor1;
            #pragma unroll
            for (int nt = 0; nt < 8; ++nt) {
                o[nt][0] *= cor0; o[nt][1] *= cor0;
                o[nt][2] *= cor1; o[nt][3] *= cor1;
            }
            // ---- fused P conversion + O += Ph.Vh + Pl.Vh (2-pass) ----
            float s0sum = 0.f, s1sum = 0.f;
            #pragma unroll
            for (int ks = 0; ks < 4; ++ks) {
                uint32_t pa_h[4], pa_l[4];
                #pragma unroll
                for (int t = 0; t < 2; ++t) {
                    const int nt = ks * 2 + t;
                    const float p0 = exp2fast(c[nt][0] - mn0);
                    const float p1 = exp2fast(c[nt][1] - mn0);
                    const float p2 = exp2fast(c[nt][2] - mn1);
                    const float p3 = exp2fast(c[nt][3] - mn1);
                    s0sum += p0 + p1; s1sum += p2 + p3;
                    split2(p0, p1, pa_h[t * 2], pa_l[t * 2]);
                    split2(p2, p3, pa_h[t * 2 + 1], pa_l[t * 2 + 1]);
                }
                #pragma unroll
                for (int hf = 0; hf < 2; ++hf) {
                    uint32_t vf[2][4];
                    #pragma unroll
                    for (int j = 0; j < 2; ++j) {
                        uint32_t off = (uint32_t)((ks * 16 + v_key) * AP
                                                  + (hf * 2 + j) * 16 + v_d) * 2;
                        LDSM4T(vf[j], kb + KVARR + off);
                    }
                    #pragma unroll
                    for (int t = 0; t < 4; ++t) {
                        const int nt = hf * 4 + t;
                        const int j = t >> 1, q = (t & 1) * 2;
                        MMA16816(o[nt], pa_h, vf[j][q], vf[j][q + 1]);
                    }
                    #pragma unroll
                    for (int t = 0; t < 4; ++t) {
                        const int nt = hf * 4 + t;
                        const int j = t >> 1, q = (t & 1) * 2;
                        MMA16816(o[nt], pa_l, vf[j][q], vf[j][q + 1]);
                    }
                }
            }
            s0sum += __shfl_xor_sync(0xffffffffu, s0sum, 1);
            s0sum += __shfl_xor_sync(0xffffffffu, s0sum, 2);
            s1sum += __shfl_xor_sync(0xffffffffu, s1sum, 1);
            s1sum += __shfl_xor_sync(0xffffffffu, s1sum, 2);
            l0 += s0sum; l1 += s1sum;
        }
        __syncthreads();
        if (kt + 2 <= last) load_kv(buf, kt + 2);
    }

    // ---- normalize + split + store fp16 hi/lo ctx [B,T,E] ----
    const float inv0 = 1.0f / l0, inv1 = 1.0f / l1;
    const int cpair = (lane & 3) * 2;
    const size_t r1 = ((size_t)b_ * TT + row0) * EE + h * 64;
    const size_t r2 = ((size_t)b_ * TT + row0 + 8) * EE + h * 64;
    #pragma unroll
    for (int nt = 0; nt < 8; ++nt) {
        const int d = nt * 8 + cpair;
        uint32_t h1, l1w, h2, l2;
        split2(o[nt][0] * inv0, o[nt][1] * inv0, h1, l1w);
        split2(o[nt][2] * inv1, o[nt][3] * inv1, h2, l2);
        *(uint32_t*)(chi + r1 + d) = h1;
        *(uint32_t*)(clo + r1 + d) = l1w;
        *(uint32_t*)(chi + r2 + d) = h2;
        *(uint32_t*)(clo + r2 + d) = l2;
    }
}

// ---------------------------------------------------------------------------
// Launch
// ---------------------------------------------------------------------------
extern "C" void kernel_launch(void* const* d_in, const int* in_sizes, int n_in,
                              void* d_out, int out_size)
{
    const float* x     = (const float*)d_in[0];
    const float* amask = (const float*)d_in[1];
    const float* Wq    = (const float*)d_in[2];
    const float* Wk    = (const float*)d_in[3];
    const float* Wv    = (const float*)d_in[4];
    const float* Wo    = (const float*)d_in[5];
    const float* bo    = (const float*)d_in[6];
    float* out = (float*)d_out;

    __half *xhi, *xlo, *wth, *woh, *chi, *clo;
    __half *qh, *ql, *kh, *vh;
    cudaGetSymbolAddress((void**)&xhi, g_xhi);
    cudaGetSymbolAddress((void**)&xlo, g_xlo);
    cudaGetSymbolAddress((void**)&wth, g_wth);
    cudaGetSymbolAddress((void**)&woh, g_woh);
    cudaGetSymbolAddress((void**)&chi, g_chi);
    cudaGetSymbolAddress((void**)&clo, g_clo);
    cudaGetSymbolAddress((void**)&qh,  g_qh);
    cudaGetSymbolAddress((void**)&ql,  g_ql);
    cudaGetSymbolAddress((void**)&kh,  g_kh);
    cudaGetSymbolAddress((void**)&vh,  g_vh);

    cudaFuncSetAttribute(mma_gemm<0>, cudaFuncAttributeMaxDynamicSharedMemorySize,
                         2 * STAGE_BYTES);
    cudaFuncSetAttribute(mma_gemm<1>, cudaFuncAttributeMaxDynamicSharedMemorySize,
                         2 * STAGE_BYTES);
    cudaFuncSetAttribute(attn_mma, cudaFuncAttributeMaxDynamicSharedMemorySize,
                         SM_TOTAL);

    conv_hilo<<<(BT * EE / 4) / 256, 256>>>(x, xhi, xlo, BT * EE / 4);
    prep_wt<<<768, 256>>>(Wq, Wk, Wv, wth);
    conv_hilo<<<(EE * EE / 4) / 256, 256>>>(Wo, woh, nullptr, EE * EE / 4);

    {   // QKV projection: Q 2-pass (hi+lo out), K/V 1-pass (hi out)
        dim3 grid(NQKV / 128, BT / 128);
        mma_gemm<0><<<grid, 256, 2 * STAGE_BYTES>>>(xhi, xlo, wth, nullptr,
                                                    qh, ql, kh, vh, nullptr);
    }
    {   // attention (2-pass S, 2-pass PV) -> fp16 hi/lo ctx
        dim3 grid(BB * HH, TT / 128);
        attn_mma<<<grid, 256, SM_TOTAL>>>(qh, ql, kh, vh, amask, chi, clo);
    }
    {   // output projection (2-pass: ctx_hi.Wo + ctx_lo.Wo)
        dim3 grid(EE / 128, BT / 128);
        mma_gemm<1><<<grid, 256, 2 * STAGE_BYTES>>>(chi, clo, woh, bo,
                                                    nullptr, nullptr, nullptr,
                                                    nullptr, out);
    }
}

// round 13
// speedup vs baseline: 1.6244x; 1.0390x over previous
#include <cuda_runtime.h>
#include <cuda_fp16.h>
#include <math_constants.h>
#include <cstdint>

// Problem constants
#define BB 4
#define TT 2048
#define EE 1024
#define HH 16
#define DD 64
#define BT (BB*TT)          // 8192
#define NQKV 3072

#define L2E 1.44269504f
#define SCALE_Q (0.125f * L2E)    // fold 1/sqrt(D) and log2(e) into q

// ---------------------------------------------------------------------------
// Scratch (allocation-free rule: __device__ globals)  — fp16 hi/lo
// ---------------------------------------------------------------------------
__device__ __align__(16) __half g_xhi[(size_t)BT*EE];
__device__ __align__(16) __half g_xlo[(size_t)BT*EE];
__device__ __align__(16) __half g_wth[(size_t)NQKV*EE];
__device__ __align__(16) __half g_woh[(size_t)EE*EE];
__device__ __align__(16) __half g_chi[(size_t)BT*EE];     // attn out hi
__device__ __align__(16) __half g_clo[(size_t)BT*EE];     // attn out lo

// fp16 q (hi+lo), k/v (hi only) in [B,H,T,D]
__device__ __align__(16) __half g_qh[(size_t)BB*HH*TT*DD];
__device__ __align__(16) __half g_ql[(size_t)BB*HH*TT*DD];
__device__ __align__(16) __half g_kh[(size_t)BB*HH*TT*DD];
__device__ __align__(16) __half g_vh[(size_t)BB*HH*TT*DD];

// ---------------------------------------------------------------------------
// Helpers (base sm_103 ISA: mma.sync / ldmatrix / cp.async)
// ---------------------------------------------------------------------------
__device__ __forceinline__ uint32_t smem_u32(const void* p) {
    uint32_t a;
    asm("{ .reg .u64 t; cvta.to.shared.u64 t, %1; cvt.u32.u64 %0, t; }"
        : "=r"(a) : "l"(p));
    return a;
}

#define LDSM4(r, addr) \
    asm volatile("ldmatrix.sync.aligned.m8n8.x4.shared.b16 {%0,%1,%2,%3}, [%4];" \
        : "=r"((r)[0]), "=r"((r)[1]), "=r"((r)[2]), "=r"((r)[3]) : "r"(addr))

#define LDSM4T(r, addr) \
    asm volatile("ldmatrix.sync.aligned.m8n8.x4.trans.shared.b16 {%0,%1,%2,%3}, [%4];" \
        : "=r"((r)[0]), "=r"((r)[1]), "=r"((r)[2]), "=r"((r)[3]) : "r"(addr))

#define MMA16816(c, a, b0, b1) \
    asm volatile("mma.sync.aligned.m16n8k16.row.col.f32.f16.f16.f32 " \
        "{%0,%1,%2,%3}, {%4,%5,%6,%7}, {%8,%9}, {%0,%1,%2,%3};" \
        : "+f"((c)[0]), "+f"((c)[1]), "+f"((c)[2]), "+f"((c)[3]) \
        : "r"((a)[0]), "r"((a)[1]), "r"((a)[2]), "r"((a)[3]), "r"(b0), "r"(b1))

#define CP_ASYNC16(dst, src) \
    asm volatile("cp.async.cg.shared.global [%0], [%1], 16;" :: "r"(dst), "l"(src))
#define CP_COMMIT() asm volatile("cp.async.commit_group;" ::: "memory")
#define CP_WAIT(n)  asm volatile("cp.async.wait_group %0;" :: "n"(n) : "memory")

// split two floats into packed fp16x2 hi and lo residual
__device__ __forceinline__ void split2(float a, float b, uint32_t& hi, uint32_t& lo) {
    __half ha = __float2half_rn(a), hb = __float2half_rn(b);
    float ra = a - __half2float(ha);
    float rb = b - __half2float(hb);
    __half2 H = __halves2half2(ha, hb);
    __half2 L = __halves2half2(__float2half_rn(ra), __float2half_rn(rb));
    hi = *(uint32_t*)&H;
    lo = *(uint32_t*)&L;
}

__device__ __forceinline__ uint32_t pack_h2(float a, float b) {
    __half2 H = __halves2half2(__float2half_rn(a), __float2half_rn(b));
    return *(uint32_t*)&H;
}

// fast exp2 on the FMA pipe (degree-7, rel err ~1e-6)
__device__ __forceinline__ float exp2fast(float x) {
    x = fmaxf(x, -125.0f);
    int n = __float2int_rd(x);
    float f = x - (float)n;
    float p = 1.3570247e-5f;
    p = fmaf(p, f, 1.5353362e-4f);
    p = fmaf(p, f, 1.3398874e-3f);
    p = fmaf(p, f, 9.6184374e-3f);
    p = fmaf(p, f, 5.5503325e-2f);
    p = fmaf(p, f, 2.4022648e-1f);
    p = fmaf(p, f, 6.9314720e-1f);
    p = fmaf(p, f, 1.0f);
    return p * __int_as_float((n + 127) << 23);
}

// ---------------------------------------------------------------------------
// Prep: fp32 -> (fp16 hi, fp16 lo)
// ---------------------------------------------------------------------------
__global__ __launch_bounds__(256) void conv_hilo(
    const float* __restrict__ s, __half* __restrict__ hi,
    __half* __restrict__ lo, int n4)
{
    int i = blockIdx.x * 256 + threadIdx.x;
    if (i >= n4) return;
    float4 v = ((const float4*)s)[i];
    uint32_t h0, l0, h1, l1;
    split2(v.x, v.y, h0, l0);
    split2(v.z, v.w, h1, l1);
    ((uint32_t*)hi)[i * 2 + 0] = h0;
    ((uint32_t*)hi)[i * 2 + 1] = h1;
    if (lo) {
        ((uint32_t*)lo)[i * 2 + 0] = l0;
        ((uint32_t*)lo)[i * 2 + 1] = l1;
    }
}

// ---------------------------------------------------------------------------
// Prep: transpose qkv weights (hi only). W[h][e][d] -> Wt[n][e]
// ---------------------------------------------------------------------------
__global__ __launch_bounds__(256) void prep_wt(
    const float* __restrict__ Wq, const float* __restrict__ Wk,
    const float* __restrict__ Wv, __half* __restrict__ th)
{
    __shared__ float ts[64][65];
    const int bx = blockIdx.x;
    const int mi = bx >> 8;
    const int rem = bx & 255;
    const int h = rem >> 4;
    const int e0 = (rem & 15) * 64;
    const float* src = (mi == 0 ? Wq : (mi == 1 ? Wk : Wv)) + (size_t)h * EE * DD;
    const int tid = threadIdx.x;

    #pragma unroll
    for (int i = 0; i < 4; ++i) {
        int idx = tid + i * 256;
        int ei = idx >> 4, d4 = idx & 15;
        float4 v = ((const float4*)(src + (size_t)(e0 + ei) * DD))[d4];
        ts[ei][d4 * 4 + 0] = v.x; ts[ei][d4 * 4 + 1] = v.y;
        ts[ei][d4 * 4 + 2] = v.z; ts[ei][d4 * 4 + 3] = v.w;
    }
    __syncthreads();

    const int d = tid >> 2, seg = tid & 3;
    const size_t row = ((size_t)mi * 1024 + h * 64 + d) * EE + e0 + seg * 16;
    alignas(16) __half hb[16];
    #pragma unroll
    for (int i = 0; i < 16; ++i)
        hb[i] = __float2half_rn(ts[seg * 16 + i][d]);
    *(uint4*)(th + row)     = *(const uint4*)(hb);
    *(uint4*)(th + row + 8) = *(const uint4*)(hb + 8);
}

// ---------------------------------------------------------------------------
// HMMA split-fp16 GEMM, 128Mx128N block, warp 32x64, 2 CTAs/SM.
// 3-stage cp.async ring, prefetch distance 2 (covers L2 latency for 1-pass
// tiles), one barrier per chunk, loads issued BEFORE compute.
// MODE 0 (qkv): Al pass only for Q range (n0<1024); K/V 1-pass.
// MODE 1 (out-proj): always 2-pass, fp32 + bias epilogue.
// ---------------------------------------------------------------------------
#define PITCH 40
#define A_ELEMS (128 * PITCH)            // 5120
#define B_ELEMS (128 * PITCH)            // 5120
#define STAGE_BYTES ((2 * A_ELEMS + B_ELEMS) * 2)   // 30720
#define NSTAGE 3

template <int MODE>
__global__ __launch_bounds__(256, 2)
void mma_gemm(const __half* __restrict__ Ah, const __half* __restrict__ Al,
              const __half* __restrict__ Bh,
              const float* __restrict__ bias,
              __half* __restrict__ qh, __half* __restrict__ ql,
              __half* __restrict__ kh, __half* __restrict__ vh,
              float* __restrict__ oplain)
{
    extern __shared__ char sm[];
    const uint32_t sbase = smem_u32(sm);
    const int tid = threadIdx.x;
    const int wid = tid >> 5, lane = tid & 31;
    const int wm = wid & 3, wn = wid >> 2;       // 4 M-warps x 2 N-warps
    const int n0 = blockIdx.x * 128;
    const int m0 = blockIdx.y * 128;
    const bool need_lo = (MODE == 1) || (n0 < 1024);   // Q range only in mode 0

    const int a_row = lane & 15;
    const int a_col = (lane >> 4) << 3;
    const int b_row = ((lane >> 4) << 3) + (lane & 7);
    const int b_col = ((lane >> 3) & 1) << 3;

    float c[2][8][4] = {};    // warp tile 32x64

    const int lr = tid >> 2, lseg = tid & 3;
    const __half* pA0 = Ah + (size_t)(m0 + lr) * EE + lseg * 8;
    const __half* pA1 = Al + (size_t)(m0 + lr) * EE + lseg * 8;
    const __half* pB0 = Bh + (size_t)(n0 + lr) * EE + lseg * 8;
    const uint32_t doff = (uint32_t)(lr * PITCH + lseg * 8) * 2;

    auto stage_load = [&](uint32_t bufbase) {
        const uint32_t d0 = bufbase + doff;
        CP_ASYNC16(d0,                                  pA0);
        CP_ASYNC16(d0 + 64 * PITCH * 2,                 pA0 + (size_t)64 * EE);
        if (need_lo) {
            CP_ASYNC16(d0 + A_ELEMS * 2,                  pA1);
            CP_ASYNC16(d0 + A_ELEMS * 2 + 64 * PITCH * 2, pA1 + (size_t)64 * EE);
            pA1 += 32;
        }
        const uint32_t b0 = d0 + 2 * A_ELEMS * 2;
        CP_ASYNC16(b0,                                  pB0);
        CP_ASYNC16(b0 + 64 * PITCH * 2,                 pB0 + (size_t)64 * EE);
        CP_COMMIT();
        pA0 += 32; pB0 += 32;
    };

    stage_load(sbase);
    stage_load(sbase + STAGE_BYTES);

    for (int ch = 0; ch < 32; ++ch) {
        if (ch < 31) CP_WAIT(1);
        else         CP_WAIT(0);
        __syncthreads();
        // issue loads for ch+2 NOW (buffer (ch+2)%3 last read at ch-1; barrier orders)
        if (ch + 2 < 32) stage_load(sbase + ((ch + 2) % NSTAGE) * STAGE_BYTES);

        const uint32_t sb  = sbase + (ch % NSTAGE) * STAGE_BYTES;
        const uint32_t sAh = sb;
        const uint32_t sAl = sb + A_ELEMS * 2;
        const uint32_t sBh = sb + 2 * A_ELEMS * 2;

        #pragma unroll
        for (int ks = 0; ks < 2; ++ks) {
            uint32_t ah[2][4], alr[2][4];
            #pragma unroll
            for (int mi = 0; mi < 2; ++mi) {
                uint32_t off = (uint32_t)((wm * 32 + mi * 16 + a_row) * PITCH
                                          + ks * 16 + a_col) * 2;
                LDSM4(ah[mi], sAh + off);
                if (need_lo) LDSM4(alr[mi], sAl + off);
            }
            #pragma unroll
            for (int jp = 0; jp < 4; ++jp) {
                uint32_t bb[4];
                uint32_t off = (uint32_t)((wn * 64 + jp * 16 + b_row) * PITCH
                                          + ks * 16 + b_col) * 2;
                LDSM4(bb, sBh + off);
                #pragma unroll
                for (int mi = 0; mi < 2; ++mi)
                    #pragma unroll
                    for (int t = 0; t < 2; ++t)
                        MMA16816(c[mi][jp * 2 + t], ah[mi],  bb[t * 2], bb[t * 2 + 1]);
                if (need_lo) {
                    #pragma unroll
                    for (int mi = 0; mi < 2; ++mi)
                        #pragma unroll
                        for (int t = 0; t < 2; ++t)
                            MMA16816(c[mi][jp * 2 + t], alr[mi], bb[t * 2], bb[t * 2 + 1]);
                }
            }
        }
    }

    const int rbase = m0 + wm * 32 + (lane >> 2);
    const int cpair = (lane & 3) * 2;

    if (MODE == 0) {
        const int which = n0 >> 10;
        const float sc = (which == 0) ? SCALE_Q : 1.0f;
        const int h = ((n0 & 1023) >> 6) + wn;
        #pragma unroll
        for (int mi = 0; mi < 2; ++mi) {
            const int m1 = rbase + mi * 16;
            const int m2 = m1 + 8;
            const size_t base1 = (((size_t)(m1 >> 11) * HH + h) * TT + (m1 & 2047)) * DD;
            const size_t base2 = (((size_t)(m2 >> 11) * HH + h) * TT + (m2 & 2047)) * DD;
            #pragma unroll
            for (int nt = 0; nt < 8; ++nt) {
                const int d = nt * 8 + cpair;
                if (which == 0) {       // q: hi + lo
                    uint32_t h1, l1, h2, l2;
                    split2(c[mi][nt][0] * sc, c[mi][nt][1] * sc, h1, l1);
                    split2(c[mi][nt][2] * sc, c[mi][nt][3] * sc, h2, l2);
                    *(uint32_t*)(qh + base1 + d) = h1;
                    *(uint32_t*)(ql + base1 + d) = l1;
                    *(uint32_t*)(qh + base2 + d) = h2;
                    *(uint32_t*)(ql + base2 + d) = l2;
                } else {                // k/v: hi only
                    __half* dst = (which == 1) ? kh : vh;
                    *(uint32_t*)(dst + base1 + d) = pack_h2(c[mi][nt][0], c[mi][nt][1]);
                    *(uint32_t*)(dst + base2 + d) = pack_h2(c[mi][nt][2], c[mi][nt][3]);
                }
            }
        }
    } else {
        #pragma unroll
        for (int mi = 0; mi < 2; ++mi) {
            const int m1 = rbase + mi * 16;
            float* r1 = oplain + (size_t)m1 * EE;
            float* r2 = oplain + (size_t)(m1 + 8) * EE;
            #pragma unroll
            for (int nt = 0; nt < 8; ++nt) {
                const int col = n0 + wn * 64 + nt * 8 + cpair;
                const float b0 = bias[col], b1v = bias[col + 1];
                float2 v1 = make_float2(c[mi][nt][0] + b0, c[mi][nt][1] + b1v);
                float2 v2 = make_float2(c[mi][nt][2] + b0, c[mi][nt][3] + b1v);
                *(float2*)(r1 + col) = v1;
                *(float2*)(r2 + col) = v2;
            }
        }
    }
}

// ---------------------------------------------------------------------------
// Tensor-core causal flash attention: 2 CTAs/SM, 2-stage KV ring (kh+vh only).
// S = Qh.Kh + Ql.Kh (2-pass); O = Ph.Vh + Pl.Vh (2-pass).
// Epilogue writes fp16 hi/lo ctx directly.  (Compute-bound; unchanged.)
// ---------------------------------------------------------------------------
#define AP 72
#define SM_Q 0
#define QARR (128 * AP * 2)
#define SM_STAGE (2 * QARR)
#define KVARR (64 * AP * 2)
#define STAGE_SZ (2 * KVARR)               // kh + vh only
#define SM_MASK (SM_STAGE + 2 * STAGE_SZ)
#define SM_TOTAL (SM_MASK + 2 * 256)

__global__ __launch_bounds__(256, 2)
void attn_mma(const __half* __restrict__ qh, const __half* __restrict__ ql,
              const __half* __restrict__ kh, const __half* __restrict__ vh,
              const float* __restrict__ amask,
              __half* __restrict__ chi, __half* __restrict__ clo)
{
    extern __shared__ char sm[];
    const uint32_t sbase = smem_u32(sm);
    const int tid = threadIdx.x;
    const int w = tid >> 5, lane = tid & 31;
    const int bh = blockIdx.x;
    const int b_ = bh >> 4, h = bh & 15;
    const int qt = 15 - blockIdx.y;
    const int q0 = qt * 128;
    const int last = 2 * qt + 1;

    const int a_row = lane & 15;
    const int a_col = (lane >> 4) << 3;
    const int b_row = ((lane >> 4) << 3) + (lane & 7);
    const int b_col = ((lane >> 3) & 1) << 3;
    const int v_key = (lane & 7) + (((lane >> 3) & 1) << 3);
    const int v_d   = (lane >> 4) << 3;

    const size_t gbase = (size_t)bh * TT * DD;

    auto load_q = [&]() {
        #pragma unroll
        for (int arr = 0; arr < 2; ++arr) {
            const __half* src0 = arr ? ql : qh;
            #pragma unroll
            for (int half = 0; half < 4; ++half) {
                int loc = half * 256 + tid;
                int r = loc >> 3, seg = loc & 7;
                const __half* src = src0 + gbase + (size_t)(q0 + r) * DD + seg * 8;
                uint32_t dst = sbase + SM_Q + arr * QARR + (uint32_t)(r * AP + seg * 8) * 2;
                CP_ASYNC16(dst, src);
            }
        }
    };
    auto load_kv = [&](int buf, int kt) {
        const int s0 = kt * 64;
        #pragma unroll
        for (int arr = 0; arr < 2; ++arr) {
            const __half* src0 = arr ? vh : kh;
            #pragma unroll
            for (int half = 0; half < 2; ++half) {
                int loc = half * 256 + tid;
                int r = loc >> 3, seg = loc & 7;
                const __half* src = src0 + gbase + (size_t)(s0 + r) * DD + seg * 8;
                uint32_t dst = sbase + SM_STAGE + buf * STAGE_SZ + arr * KVARR
                             + (uint32_t)(r * AP + seg * 8) * 2;
                CP_ASYNC16(dst, src);
            }
        }
        if (tid < 16) {
            const float* msrc = amask + (size_t)b_ * TT + s0 + tid * 4;
            uint32_t mdst = sbase + SM_MASK + buf * 256 + tid * 16;
            CP_ASYNC16(mdst, msrc);
        }
        CP_COMMIT();
    };

    load_q();
    load_kv(0, 0);
    load_kv(1, 1);
    CP_WAIT(1);
    __syncthreads();

    uint32_t qa_h[4][4], qa_l[4][4];
    #pragma unroll
    for (int ks = 0; ks < 4; ++ks) {
        uint32_t off = (uint32_t)((w * 16 + a_row) * AP + ks * 16 + a_col) * 2;
        LDSM4(qa_h[ks], sbase + SM_Q + off);
        LDSM4(qa_l[ks], sbase + SM_Q + QARR + off);
    }

    float o[8][4] = {};
    float m0r = -1e30f, m1r = -1e30f, l0 = 0.f, l1 = 0.f;
    const int row0 = q0 + w * 16 + (lane >> 2);
    const int wrow_hi = q0 + w * 16 + 15;

    for (int kt = 0; kt <= last; ++kt) {
        if (kt < last) CP_WAIT(1);
        else           CP_WAIT(0);
        __syncthreads();

        const int buf = kt & 1;
        const int s0 = kt * 64;
        const bool active = (s0 <= wrow_hi);

        if (active) {
            const uint32_t kb = sbase + SM_STAGE + buf * STAGE_SZ;
            // ---- S = Qh.Kh + Ql.Kh (2-pass) ----
            float c[8][4] = {};
            #pragma unroll
            for (int ks = 0; ks < 4; ++ks) {
                #pragma unroll
                for (int hf = 0; hf < 2; ++hf) {
                    uint32_t kf[2][4];
                    #pragma unroll
                    for (int j = 0; j < 2; ++j) {
                        uint32_t off = (uint32_t)(((hf * 2 + j) * 16 + b_row) * AP
                                                  + ks * 16 + b_col) * 2;
                        LDSM4(kf[j], kb + off);
                    }
                    #pragma unroll
                    for (int t = 0; t < 4; ++t) {
                        const int nt = hf * 4 + t;
                        const int j = t >> 1, q = (t & 1) * 2;
                        MMA16816(c[nt], qa_h[ks], kf[j][q], kf[j][q + 1]);
                    }
                    #pragma unroll
                    for (int t = 0; t < 4; ++t) {
                        const int nt = hf * 4 + t;
                        const int j = t >> 1, q = (t & 1) * 2;
                        MMA16816(c[nt], qa_l[ks], kf[j][q], kf[j][q + 1]);
                    }
                }
            }
            // ---- mask + causal ----
            const float* mk = (const float*)(sm + SM_MASK + buf * 256);
            const bool dg = (s0 + 63) > (q0 + w * 16);
            #pragma unroll
            for (int nt = 0; nt < 8; ++nt) {
                const int cl = nt * 8 + (lane & 3) * 2;
                const float mv0 = mk[cl], mv1 = mk[cl + 1];
                const float ma0 = (1.0f - mv0) * -1e30f;
                const float ma1 = (1.0f - mv1) * -1e30f;
                c[nt][0] += ma0; c[nt][1] += ma1;
                c[nt][2] += ma0; c[nt][3] += ma1;
                if (dg) {
                    const int cg = s0 + cl;
                    if (cg     > row0)     c[nt][0] = -1e30f;
                    if (cg + 1 > row0)     c[nt][1] = -1e30f;
                    if (cg     > row0 + 8) c[nt][2] = -1e30f;
                    if (cg + 1 > row0 + 8) c[nt][3] = -1e30f;
                }
            }
            // ---- online softmax ----
            float t0 = -1e30f, t1 = -1e30f;
            #pragma unroll
            for (int nt = 0; nt < 8; ++nt) {
                t0 = fmaxf(t0, fmaxf(c[nt][0], c[nt][1]));
                t1 = fmaxf(t1, fmaxf(c[nt][2], c[nt][3]));
            }
            t0 = fmaxf(t0, __shfl_xor_sync(0xffffffffu, t0, 1));
            t0 = fmaxf(t0, __shfl_xor_sync(0xffffffffu, t0, 2));
            t1 = fmaxf(t1, __shfl_xor_sync(0xffffffffu, t1, 1));
            t1 = fmaxf(t1, __shfl_xor_sync(0xffffffffu, t1, 2));
            const float mn0 = fmaxf(m0r, t0), mn1 = fmaxf(m1r, t1);
            const float cor0 = exp2fast(m0r - mn0), cor1 = exp2fast(m1r - mn1);
            m0r = mn0; m1r = mn1;
            l0 *= cor0; l1 *= cor1;
            #pragma unroll
            for (int nt = 0; nt < 8; ++nt) {
                o[nt][0] *= cor0; o[nt][1] *= cor0;
                o[nt][2] *= cor1; o[nt][3] *= cor1;
            }
            // ---- fused P conversion + O += Ph.Vh + Pl.Vh (2-pass) ----
            float s0sum = 0.f, s1sum = 0.f;
            #pragma unroll
            for (int ks = 0; ks < 4; ++ks) {
                uint32_t pa_h[4], pa_l[4];
                #pragma unroll
                for (int t = 0; t < 2; ++t) {
                    const int nt = ks * 2 + t;
                    const float p0 = exp2fast(c[nt][0] - mn0);
                    const float p1 = exp2fast(c[nt][1] - mn0);
                    const float p2 = exp2fast(c[nt][2] - mn1);
                    const float p3 = exp2fast(c[nt][3] - mn1);
                    s0sum += p0 + p1; s1sum += p2 + p3;
                    split2(p0, p1, pa_h[t * 2], pa_l[t * 2]);
                    split2(p2, p3, pa_h[t * 2 + 1], pa_l[t * 2 + 1]);
                }
                #pragma unroll
                for (int hf = 0; hf < 2; ++hf) {
                    uint32_t vf[2][4];
                    #pragma unroll
                    for (int j = 0; j < 2; ++j) {
                        uint32_t off = (uint32_t)((ks * 16 + v_key) * AP
                                                  + (hf * 2 + j) * 16 + v_d) * 2;
                        LDSM4T(vf[j], kb + KVARR + off);
                    }
                    #pragma unroll
                    for (int t = 0; t < 4; ++t) {
                        const int nt = hf * 4 + t;
                        const int j = t >> 1, q = (t & 1) * 2;
                        MMA16816(o[nt], pa_h, vf[j][q], vf[j][q + 1]);
                    }
                    #pragma unroll
                    for (int t = 0; t < 4; ++t) {
                        const int nt = hf * 4 + t;
                        const int j = t >> 1, q = (t & 1) * 2;
                        MMA16816(o[nt], pa_l, vf[j][q], vf[j][q + 1]);
                    }
                }
            }
            s0sum += __shfl_xor_sync(0xffffffffu, s0sum, 1);
            s0sum += __shfl_xor_sync(0xffffffffu, s0sum, 2);
            s1sum += __shfl_xor_sync(0xffffffffu, s1sum, 1);
            s1sum += __shfl_xor_sync(0xffffffffu, s1sum, 2);
            l0 += s0sum; l1 += s1sum;
        }
        __syncthreads();
        if (kt + 2 <= last) load_kv(buf, kt + 2);
    }

    // ---- normalize + split + store fp16 hi/lo ctx [B,T,E] ----
    const float inv0 = 1.0f / l0, inv1 = 1.0f / l1;
    const int cpair = (lane & 3) * 2;
    const size_t r1 = ((size_t)b_ * TT + row0) * EE + h * 64;
    const size_t r2 = ((size_t)b_ * TT + row0 + 8) * EE + h * 64;
    #pragma unroll
    for (int nt = 0; nt < 8; ++nt) {
        const int d = nt * 8 + cpair;
        uint32_t h1, l1w, h2, l2;
        split2(o[nt][0] * inv0, o[nt][1] * inv0, h1, l1w);
        split2(o[nt][2] * inv1, o[nt][3] * inv1, h2, l2);
        *(uint32_t*)(chi + r1 + d) = h1;
        *(uint32_t*)(clo + r1 + d) = l1w;
        *(uint32_t*)(chi + r2 + d) = h2;
        *(uint32_t*)(clo + r2 + d) = l2;
    }
}

// ---------------------------------------------------------------------------
// Launch
// ---------------------------------------------------------------------------
extern "C" void kernel_launch(void* const* d_in, const int* in_sizes, int n_in,
                              void* d_out, int out_size)
{
    const float* x     = (const float*)d_in[0];
    const float* amask = (const float*)d_in[1];
    const float* Wq    = (const float*)d_in[2];
    const float* Wk    = (const float*)d_in[3];
    const float* Wv    = (const float*)d_in[4];
    const float* Wo    = (const float*)d_in[5];
    const float* bo    = (const float*)d_in[6];
    float* out = (float*)d_out;

    __half *xhi, *xlo, *wth, *woh, *chi, *clo;
    __half *qh, *ql, *kh, *vh;
    cudaGetSymbolAddress((void**)&xhi, g_xhi);
    cudaGetSymbolAddress((void**)&xlo, g_xlo);
    cudaGetSymbolAddress((void**)&wth, g_wth);
    cudaGetSymbolAddress((void**)&woh, g_woh);
    cudaGetSymbolAddress((void**)&chi, g_chi);
    cudaGetSymbolAddress((void**)&clo, g_clo);
    cudaGetSymbolAddress((void**)&qh,  g_qh);
    cudaGetSymbolAddress((void**)&ql,  g_ql);
    cudaGetSymbolAddress((void**)&kh,  g_kh);
    cudaGetSymbolAddress((void**)&vh,  g_vh);

    cudaFuncSetAttribute(mma_gemm<0>, cudaFuncAttributeMaxDynamicSharedMemorySize,
                         NSTAGE * STAGE_BYTES);
    cudaFuncSetAttribute(mma_gemm<1>, cudaFuncAttributeMaxDynamicSharedMemorySize,
                         NSTAGE * STAGE_BYTES);
    cudaFuncSetAttribute(attn_mma, cudaFuncAttributeMaxDynamicSharedMemorySize,
                         SM_TOTAL);

    conv_hilo<<<(BT * EE / 4) / 256, 256>>>(x, xhi, xlo, BT * EE / 4);
    prep_wt<<<768, 256>>>(Wq, Wk, Wv, wth);
    conv_hilo<<<(EE * EE / 4) / 256, 256>>>(Wo, woh, nullptr, EE * EE / 4);

    {   // QKV projection: Q 2-pass (hi+lo out), K/V 1-pass (hi out)
        dim3 grid(NQKV / 128, BT / 128);
        mma_gemm<0><<<grid, 256, NSTAGE * STAGE_BYTES>>>(xhi, xlo, wth, nullptr,
                                                         qh, ql, kh, vh, nullptr);
    }
    {   // attention (2-pass S, 2-pass PV) -> fp16 hi/lo ctx
        dim3 grid(BB * HH, TT / 128);
        attn_mma<<<grid, 256, SM_TOTAL>>>(qh, ql, kh, vh, amask, chi, clo);
    }
    {   // output projection (2-pass: ctx_hi.Wo + ctx_lo.Wo)
        dim3 grid(EE / 128, BT / 128);
        mma_gemm<1><<<grid, 256, NSTAGE * STAGE_BYTES>>>(chi, clo, woh, bo,
                                                         nullptr, nullptr, nullptr,
                                                         nullptr, out);
    }
}

// round 14
// speedup vs baseline: 2.1932x; 1.3502x over previous
#include <cuda_runtime.h>
#include <cuda_fp16.h>
#include <math_constants.h>
#include <cstdint>

// Problem constants
#define BB 4
#define TT 2048
#define EE 1024
#define HH 16
#define DD 64
#define BT (BB*TT)          // 8192
#define NQKV 3072

#define L2E 1.44269504f
#define SCALE_Q (0.125f * L2E)    // fold 1/sqrt(D) and log2(e) into q

// ---------------------------------------------------------------------------
// Scratch (allocation-free rule: __device__ globals)
// ---------------------------------------------------------------------------
__device__ __align__(16) __half g_xhi[(size_t)BT*EE];
__device__ __align__(16) __half g_wth[(size_t)NQKV*EE];
__device__ __align__(16) __half g_woh[(size_t)EE*EE];
__device__ __align__(16) __half g_chi[(size_t)BT*EE];     // attn out hi
__device__ __align__(16) __half g_clo[(size_t)BT*EE];     // attn out lo

// fp16 q/k/v (hi only) in [B,H,T,D]
__device__ __align__(16) __half g_qh[(size_t)BB*HH*TT*DD];
__device__ __align__(16) __half g_kh[(size_t)BB*HH*TT*DD];
__device__ __align__(16) __half g_vh[(size_t)BB*HH*TT*DD];

// ---------------------------------------------------------------------------
// Helpers (base sm_103 ISA: mma.sync / ldmatrix / cp.async)
// ---------------------------------------------------------------------------
__device__ __forceinline__ uint32_t smem_u32(const void* p) {
    uint32_t a;
    asm("{ .reg .u64 t; cvta.to.shared.u64 t, %1; cvt.u32.u64 %0, t; }"
        : "=r"(a) : "l"(p));
    return a;
}

#define LDSM4(r, addr) \
    asm volatile("ldmatrix.sync.aligned.m8n8.x4.shared.b16 {%0,%1,%2,%3}, [%4];" \
        : "=r"((r)[0]), "=r"((r)[1]), "=r"((r)[2]), "=r"((r)[3]) : "r"(addr))

#define LDSM4T(r, addr) \
    asm volatile("ldmatrix.sync.aligned.m8n8.x4.trans.shared.b16 {%0,%1,%2,%3}, [%4];" \
        : "=r"((r)[0]), "=r"((r)[1]), "=r"((r)[2]), "=r"((r)[3]) : "r"(addr))

#define MMA16816(c, a, b0, b1) \
    asm volatile("mma.sync.aligned.m16n8k16.row.col.f32.f16.f16.f32 " \
        "{%0,%1,%2,%3}, {%4,%5,%6,%7}, {%8,%9}, {%0,%1,%2,%3};" \
        : "+f"((c)[0]), "+f"((c)[1]), "+f"((c)[2]), "+f"((c)[3]) \
        : "r"((a)[0]), "r"((a)[1]), "r"((a)[2]), "r"((a)[3]), "r"(b0), "r"(b1))

#define CP_ASYNC16(dst, src) \
    asm volatile("cp.async.cg.shared.global [%0], [%1], 16;" :: "r"(dst), "l"(src))
#define CP_COMMIT() asm volatile("cp.async.commit_group;" ::: "memory")
#define CP_WAIT(n)  asm volatile("cp.async.wait_group %0;" :: "n"(n) : "memory")

// split two floats into packed fp16x2 hi and lo residual
__device__ __forceinline__ void split2(float a, float b, uint32_t& hi, uint32_t& lo) {
    __half ha = __float2half_rn(a), hb = __float2half_rn(b);
    float ra = a - __half2float(ha);
    float rb = b - __half2float(hb);
    __half2 H = __halves2half2(ha, hb);
    __half2 L = __halves2half2(__float2half_rn(ra), __float2half_rn(rb));
    hi = *(uint32_t*)&H;
    lo = *(uint32_t*)&L;
}

__device__ __forceinline__ uint32_t pack_h2(float a, float b) {
    __half2 H = __halves2half2(__float2half_rn(a), __float2half_rn(b));
    return *(uint32_t*)&H;
}

// fast exp2 on the FMA pipe (degree-7, rel err ~1e-6)
__device__ __forceinline__ float exp2fast(float x) {
    x = fmaxf(x, -125.0f);
    int n = __float2int_rd(x);
    float f = x - (float)n;
    float p = 1.3570247e-5f;
    p = fmaf(p, f, 1.5353362e-4f);
    p = fmaf(p, f, 1.3398874e-3f);
    p = fmaf(p, f, 9.6184374e-3f);
    p = fmaf(p, f, 5.5503325e-2f);
    p = fmaf(p, f, 2.4022648e-1f);
    p = fmaf(p, f, 6.9314720e-1f);
    p = fmaf(p, f, 1.0f);
    return p * __int_as_float((n + 127) << 23);
}

// ---------------------------------------------------------------------------
// Prep: fp32 -> fp16 hi (lo optional)
// ---------------------------------------------------------------------------
__global__ __launch_bounds__(256) void conv_hilo(
    const float* __restrict__ s, __half* __restrict__ hi,
    __half* __restrict__ lo, int n4)
{
    int i = blockIdx.x * 256 + threadIdx.x;
    if (i >= n4) return;
    float4 v = ((const float4*)s)[i];
    uint32_t h0, l0, h1, l1;
    split2(v.x, v.y, h0, l0);
    split2(v.z, v.w, h1, l1);
    ((uint32_t*)hi)[i * 2 + 0] = h0;
    ((uint32_t*)hi)[i * 2 + 1] = h1;
    if (lo) {
        ((uint32_t*)lo)[i * 2 + 0] = l0;
        ((uint32_t*)lo)[i * 2 + 1] = l1;
    }
}

// ---------------------------------------------------------------------------
// Prep: transpose qkv weights (hi only). W[h][e][d] -> Wt[n][e]
// ---------------------------------------------------------------------------
__global__ __launch_bounds__(256) void prep_wt(
    const float* __restrict__ Wq, const float* __restrict__ Wk,
    const float* __restrict__ Wv, __half* __restrict__ th)
{
    __shared__ float ts[64][65];
    const int bx = blockIdx.x;
    const int mi = bx >> 8;
    const int rem = bx & 255;
    const int h = rem >> 4;
    const int e0 = (rem & 15) * 64;
    const float* src = (mi == 0 ? Wq : (mi == 1 ? Wk : Wv)) + (size_t)h * EE * DD;
    const int tid = threadIdx.x;

    #pragma unroll
    for (int i = 0; i < 4; ++i) {
        int idx = tid + i * 256;
        int ei = idx >> 4, d4 = idx & 15;
        float4 v = ((const float4*)(src + (size_t)(e0 + ei) * DD))[d4];
        ts[ei][d4 * 4 + 0] = v.x; ts[ei][d4 * 4 + 1] = v.y;
        ts[ei][d4 * 4 + 2] = v.z; ts[ei][d4 * 4 + 3] = v.w;
    }
    __syncthreads();

    const int d = tid >> 2, seg = tid & 3;
    const size_t row = ((size_t)mi * 1024 + h * 64 + d) * EE + e0 + seg * 16;
    alignas(16) __half hb[16];
    #pragma unroll
    for (int i = 0; i < 16; ++i)
        hb[i] = __float2half_rn(ts[seg * 16 + i][d]);
    *(uint4*)(th + row)     = *(const uint4*)(hb);
    *(uint4*)(th + row + 8) = *(const uint4*)(hb + 8);
}

// ---------------------------------------------------------------------------
// HMMA fp16 GEMM, 128Mx128N block, warp 32x64, 2 CTAs/SM, 3-stage ring.
// MODE 0 (qkv): 1-pass C = Ah.Bh -> fp16 hi q/k/v (SCALE_Q folded into q)
// MODE 1 (out): 2-pass C = Ah.Bh + Al.Bh -> fp32 + bias
// ---------------------------------------------------------------------------
#define PITCH 40
#define A_ELEMS (128 * PITCH)            // 5120
#define B_ELEMS (128 * PITCH)            // 5120
#define STB0 ((A_ELEMS + B_ELEMS) * 2)       // 20480
#define STB1 ((2 * A_ELEMS + B_ELEMS) * 2)   // 30720
#define NSTAGE 3

template <int MODE>
__global__ __launch_bounds__(256, 2)
void mma_gemm(const __half* __restrict__ Ah, const __half* __restrict__ Al,
              const __half* __restrict__ Bh,
              const float* __restrict__ bias,
              __half* __restrict__ qh, __half* __restrict__ kh,
              __half* __restrict__ vh,
              float* __restrict__ oplain)
{
    constexpr uint32_t STAGE_BYTES = (MODE == 0) ? STB0 : STB1;
    constexpr bool NEED_LO = (MODE == 1);
    extern __shared__ char sm[];
    const uint32_t sbase = smem_u32(sm);
    const int tid = threadIdx.x;
    const int wid = tid >> 5, lane = tid & 31;
    const int wm = wid & 3, wn = wid >> 2;       // 4 M-warps x 2 N-warps
    const int n0 = blockIdx.x * 128;
    const int m0 = blockIdx.y * 128;

    const int a_row = lane & 15;
    const int a_col = (lane >> 4) << 3;
    const int b_row = ((lane >> 4) << 3) + (lane & 7);
    const int b_col = ((lane >> 3) & 1) << 3;

    float c[2][8][4] = {};    // warp tile 32x64

    const int lr = tid >> 2, lseg = tid & 3;
    const __half* pA0 = Ah + (size_t)(m0 + lr) * EE + lseg * 8;
    const __half* pA1 = NEED_LO ? Al + (size_t)(m0 + lr) * EE + lseg * 8 : nullptr;
    const __half* pB0 = Bh + (size_t)(n0 + lr) * EE + lseg * 8;
    const uint32_t doff = (uint32_t)(lr * PITCH + lseg * 8) * 2;

    auto stage_load = [&](uint32_t bufbase) {
        const uint32_t d0 = bufbase + doff;
        CP_ASYNC16(d0,                                  pA0);
        CP_ASYNC16(d0 + 64 * PITCH * 2,                 pA0 + (size_t)64 * EE);
        if (NEED_LO) {
            CP_ASYNC16(d0 + A_ELEMS * 2,                  pA1);
            CP_ASYNC16(d0 + A_ELEMS * 2 + 64 * PITCH * 2, pA1 + (size_t)64 * EE);
            pA1 += 32;
        }
        const uint32_t b0 = d0 + (NEED_LO ? 2 : 1) * A_ELEMS * 2;
        CP_ASYNC16(b0,                                  pB0);
        CP_ASYNC16(b0 + 64 * PITCH * 2,                 pB0 + (size_t)64 * EE);
        CP_COMMIT();
        pA0 += 32; pB0 += 32;
    };

    stage_load(sbase);
    stage_load(sbase + STAGE_BYTES);

    for (int ch = 0; ch < 32; ++ch) {
        if (ch < 31) CP_WAIT(1);
        else         CP_WAIT(0);
        __syncthreads();
        if (ch + 2 < 32) stage_load(sbase + ((ch + 2) % NSTAGE) * STAGE_BYTES);

        const uint32_t sb  = sbase + (ch % NSTAGE) * STAGE_BYTES;
        const uint32_t sAh = sb;
        const uint32_t sAl = sb + A_ELEMS * 2;
        const uint32_t sBh = sb + (NEED_LO ? 2 : 1) * A_ELEMS * 2;

        #pragma unroll
        for (int ks = 0; ks < 2; ++ks) {
            uint32_t ah[2][4], alr[2][4];
            #pragma unroll
            for (int mi = 0; mi < 2; ++mi) {
                uint32_t off = (uint32_t)((wm * 32 + mi * 16 + a_row) * PITCH
                                          + ks * 16 + a_col) * 2;
                LDSM4(ah[mi], sAh + off);
                if (NEED_LO) LDSM4(alr[mi], sAl + off);
            }
            #pragma unroll
            for (int jp = 0; jp < 4; ++jp) {
                uint32_t bb[4];
                uint32_t off = (uint32_t)((wn * 64 + jp * 16 + b_row) * PITCH
                                          + ks * 16 + b_col) * 2;
                LDSM4(bb, sBh + off);
                #pragma unroll
                for (int mi = 0; mi < 2; ++mi)
                    #pragma unroll
                    for (int t = 0; t < 2; ++t)
                        MMA16816(c[mi][jp * 2 + t], ah[mi],  bb[t * 2], bb[t * 2 + 1]);
                if (NEED_LO) {
                    #pragma unroll
                    for (int mi = 0; mi < 2; ++mi)
                        #pragma unroll
                        for (int t = 0; t < 2; ++t)
                            MMA16816(c[mi][jp * 2 + t], alr[mi], bb[t * 2], bb[t * 2 + 1]);
                }
            }
        }
    }

    const int rbase = m0 + wm * 32 + (lane >> 2);
    const int cpair = (lane & 3) * 2;

    if (MODE == 0) {
        const int which = n0 >> 10;
        __half* dst = (which == 0) ? qh : (which == 1) ? kh : vh;
        const float sc = (which == 0) ? SCALE_Q : 1.0f;
        const int h = ((n0 & 1023) >> 6) + wn;
        #pragma unroll
        for (int mi = 0; mi < 2; ++mi) {
            const int m1 = rbase + mi * 16;
            const int m2 = m1 + 8;
            const size_t base1 = (((size_t)(m1 >> 11) * HH + h) * TT + (m1 & 2047)) * DD;
            const size_t base2 = (((size_t)(m2 >> 11) * HH + h) * TT + (m2 & 2047)) * DD;
            #pragma unroll
            for (int nt = 0; nt < 8; ++nt) {
                const int d = nt * 8 + cpair;
                *(uint32_t*)(dst + base1 + d) = pack_h2(c[mi][nt][0] * sc, c[mi][nt][1] * sc);
                *(uint32_t*)(dst + base2 + d) = pack_h2(c[mi][nt][2] * sc, c[mi][nt][3] * sc);
            }
        }
    } else {
        #pragma unroll
        for (int mi = 0; mi < 2; ++mi) {
            const int m1 = rbase + mi * 16;
            float* r1 = oplain + (size_t)m1 * EE;
            float* r2 = oplain + (size_t)(m1 + 8) * EE;
            #pragma unroll
            for (int nt = 0; nt < 8; ++nt) {
                const int col = n0 + wn * 64 + nt * 8 + cpair;
                const float b0 = bias[col], b1v = bias[col + 1];
                float2 v1 = make_float2(c[mi][nt][0] + b0, c[mi][nt][1] + b1v);
                float2 v2 = make_float2(c[mi][nt][2] + b0, c[mi][nt][3] + b1v);
                *(float2*)(r1 + col) = v1;
                *(float2*)(r2 + col) = v2;
            }
        }
    }
}

// ---------------------------------------------------------------------------
// Tensor-core causal flash attention: 2 CTAs/SM, 2-stage KV ring.
// S = Qh.Kh (1-pass); O = Ph.Vh (1-pass).  Epilogue: fp16 hi/lo ctx.
// ---------------------------------------------------------------------------
#define AP 72
#define SM_Q 0
#define QARR (128 * AP * 2)                // Q hi only
#define SM_STAGE QARR
#define KVARR (64 * AP * 2)
#define STAGE_SZ (2 * KVARR)               // kh + vh
#define SM_MASK (SM_STAGE + 2 * STAGE_SZ)
#define SM_TOTAL (SM_MASK + 2 * 256)

__global__ __launch_bounds__(256, 2)
void attn_mma(const __half* __restrict__ qh,
              const __half* __restrict__ kh, const __half* __restrict__ vh,
              const float* __restrict__ amask,
              __half* __restrict__ chi, __half* __restrict__ clo)
{
    extern __shared__ char sm[];
    const uint32_t sbase = smem_u32(sm);
    const int tid = threadIdx.x;
    const int w = tid >> 5, lane = tid & 31;
    const int bh = blockIdx.x;
    const int b_ = bh >> 4, h = bh & 15;
    const int qt = 15 - blockIdx.y;
    const int q0 = qt * 128;
    const int last = 2 * qt + 1;

    const int a_row = lane & 15;
    const int a_col = (lane >> 4) << 3;
    const int b_row = ((lane >> 4) << 3) + (lane & 7);
    const int b_col = ((lane >> 3) & 1) << 3;
    const int v_key = (lane & 7) + (((lane >> 3) & 1) << 3);
    const int v_d   = (lane >> 4) << 3;

    const size_t gbase = (size_t)bh * TT * DD;

    auto load_q = [&]() {
        #pragma unroll
        for (int half = 0; half < 4; ++half) {
            int loc = half * 256 + tid;
            int r = loc >> 3, seg = loc & 7;
            const __half* src = qh + gbase + (size_t)(q0 + r) * DD + seg * 8;
            uint32_t dst = sbase + SM_Q + (uint32_t)(r * AP + seg * 8) * 2;
            CP_ASYNC16(dst, src);
        }
    };
    auto load_kv = [&](int buf, int kt) {
        const int s0 = kt * 64;
        #pragma unroll
        for (int arr = 0; arr < 2; ++arr) {
            const __half* src0 = arr ? vh : kh;
            #pragma unroll
            for (int half = 0; half < 2; ++half) {
                int loc = half * 256 + tid;
                int r = loc >> 3, seg = loc & 7;
                const __half* src = src0 + gbase + (size_t)(s0 + r) * DD + seg * 8;
                uint32_t dst = sbase + SM_STAGE + buf * STAGE_SZ + arr * KVARR
                             + (uint32_t)(r * AP + seg * 8) * 2;
                CP_ASYNC16(dst, src);
            }
        }
        if (tid < 16) {
            const float* msrc = amask + (size_t)b_ * TT + s0 + tid * 4;
            uint32_t mdst = sbase + SM_MASK + buf * 256 + tid * 16;
            CP_ASYNC16(mdst, msrc);
        }
        CP_COMMIT();
    };

    load_q();
    load_kv(0, 0);
    load_kv(1, 1);
    CP_WAIT(1);
    __syncthreads();

    uint32_t qa_h[4][4];
    #pragma unroll
    for (int ks = 0; ks < 4; ++ks) {
        uint32_t off = (uint32_t)((w * 16 + a_row) * AP + ks * 16 + a_col) * 2;
        LDSM4(qa_h[ks], sbase + SM_Q + off);
    }

    float o[8][4] = {};
    float m0r = -1e30f, m1r = -1e30f, l0 = 0.f, l1 = 0.f;
    const int row0 = q0 + w * 16 + (lane >> 2);
    const int wrow_hi = q0 + w * 16 + 15;

    for (int kt = 0; kt <= last; ++kt) {
        if (kt < last) CP_WAIT(1);
        else           CP_WAIT(0);
        __syncthreads();

        const int buf = kt & 1;
        const int s0 = kt * 64;
        const bool active = (s0 <= wrow_hi);

        if (active) {
            const uint32_t kb = sbase + SM_STAGE + buf * STAGE_SZ;
            // ---- S = Qh.Kh (1-pass) ----
            float c[8][4] = {};
            #pragma unroll
            for (int ks = 0; ks < 4; ++ks) {
                #pragma unroll
                for (int hf = 0; hf < 2; ++hf) {
                    uint32_t kf[2][4];
                    #pragma unroll
                    for (int j = 0; j < 2; ++j) {
                        uint32_t off = (uint32_t)(((hf * 2 + j) * 16 + b_row) * AP
                                                  + ks * 16 + b_col) * 2;
                        LDSM4(kf[j], kb + off);
                    }
                    #pragma unroll
                    for (int t = 0; t < 4; ++t) {
                        const int nt = hf * 4 + t;
                        const int j = t >> 1, q = (t & 1) * 2;
                        MMA16816(c[nt], qa_h[ks], kf[j][q], kf[j][q + 1]);
                    }
                }
            }
            // ---- mask + causal ----
            const float* mk = (const float*)(sm + SM_MASK + buf * 256);
            const bool dg = (s0 + 63) > (q0 + w * 16);
            #pragma unroll
            for (int nt = 0; nt < 8; ++nt) {
                const int cl = nt * 8 + (lane & 3) * 2;
                const float mv0 = mk[cl], mv1 = mk[cl + 1];
                const float ma0 = (1.0f - mv0) * -1e30f;
                const float ma1 = (1.0f - mv1) * -1e30f;
                c[nt][0] += ma0; c[nt][1] += ma1;
                c[nt][2] += ma0; c[nt][3] += ma1;
                if (dg) {
                    const int cg = s0 + cl;
                    if (cg     > row0)     c[nt][0] = -1e30f;
                    if (cg + 1 > row0)     c[nt][1] = -1e30f;
                    if (cg     > row0 + 8) c[nt][2] = -1e30f;
                    if (cg + 1 > row0 + 8) c[nt][3] = -1e30f;
                }
            }
            // ---- online softmax ----
            float t0 = -1e30f, t1 = -1e30f;
            #pragma unroll
            for (int nt = 0; nt < 8; ++nt) {
                t0 = fmaxf(t0, fmaxf(c[nt][0], c[nt][1]));
                t1 = fmaxf(t1, fmaxf(c[nt][2], c[nt][3]));
            }
            t0 = fmaxf(t0, __shfl_xor_sync(0xffffffffu, t0, 1));
            t0 = fmaxf(t0, __shfl_xor_sync(0xffffffffu, t0, 2));
            t1 = fmaxf(t1, __shfl_xor_sync(0xffffffffu, t1, 1));
            t1 = fmaxf(t1, __shfl_xor_sync(0xffffffffu, t1, 2));
            const float mn0 = fmaxf(m0r, t0), mn1 = fmaxf(m1r, t1);
            const float cor0 = exp2fast(m0r - mn0), cor1 = exp2fast(m1r - mn1);
            m0r = mn0; m1r = mn1;
            l0 *= cor0; l1 *= cor1;
            #pragma unroll
            for (int nt = 0; nt < 8; ++nt) {
                o[nt][0] *= cor0; o[nt][1] *= cor0;
                o[nt][2] *= cor1; o[nt][3] *= cor1;
            }
            // ---- P = exp2(S - m) (fp16 pack), O += Ph.Vh (1-pass) ----
            float s0sum = 0.f, s1sum = 0.f;
            #pragma unroll
            for (int ks = 0; ks < 4; ++ks) {
                uint32_t pa[4];
                #pragma unroll
                for (int t = 0; t < 2; ++t) {
                    const int nt = ks * 2 + t;
                    const float p0 = exp2fast(c[nt][0] - mn0);
                    const float p1 = exp2fast(c[nt][1] - mn0);
                    const float p2 = exp2fast(c[nt][2] - mn1);
                    const float p3 = exp2fast(c[nt][3] - mn1);
                    s0sum += p0 + p1; s1sum += p2 + p3;
                    pa[t * 2]     = pack_h2(p0, p1);
                    pa[t * 2 + 1] = pack_h2(p2, p3);
                }
                #pragma unroll
                for (int hf = 0; hf < 2; ++hf) {
                    uint32_t vf[2][4];
                    #pragma unroll
                    for (int j = 0; j < 2; ++j) {
                        uint32_t off = (uint32_t)((ks * 16 + v_key) * AP
                                                  + (hf * 2 + j) * 16 + v_d) * 2;
                        LDSM4T(vf[j], kb + KVARR + off);
                    }
                    #pragma unroll
                    for (int t = 0; t < 4; ++t) {
                        const int nt = hf * 4 + t;
                        const int j = t >> 1, q = (t & 1) * 2;
                        MMA16816(o[nt], pa, vf[j][q], vf[j][q + 1]);
                    }
                }
            }
            s0sum += __shfl_xor_sync(0xffffffffu, s0sum, 1);
            s0sum += __shfl_xor_sync(0xffffffffu, s0sum, 2);
            s1sum += __shfl_xor_sync(0xffffffffu, s1sum, 1);
            s1sum += __shfl_xor_sync(0xffffffffu, s1sum, 2);
            l0 += s0sum; l1 += s1sum;
        }
        __syncthreads();
        if (kt + 2 <= last) load_kv(buf, kt + 2);
    }

    // ---- normalize + split + store fp16 hi/lo ctx [B,T,E] ----
    const float inv0 = 1.0f / l0, inv1 = 1.0f / l1;
    const int cpair = (lane & 3) * 2;
    const size_t r1 = ((size_t)b_ * TT + row0) * EE + h * 64;
    const size_t r2 = ((size_t)b_ * TT + row0 + 8) * EE + h * 64;
    #pragma unroll
    for (int nt = 0; nt < 8; ++nt) {
        const int d = nt * 8 + cpair;
        uint32_t h1, l1w, h2, l2;
        split2(o[nt][0] * inv0, o[nt][1] * inv0, h1, l1w);
        split2(o[nt][2] * inv1, o[nt][3] * inv1, h2, l2);
        *(uint32_t*)(chi + r1 + d) = h1;
        *(uint32_t*)(clo + r1 + d) = l1w;
        *(uint32_t*)(chi + r2 + d) = h2;
        *(uint32_t*)(clo + r2 + d) = l2;
    }
}

// ---------------------------------------------------------------------------
// Launch
// ---------------------------------------------------------------------------
extern "C" void kernel_launch(void* const* d_in, const int* in_sizes, int n_in,
                              void* d_out, int out_size)
{
    const float* x     = (const float*)d_in[0];
    const float* amask = (const float*)d_in[1];
    const float* Wq    = (const float*)d_in[2];
    const float* Wk    = (const float*)d_in[3];
    const float* Wv    = (const float*)d_in[4];
    const float* Wo    = (const float*)d_in[5];
    const float* bo    = (const float*)d_in[6];
    float* out = (float*)d_out;

    __half *xhi, *wth, *woh, *chi, *clo;
    __half *qh, *kh, *vh;
    cudaGetSymbolAddress((void**)&xhi, g_xhi);
    cudaGetSymbolAddress((void**)&wth, g_wth);
    cudaGetSymbolAddress((void**)&woh, g_woh);
    cudaGetSymbolAddress((void**)&chi, g_chi);
    cudaGetSymbolAddress((void**)&clo, g_clo);
    cudaGetSymbolAddress((void**)&qh,  g_qh);
    cudaGetSymbolAddress((void**)&kh,  g_kh);
    cudaGetSymbolAddress((void**)&vh,  g_vh);

    cudaFuncSetAttribute(mma_gemm<0>, cudaFuncAttributeMaxDynamicSharedMemorySize,
                         NSTAGE * STB0);
    cudaFuncSetAttribute(mma_gemm<1>, cudaFuncAttributeMaxDynamicSharedMemorySize,
                         NSTAGE * STB1);
    cudaFuncSetAttribute(attn_mma, cudaFuncAttributeMaxDynamicSharedMemorySize,
                         SM_TOTAL);

    conv_hilo<<<(BT * EE / 4) / 256, 256>>>(x, xhi, nullptr, BT * EE / 4);
    prep_wt<<<768, 256>>>(Wq, Wk, Wv, wth);
    conv_hilo<<<(EE * EE / 4) / 256, 256>>>(Wo, woh, nullptr, EE * EE / 4);

    {   // QKV projection: 1-pass, fp16 hi outputs
        dim3 grid(NQKV / 128, BT / 128);
        mma_gemm<0><<<grid, 256, NSTAGE * STB0>>>(xhi, nullptr, wth, nullptr,
                                                  qh, kh, vh, nullptr);
    }
    {   // attention (1-pass S, 1-pass PV) -> fp16 hi/lo ctx
        dim3 grid(BB * HH, TT / 128);
        attn_mma<<<grid, 256, SM_TOTAL>>>(qh, kh, vh, amask, chi, clo);
    }
    {   // output projection (2-pass: ctx_hi.Wo + ctx_lo.Wo)
        dim3 grid(EE / 128, BT / 128);
        mma_gemm<1><<<grid, 256, NSTAGE * STB1>>>(chi, clo, woh, bo,
                                                  nullptr, nullptr, nullptr, out);
    }
}

// round 15
// speedup vs baseline: 2.4145x; 1.1009x over previous
#include <cuda_runtime.h>
#include <cuda_fp16.h>
#include <math_constants.h>
#include <cstdint>

// Problem constants
#define BB 4
#define TT 2048
#define EE 1024
#define HH 16
#define DD 64
#define BT (BB*TT)          // 8192
#define NQKV 3072

#define L2E 1.44269504f
#define SCALE_Q (0.125f * L2E)    // fold 1/sqrt(D) and log2(e) into q

// ---------------------------------------------------------------------------
// Scratch (allocation-free rule: __device__ globals)
// ---------------------------------------------------------------------------
__device__ __align__(16) __half g_xhi[(size_t)BT*EE];
__device__ __align__(16) __half g_wth[(size_t)NQKV*EE];
__device__ __align__(16) __half g_woh[(size_t)EE*EE];
__device__ __align__(16) __half g_chi[(size_t)BT*EE];     // attn out (fp16)

// fp16 q/k/v in [B,H,T,D]
__device__ __align__(16) __half g_qh[(size_t)BB*HH*TT*DD];
__device__ __align__(16) __half g_kh[(size_t)BB*HH*TT*DD];
__device__ __align__(16) __half g_vh[(size_t)BB*HH*TT*DD];

// ---------------------------------------------------------------------------
// Helpers (base sm_103 ISA: mma.sync / ldmatrix / cp.async)
// ---------------------------------------------------------------------------
__device__ __forceinline__ uint32_t smem_u32(const void* p) {
    uint32_t a;
    asm("{ .reg .u64 t; cvta.to.shared.u64 t, %1; cvt.u32.u64 %0, t; }"
        : "=r"(a) : "l"(p));
    return a;
}

#define LDSM4(r, addr) \
    asm volatile("ldmatrix.sync.aligned.m8n8.x4.shared.b16 {%0,%1,%2,%3}, [%4];" \
        : "=r"((r)[0]), "=r"((r)[1]), "=r"((r)[2]), "=r"((r)[3]) : "r"(addr))

#define LDSM4T(r, addr) \
    asm volatile("ldmatrix.sync.aligned.m8n8.x4.trans.shared.b16 {%0,%1,%2,%3}, [%4];" \
        : "=r"((r)[0]), "=r"((r)[1]), "=r"((r)[2]), "=r"((r)[3]) : "r"(addr))

#define MMA16816(c, a, b0, b1) \
    asm volatile("mma.sync.aligned.m16n8k16.row.col.f32.f16.f16.f32 " \
        "{%0,%1,%2,%3}, {%4,%5,%6,%7}, {%8,%9}, {%0,%1,%2,%3};" \
        : "+f"((c)[0]), "+f"((c)[1]), "+f"((c)[2]), "+f"((c)[3]) \
        : "r"((a)[0]), "r"((a)[1]), "r"((a)[2]), "r"((a)[3]), "r"(b0), "r"(b1))

#define CP_ASYNC16(dst, src) \
    asm volatile("cp.async.cg.shared.global [%0], [%1], 16;" :: "r"(dst), "l"(src))
#define CP_COMMIT() asm volatile("cp.async.commit_group;" ::: "memory")
#define CP_WAIT(n)  asm volatile("cp.async.wait_group %0;" :: "n"(n) : "memory")

__device__ __forceinline__ uint32_t pack_h2(float a, float b) {
    __half2 H = __halves2half2(__float2half_rn(a), __float2half_rn(b));
    return *(uint32_t*)&H;
}

// fast exp2 on the FMA pipe (degree-7, rel err ~1e-6)
__device__ __forceinline__ float exp2fast(float x) {
    x = fmaxf(x, -125.0f);
    int n = __float2int_rd(x);
    float f = x - (float)n;
    float p = 1.3570247e-5f;
    p = fmaf(p, f, 1.5353362e-4f);
    p = fmaf(p, f, 1.3398874e-3f);
    p = fmaf(p, f, 9.6184374e-3f);
    p = fmaf(p, f, 5.5503325e-2f);
    p = fmaf(p, f, 2.4022648e-1f);
    p = fmaf(p, f, 6.9314720e-1f);
    p = fmaf(p, f, 1.0f);
    return p * __int_as_float((n + 127) << 23);
}

// ---------------------------------------------------------------------------
// Prep: fp32 -> fp16
// ---------------------------------------------------------------------------
__global__ __launch_bounds__(256) void conv_h(
    const float* __restrict__ s, __half* __restrict__ hi, int n4)
{
    int i = blockIdx.x * 256 + threadIdx.x;
    if (i >= n4) return;
    float4 v = ((const float4*)s)[i];
    ((uint32_t*)hi)[i * 2 + 0] = pack_h2(v.x, v.y);
    ((uint32_t*)hi)[i * 2 + 1] = pack_h2(v.z, v.w);
}

// ---------------------------------------------------------------------------
// Prep: transpose qkv weights. W[h][e][d] -> Wt[n][e]
// ---------------------------------------------------------------------------
__global__ __launch_bounds__(256) void prep_wt(
    const float* __restrict__ Wq, const float* __restrict__ Wk,
    const float* __restrict__ Wv, __half* __restrict__ th)
{
    __shared__ float ts[64][65];
    const int bx = blockIdx.x;
    const int mi = bx >> 8;
    const int rem = bx & 255;
    const int h = rem >> 4;
    const int e0 = (rem & 15) * 64;
    const float* src = (mi == 0 ? Wq : (mi == 1 ? Wk : Wv)) + (size_t)h * EE * DD;
    const int tid = threadIdx.x;

    #pragma unroll
    for (int i = 0; i < 4; ++i) {
        int idx = tid + i * 256;
        int ei = idx >> 4, d4 = idx & 15;
        float4 v = ((const float4*)(src + (size_t)(e0 + ei) * DD))[d4];
        ts[ei][d4 * 4 + 0] = v.x; ts[ei][d4 * 4 + 1] = v.y;
        ts[ei][d4 * 4 + 2] = v.z; ts[ei][d4 * 4 + 3] = v.w;
    }
    __syncthreads();

    const int d = tid >> 2, seg = tid & 3;
    const size_t row = ((size_t)mi * 1024 + h * 64 + d) * EE + e0 + seg * 16;
    alignas(16) __half hb[16];
    #pragma unroll
    for (int i = 0; i < 16; ++i)
        hb[i] = __float2half_rn(ts[seg * 16 + i][d]);
    *(uint4*)(th + row)     = *(const uint4*)(hb);
    *(uint4*)(th + row + 8) = *(const uint4*)(hb + 8);
}

// ---------------------------------------------------------------------------
// HMMA fp16 GEMM (1-pass), 128Mx128N block, warp 32x64, 2 CTAs/SM,
// 4-stage cp.async ring (prefetch distance 3, covers L2 latency).
// MODE 0 (qkv): -> fp16 q/k/v (SCALE_Q folded into q)
// MODE 1 (out): -> fp32 + bias
// ---------------------------------------------------------------------------
#define PITCH 40
#define A_ELEMS (128 * PITCH)            // 5120
#define B_ELEMS (128 * PITCH)            // 5120
#define STAGE_BYTES ((A_ELEMS + B_ELEMS) * 2)   // 20480
#define NSTAGE 4

template <int MODE>
__global__ __launch_bounds__(256, 2)
void mma_gemm(const __half* __restrict__ Ah, const __half* __restrict__ Bh,
              const float* __restrict__ bias,
              __half* __restrict__ qh, __half* __restrict__ kh,
              __half* __restrict__ vh,
              float* __restrict__ oplain)
{
    extern __shared__ char sm[];
    const uint32_t sbase = smem_u32(sm);
    const int tid = threadIdx.x;
    const int wid = tid >> 5, lane = tid & 31;
    const int wm = wid & 3, wn = wid >> 2;       // 4 M-warps x 2 N-warps
    const int n0 = blockIdx.x * 128;
    const int m0 = blockIdx.y * 128;

    const int a_row = lane & 15;
    const int a_col = (lane >> 4) << 3;
    const int b_row = ((lane >> 4) << 3) + (lane & 7);
    const int b_col = ((lane >> 3) & 1) << 3;

    float c[2][8][4] = {};    // warp tile 32x64

    const int lr = tid >> 2, lseg = tid & 3;
    const __half* pA0 = Ah + (size_t)(m0 + lr) * EE + lseg * 8;
    const __half* pB0 = Bh + (size_t)(n0 + lr) * EE + lseg * 8;
    const uint32_t doff = (uint32_t)(lr * PITCH + lseg * 8) * 2;

    auto stage_load = [&](uint32_t bufbase) {
        const uint32_t d0 = bufbase + doff;
        CP_ASYNC16(d0,                                  pA0);
        CP_ASYNC16(d0 + 64 * PITCH * 2,                 pA0 + (size_t)64 * EE);
        const uint32_t b0 = d0 + A_ELEMS * 2;
        CP_ASYNC16(b0,                                  pB0);
        CP_ASYNC16(b0 + 64 * PITCH * 2,                 pB0 + (size_t)64 * EE);
        CP_COMMIT();
        pA0 += 32; pB0 += 32;
    };

    stage_load(sbase);
    stage_load(sbase + STAGE_BYTES);
    stage_load(sbase + 2 * STAGE_BYTES);

    for (int ch = 0; ch < 32; ++ch) {
        if (ch < 30) CP_WAIT(2);
        else if (ch == 30) CP_WAIT(1);
        else         CP_WAIT(0);
        __syncthreads();
        // issue loads for ch+3 (buffer (ch+3)%4 last read at ch-1; barrier orders)
        if (ch + 3 < 32) stage_load(sbase + ((ch + 3) % NSTAGE) * STAGE_BYTES);

        const uint32_t sb  = sbase + (ch % NSTAGE) * STAGE_BYTES;
        const uint32_t sAh = sb;
        const uint32_t sBh = sb + A_ELEMS * 2;

        #pragma unroll
        for (int ks = 0; ks < 2; ++ks) {
            uint32_t ah[2][4];
            #pragma unroll
            for (int mi = 0; mi < 2; ++mi) {
                uint32_t off = (uint32_t)((wm * 32 + mi * 16 + a_row) * PITCH
                                          + ks * 16 + a_col) * 2;
                LDSM4(ah[mi], sAh + off);
            }
            #pragma unroll
            for (int jp = 0; jp < 4; ++jp) {
                uint32_t bb[4];
                uint32_t off = (uint32_t)((wn * 64 + jp * 16 + b_row) * PITCH
                                          + ks * 16 + b_col) * 2;
                LDSM4(bb, sBh + off);
                #pragma unroll
                for (int mi = 0; mi < 2; ++mi)
                    #pragma unroll
                    for (int t = 0; t < 2; ++t)
                        MMA16816(c[mi][jp * 2 + t], ah[mi], bb[t * 2], bb[t * 2 + 1]);
            }
        }
    }

    const int rbase = m0 + wm * 32 + (lane >> 2);
    const int cpair = (lane & 3) * 2;

    if (MODE == 0) {
        const int which = n0 >> 10;
        __half* dst = (which == 0) ? qh : (which == 1) ? kh : vh;
        const float sc = (which == 0) ? SCALE_Q : 1.0f;
        const int h = ((n0 & 1023) >> 6) + wn;
        #pragma unroll
        for (int mi = 0; mi < 2; ++mi) {
            const int m1 = rbase + mi * 16;
            const int m2 = m1 + 8;
            const size_t base1 = (((size_t)(m1 >> 11) * HH + h) * TT + (m1 & 2047)) * DD;
            const size_t base2 = (((size_t)(m2 >> 11) * HH + h) * TT + (m2 & 2047)) * DD;
            #pragma unroll
            for (int nt = 0; nt < 8; ++nt) {
                const int d = nt * 8 + cpair;
                *(uint32_t*)(dst + base1 + d) = pack_h2(c[mi][nt][0] * sc, c[mi][nt][1] * sc);
                *(uint32_t*)(dst + base2 + d) = pack_h2(c[mi][nt][2] * sc, c[mi][nt][3] * sc);
            }
        }
    } else {
        #pragma unroll
        for (int mi = 0; mi < 2; ++mi) {
            const int m1 = rbase + mi * 16;
            float* r1 = oplain + (size_t)m1 * EE;
            float* r2 = oplain + (size_t)(m1 + 8) * EE;
            #pragma unroll
            for (int nt = 0; nt < 8; ++nt) {
                const int col = n0 + wn * 64 + nt * 8 + cpair;
                const float b0 = bias[col], b1v = bias[col + 1];
                float2 v1 = make_float2(c[mi][nt][0] + b0, c[mi][nt][1] + b1v);
                float2 v2 = make_float2(c[mi][nt][2] + b0, c[mi][nt][3] + b1v);
                *(float2*)(r1 + col) = v1;
                *(float2*)(r2 + col) = v2;
            }
        }
    }
}

// ---------------------------------------------------------------------------
// Tensor-core causal flash attention: 2 CTAs/SM, 2-stage KV ring.
// S = Qh.Kh; O = Ph.Vh.  Epilogue: plain fp16 ctx.
// ---------------------------------------------------------------------------
#define AP 72
#define SM_Q 0
#define QARR (128 * AP * 2)
#define SM_STAGE QARR
#define KVARR (64 * AP * 2)
#define STAGE_SZ (2 * KVARR)
#define SM_MASK (SM_STAGE + 2 * STAGE_SZ)
#define SM_TOTAL (SM_MASK + 2 * 256)

__global__ __launch_bounds__(256, 2)
void attn_mma(const __half* __restrict__ qh,
              const __half* __restrict__ kh, const __half* __restrict__ vh,
              const float* __restrict__ amask,
              __half* __restrict__ chi)
{
    extern __shared__ char sm[];
    const uint32_t sbase = smem_u32(sm);
    const int tid = threadIdx.x;
    const int w = tid >> 5, lane = tid & 31;
    const int bh = blockIdx.x;
    const int b_ = bh >> 4, h = bh & 15;
    const int qt = 15 - blockIdx.y;
    const int q0 = qt * 128;
    const int last = 2 * qt + 1;

    const int a_row = lane & 15;
    const int a_col = (lane >> 4) << 3;
    const int b_row = ((lane >> 4) << 3) + (lane & 7);
    const int b_col = ((lane >> 3) & 1) << 3;
    const int v_key = (lane & 7) + (((lane >> 3) & 1) << 3);
    const int v_d   = (lane >> 4) << 3;

    const size_t gbase = (size_t)bh * TT * DD;

    auto load_q = [&]() {
        #pragma unroll
        for (int half = 0; half < 4; ++half) {
            int loc = half * 256 + tid;
            int r = loc >> 3, seg = loc & 7;
            const __half* src = qh + gbase + (size_t)(q0 + r) * DD + seg * 8;
            uint32_t dst = sbase + SM_Q + (uint32_t)(r * AP + seg * 8) * 2;
            CP_ASYNC16(dst, src);
        }
    };
    auto load_kv = [&](int buf, int kt) {
        const int s0 = kt * 64;
        #pragma unroll
        for (int arr = 0; arr < 2; ++arr) {
            const __half* src0 = arr ? vh : kh;
            #pragma unroll
            for (int half = 0; half < 2; ++half) {
                int loc = half * 256 + tid;
                int r = loc >> 3, seg = loc & 7;
                const __half* src = src0 + gbase + (size_t)(s0 + r) * DD + seg * 8;
                uint32_t dst = sbase + SM_STAGE + buf * STAGE_SZ + arr * KVARR
                             + (uint32_t)(r * AP + seg * 8) * 2;
                CP_ASYNC16(dst, src);
            }
        }
        if (tid < 16) {
            const float* msrc = amask + (size_t)b_ * TT + s0 + tid * 4;
            uint32_t mdst = sbase + SM_MASK + buf * 256 + tid * 16;
            CP_ASYNC16(mdst, msrc);
        }
        CP_COMMIT();
    };

    load_q();
    load_kv(0, 0);
    load_kv(1, 1);
    CP_WAIT(1);
    __syncthreads();

    uint32_t qa_h[4][4];
    #pragma unroll
    for (int ks = 0; ks < 4; ++ks) {
        uint32_t off = (uint32_t)((w * 16 + a_row) * AP + ks * 16 + a_col) * 2;
        LDSM4(qa_h[ks], sbase + SM_Q + off);
    }

    float o[8][4] = {};
    float m0r = -1e30f, m1r = -1e30f, l0 = 0.f, l1 = 0.f;
    const int row0 = q0 + w * 16 + (lane >> 2);
    const int wrow_hi = q0 + w * 16 + 15;

    for (int kt = 0; kt <= last; ++kt) {
        if (kt < last) CP_WAIT(1);
        else           CP_WAIT(0);
        __syncthreads();

        const int buf = kt & 1;
        const int s0 = kt * 64;
        const bool active = (s0 <= wrow_hi);

        if (active) {
            const uint32_t kb = sbase + SM_STAGE + buf * STAGE_SZ;
            // ---- S = Qh.Kh ----
            float c[8][4] = {};
            #pragma unroll
            for (int ks = 0; ks < 4; ++ks) {
                #pragma unroll
                for (int hf = 0; hf < 2; ++hf) {
                    uint32_t kf[2][4];
                    #pragma unroll
                    for (int j = 0; j < 2; ++j) {
                        uint32_t off = (uint32_t)(((hf * 2 + j) * 16 + b_row) * AP
                                                  + ks * 16 + b_col) * 2;
                        LDSM4(kf[j], kb + off);
                    }
                    #pragma unroll
                    for (int t = 0; t < 4; ++t) {
                        const int nt = hf * 4 + t;
                        const int j = t >> 1, q = (t & 1) * 2;
                        MMA16816(c[nt], qa_h[ks], kf[j][q], kf[j][q + 1]);
                    }
                }
            }
            // ---- mask + causal ----
            const float* mk = (const float*)(sm + SM_MASK + buf * 256);
            const bool dg = (s0 + 63) > (q0 + w * 16);
            #pragma unroll
            for (int nt = 0; nt < 8; ++nt) {
                const int cl = nt * 8 + (lane & 3) * 2;
                const float mv0 = mk[cl], mv1 = mk[cl + 1];
                const float ma0 = (1.0f - mv0) * -1e30f;
                const float ma1 = (1.0f - mv1) * -1e30f;
                c[nt][0] += ma0; c[nt][1] += ma1;
                c[nt][2] += ma0; c[nt][3] += ma1;
                if (dg) {
                    const int cg = s0 + cl;
                    if (cg     > row0)     c[nt][0] = -1e30f;
                    if (cg + 1 > row0)     c[nt][1] = -1e30f;
                    if (cg     > row0 + 8) c[nt][2] = -1e30f;
                    if (cg + 1 > row0 + 8) c[nt][3] = -1e30f;
                }
            }
            // ---- online softmax ----
            float t0 = -1e30f, t1 = -1e30f;
            #pragma unroll
            for (int nt = 0; nt < 8; ++nt) {
                t0 = fmaxf(t0, fmaxf(c[nt][0], c[nt][1]));
                t1 = fmaxf(t1, fmaxf(c[nt][2], c[nt][3]));
            }
            t0 = fmaxf(t0, __shfl_xor_sync(0xffffffffu, t0, 1));
            t0 = fmaxf(t0, __shfl_xor_sync(0xffffffffu, t0, 2));
            t1 = fmaxf(t1, __shfl_xor_sync(0xffffffffu, t1, 1));
            t1 = fmaxf(t1, __shfl_xor_sync(0xffffffffu, t1, 2));
            const float mn0 = fmaxf(m0r, t0), mn1 = fmaxf(m1r, t1);
            const float cor0 = exp2fast(m0r - mn0), cor1 = exp2fast(m1r - mn1);
            m0r = mn0; m1r = mn1;
            l0 *= cor0; l1 *= cor1;
            #pragma unroll
            for (int nt = 0; nt < 8; ++nt) {
                o[nt][0] *= cor0; o[nt][1] *= cor0;
                o[nt][2] *= cor1; o[nt][3] *= cor1;
            }
            // ---- P = exp2(S - m), O += Ph.Vh ----
            float s0sum = 0.f, s1sum = 0.f;
            #pragma unroll
            for (int ks = 0; ks < 4; ++ks) {
                uint32_t pa[4];
                #pragma unroll
                for (int t = 0; t < 2; ++t) {
                    const int nt = ks * 2 + t;
                    const float p0 = exp2fast(c[nt][0] - mn0);
                    const float p1 = exp2fast(c[nt][1] - mn0);
                    const float p2 = exp2fast(c[nt][2] - mn1);
                    const float p3 = exp2fast(c[nt][3] - mn1);
                    s0sum += p0 + p1; s1sum += p2 + p3;
                    pa[t * 2]     = pack_h2(p0, p1);
                    pa[t * 2 + 1] = pack_h2(p2, p3);
                }
                #pragma unroll
                for (int hf = 0; hf < 2; ++hf) {
                    uint32_t vf[2][4];
                    #pragma unroll
                    for (int j = 0; j < 2; ++j) {
                        uint32_t off = (uint32_t)((ks * 16 + v_key) * AP
                                                  + (hf * 2 + j) * 16 + v_d) * 2;
                        LDSM4T(vf[j], kb + KVARR + off);
                    }
                    #pragma unroll
                    for (int t = 0; t < 4; ++t) {
                        const int nt = hf * 4 + t;
                        const int j = t >> 1, q = (t & 1) * 2;
                        MMA16816(o[nt], pa, vf[j][q], vf[j][q + 1]);
                    }
                }
            }
            s0sum += __shfl_xor_sync(0xffffffffu, s0sum, 1);
            s0sum += __shfl_xor_sync(0xffffffffu, s0sum, 2);
            s1sum += __shfl_xor_sync(0xffffffffu, s1sum, 1);
            s1sum += __shfl_xor_sync(0xffffffffu, s1sum, 2);
            l0 += s0sum; l1 += s1sum;
        }
        __syncthreads();
        if (kt + 2 <= last) load_kv(buf, kt + 2);
    }

    // ---- normalize + store fp16 ctx [B,T,E] ----
    const float inv0 = 1.0f / l0, inv1 = 1.0f / l1;
    const int cpair = (lane & 3) * 2;
    const size_t r1 = ((size_t)b_ * TT + row0) * EE + h * 64;
    const size_t r2 = ((size_t)b_ * TT + row0 + 8) * EE + h * 64;
    #pragma unroll
    for (int nt = 0; nt < 8; ++nt) {
        const int d = nt * 8 + cpair;
        *(uint32_t*)(chi + r1 + d) = pack_h2(o[nt][0] * inv0, o[nt][1] * inv0);
        *(uint32_t*)(chi + r2 + d) = pack_h2(o[nt][2] * inv1, o[nt][3] * inv1);
    }
}

// ---------------------------------------------------------------------------
// Launch
// ---------------------------------------------------------------------------
extern "C" void kernel_launch(void* const* d_in, const int* in_sizes, int n_in,
                              void* d_out, int out_size)
{
    const float* x     = (const float*)d_in[0];
    const float* amask = (const float*)d_in[1];
    const float* Wq    = (const float*)d_in[2];
    const float* Wk    = (const float*)d_in[3];
    const float* Wv    = (const float*)d_in[4];
    const float* Wo    = (const float*)d_in[5];
    const float* bo    = (const float*)d_in[6];
    float* out = (float*)d_out;

    __half *xhi, *wth, *woh, *chi;
    __half *qh, *kh, *vh;
    cudaGetSymbolAddress((void**)&xhi, g_xhi);
    cudaGetSymbolAddress((void**)&wth, g_wth);
    cudaGetSymbolAddress((void**)&woh, g_woh);
    cudaGetSymbolAddress((void**)&chi, g_chi);
    cudaGetSymbolAddress((void**)&qh,  g_qh);
    cudaGetSymbolAddress((void**)&kh,  g_kh);
    cudaGetSymbolAddress((void**)&vh,  g_vh);

    cudaFuncSetAttribute(mma_gemm<0>, cudaFuncAttributeMaxDynamicSharedMemorySize,
                         NSTAGE * STAGE_BYTES);
    cudaFuncSetAttribute(mma_gemm<1>, cudaFuncAttributeMaxDynamicSharedMemorySize,
                         NSTAGE * STAGE_BYTES);
    cudaFuncSetAttribute(attn_mma, cudaFuncAttributeMaxDynamicSharedMemorySize,
                         SM_TOTAL);

    conv_h<<<(BT * EE / 4) / 256, 256>>>(x, xhi, BT * EE / 4);
    prep_wt<<<768, 256>>>(Wq, Wk, Wv, wth);
    conv_h<<<(EE * EE / 4) / 256, 256>>>(Wo, woh, EE * EE / 4);

    {   // QKV projection (1-pass)
        dim3 grid(NQKV / 128, BT / 128);
        mma_gemm<0><<<grid, 256, NSTAGE * STAGE_BYTES>>>(xhi, wth, nullptr,
                                                         qh, kh, vh, nullptr);
    }
    {   // attention (1-pass) -> fp16 ctx
        dim3 grid(BB * HH, TT / 128);
        attn_mma<<<grid, 256, SM_TOTAL>>>(qh, kh, vh, amask, chi);
    }
    {   // output projection (1-pass) + bias
        dim3 grid(EE / 128, BT / 128);
        mma_gemm<1><<<grid, 256, NSTAGE * STAGE_BYTES>>>(chi, woh, bo,
                                                         nullptr, nullptr, nullptr,
                                                         out);
    }
}

// round 16
// speedup vs baseline: 2.4903x; 1.0314x over previous
#include <cuda_runtime.h>
#include <cuda_fp16.h>
#include <math_constants.h>
#include <cstdint>

// Problem constants
#define BB 4
#define TT 2048
#define EE 1024
#define HH 16
#define DD 64
#define BT (BB*TT)          // 8192
#define NQKV 3072

#define L2E 1.44269504f
#define SCALE_Q (0.125f * L2E)    // fold 1/sqrt(D) and log2(e) into q

// ---------------------------------------------------------------------------
// Scratch (allocation-free rule: __device__ globals)
// ---------------------------------------------------------------------------
__device__ __align__(16) __half g_xhi[(size_t)BT*EE];
__device__ __align__(16) __half g_wth[(size_t)NQKV*EE];
__device__ __align__(16) __half g_woh[(size_t)EE*EE];
__device__ __align__(16) __half g_chi[(size_t)BT*EE];     // attn out (fp16)

// fp16 q/k/v in [B,H,T,D]
__device__ __align__(16) __half g_qh[(size_t)BB*HH*TT*DD];
__device__ __align__(16) __half g_kh[(size_t)BB*HH*TT*DD];
__device__ __align__(16) __half g_vh[(size_t)BB*HH*TT*DD];

// ---------------------------------------------------------------------------
// Helpers (base sm_103 ISA: mma.sync / ldmatrix / cp.async)
// ---------------------------------------------------------------------------
__device__ __forceinline__ uint32_t smem_u32(const void* p) {
    uint32_t a;
    asm("{ .reg .u64 t; cvta.to.shared.u64 t, %1; cvt.u32.u64 %0, t; }"
        : "=r"(a) : "l"(p));
    return a;
}

#define LDSM4(r, addr) \
    asm volatile("ldmatrix.sync.aligned.m8n8.x4.shared.b16 {%0,%1,%2,%3}, [%4];" \
        : "=r"((r)[0]), "=r"((r)[1]), "=r"((r)[2]), "=r"((r)[3]) : "r"(addr))

#define LDSM4T(r, addr) \
    asm volatile("ldmatrix.sync.aligned.m8n8.x4.trans.shared.b16 {%0,%1,%2,%3}, [%4];" \
        : "=r"((r)[0]), "=r"((r)[1]), "=r"((r)[2]), "=r"((r)[3]) : "r"(addr))

#define MMA16816(c, a, b0, b1) \
    asm volatile("mma.sync.aligned.m16n8k16.row.col.f32.f16.f16.f32 " \
        "{%0,%1,%2,%3}, {%4,%5,%6,%7}, {%8,%9}, {%0,%1,%2,%3};" \
        : "+f"((c)[0]), "+f"((c)[1]), "+f"((c)[2]), "+f"((c)[3]) \
        : "r"((a)[0]), "r"((a)[1]), "r"((a)[2]), "r"((a)[3]), "r"(b0), "r"(b1))

#define CP_ASYNC16(dst, src) \
    asm volatile("cp.async.cg.shared.global [%0], [%1], 16;" :: "r"(dst), "l"(src))
#define CP_COMMIT() asm volatile("cp.async.commit_group;" ::: "memory")
#define CP_WAIT(n)  asm volatile("cp.async.wait_group %0;" :: "n"(n) : "memory")

__device__ __forceinline__ uint32_t pack_h2(float a, float b) {
    __half2 H = __halves2half2(__float2half_rn(a), __float2half_rn(b));
    return *(uint32_t*)&H;
}

// fast exp2 on the FMA pipe (degree-7, rel err ~1e-6)
__device__ __forceinline__ float exp2fast(float x) {
    x = fmaxf(x, -125.0f);
    int n = __float2int_rd(x);
    float f = x - (float)n;
    float p = 1.3570247e-5f;
    p = fmaf(p, f, 1.5353362e-4f);
    p = fmaf(p, f, 1.3398874e-3f);
    p = fmaf(p, f, 9.6184374e-3f);
    p = fmaf(p, f, 5.5503325e-2f);
    p = fmaf(p, f, 2.4022648e-1f);
    p = fmaf(p, f, 6.9314720e-1f);
    p = fmaf(p, f, 1.0f);
    return p * __int_as_float((n + 127) << 23);
}

// ---------------------------------------------------------------------------
// Prep: fp32 -> fp16
// ---------------------------------------------------------------------------
__global__ __launch_bounds__(256) void conv_h(
    const float* __restrict__ s, __half* __restrict__ hi, int n4)
{
    int i = blockIdx.x * 256 + threadIdx.x;
    if (i >= n4) return;
    float4 v = ((const float4*)s)[i];
    ((uint32_t*)hi)[i * 2 + 0] = pack_h2(v.x, v.y);
    ((uint32_t*)hi)[i * 2 + 1] = pack_h2(v.z, v.w);
}

// ---------------------------------------------------------------------------
// Prep: transpose qkv weights. W[h][e][d] -> Wt[n][e]
// ---------------------------------------------------------------------------
__global__ __launch_bounds__(256) void prep_wt(
    const float* __restrict__ Wq, const float* __restrict__ Wk,
    const float* __restrict__ Wv, __half* __restrict__ th)
{
    __shared__ float ts[64][65];
    const int bx = blockIdx.x;
    const int mi = bx >> 8;
    const int rem = bx & 255;
    const int h = rem >> 4;
    const int e0 = (rem & 15) * 64;
    const float* src = (mi == 0 ? Wq : (mi == 1 ? Wk : Wv)) + (size_t)h * EE * DD;
    const int tid = threadIdx.x;

    #pragma unroll
    for (int i = 0; i < 4; ++i) {
        int idx = tid + i * 256;
        int ei = idx >> 4, d4 = idx & 15;
        float4 v = ((const float4*)(src + (size_t)(e0 + ei) * DD))[d4];
        ts[ei][d4 * 4 + 0] = v.x; ts[ei][d4 * 4 + 1] = v.y;
        ts[ei][d4 * 4 + 2] = v.z; ts[ei][d4 * 4 + 3] = v.w;
    }
    __syncthreads();

    const int d = tid >> 2, seg = tid & 3;
    const size_t row = ((size_t)mi * 1024 + h * 64 + d) * EE + e0 + seg * 16;
    alignas(16) __half hb[16];
    #pragma unroll
    for (int i = 0; i < 16; ++i)
        hb[i] = __float2half_rn(ts[seg * 16 + i][d]);
    *(uint4*)(th + row)     = *(const uint4*)(hb);
    *(uint4*)(th + row + 8) = *(const uint4*)(hb + 8);
}

// ---------------------------------------------------------------------------
// HMMA fp16 GEMM (1-pass), 128Mx128N block, warp 32x64, 2 CTAs/SM.
// K-chunk 64 (16 chunks -> half the barriers), 3-stage ring, single barrier
// per chunk with loads issued before compute.
// MODE 0 (qkv): -> fp16 q/k/v (SCALE_Q folded into q)
// MODE 1 (out): -> fp32 + bias
// ---------------------------------------------------------------------------
#define GP 72                              // chunk pitch (fp16 elems), conflict-free
#define G_ELEMS (128 * GP)                 // 9216 per array
#define STAGE_BYTES (2 * G_ELEMS * 2)      // A + B = 36864
#define NSTAGE 3

template <int MODE>
__global__ __launch_bounds__(256, 2)
void mma_gemm(const __half* __restrict__ Ah, const __half* __restrict__ Bh,
              const float* __restrict__ bias,
              __half* __restrict__ qh, __half* __restrict__ kh,
              __half* __restrict__ vh,
              float* __restrict__ oplain)
{
    extern __shared__ char sm[];
    const uint32_t sbase = smem_u32(sm);
    const int tid = threadIdx.x;
    const int wid = tid >> 5, lane = tid & 31;
    const int wm = wid & 3, wn = wid >> 2;       // 4 M-warps x 2 N-warps
    const int n0 = blockIdx.x * 128;
    const int m0 = blockIdx.y * 128;

    const int a_row = lane & 15;
    const int a_col = (lane >> 4) << 3;
    const int b_row = ((lane >> 4) << 3) + (lane & 7);
    const int b_col = ((lane >> 3) & 1) << 3;

    float c[2][8][4] = {};    // warp tile 32x64

    // loader: 128 rows x 8 granules(16B) per array; 4 granules/thread/array
    const int lrow = tid >> 3, lseg = tid & 7;   // covers rows 0..31 per quarter
    const __half* pA0 = Ah + (size_t)(m0 + lrow) * EE + lseg * 8;
    const __half* pB0 = Bh + (size_t)(n0 + lrow) * EE + lseg * 8;
    const uint32_t doff = (uint32_t)(lrow * GP + lseg * 8) * 2;

    auto stage_load = [&](uint32_t bufbase) {
        const uint32_t d0 = bufbase + doff;
        #pragma unroll
        for (int i = 0; i < 4; ++i) {
            CP_ASYNC16(d0 + (uint32_t)(i * 32 * GP) * 2, pA0 + (size_t)(i * 32) * EE);
        }
        const uint32_t b0 = d0 + G_ELEMS * 2;
        #pragma unroll
        for (int i = 0; i < 4; ++i) {
            CP_ASYNC16(b0 + (uint32_t)(i * 32 * GP) * 2, pB0 + (size_t)(i * 32) * EE);
        }
        CP_COMMIT();
        pA0 += 64; pB0 += 64;
    };

    stage_load(sbase);
    stage_load(sbase + STAGE_BYTES);

    for (int ch = 0; ch < 16; ++ch) {
        if (ch < 15) CP_WAIT(1);
        else         CP_WAIT(0);
        __syncthreads();
        if (ch + 2 < 16) stage_load(sbase + ((ch + 2) % NSTAGE) * STAGE_BYTES);

        const uint32_t sb  = sbase + (ch % NSTAGE) * STAGE_BYTES;
        const uint32_t sAh = sb;
        const uint32_t sBh = sb + G_ELEMS * 2;

        #pragma unroll
        for (int ks = 0; ks < 4; ++ks) {
            uint32_t ah[2][4];
            #pragma unroll
            for (int mi = 0; mi < 2; ++mi) {
                uint32_t off = (uint32_t)((wm * 32 + mi * 16 + a_row) * GP
                                          + ks * 16 + a_col) * 2;
                LDSM4(ah[mi], sAh + off);
            }
            #pragma unroll
            for (int jp = 0; jp < 4; ++jp) {
                uint32_t bb[4];
                uint32_t off = (uint32_t)((wn * 64 + jp * 16 + b_row) * GP
                                          + ks * 16 + b_col) * 2;
                LDSM4(bb, sBh + off);
                #pragma unroll
                for (int mi = 0; mi < 2; ++mi)
                    #pragma unroll
                    for (int t = 0; t < 2; ++t)
                        MMA16816(c[mi][jp * 2 + t], ah[mi], bb[t * 2], bb[t * 2 + 1]);
            }
        }
    }

    const int rbase = m0 + wm * 32 + (lane >> 2);
    const int cpair = (lane & 3) * 2;

    if (MODE == 0) {
        const int which = n0 >> 10;
        __half* dst = (which == 0) ? qh : (which == 1) ? kh : vh;
        const float sc = (which == 0) ? SCALE_Q : 1.0f;
        const int h = ((n0 & 1023) >> 6) + wn;
        #pragma unroll
        for (int mi = 0; mi < 2; ++mi) {
            const int m1 = rbase + mi * 16;
            const int m2 = m1 + 8;
            const size_t base1 = (((size_t)(m1 >> 11) * HH + h) * TT + (m1 & 2047)) * DD;
            const size_t base2 = (((size_t)(m2 >> 11) * HH + h) * TT + (m2 & 2047)) * DD;
            #pragma unroll
            for (int nt = 0; nt < 8; ++nt) {
                const int d = nt * 8 + cpair;
                *(uint32_t*)(dst + base1 + d) = pack_h2(c[mi][nt][0] * sc, c[mi][nt][1] * sc);
                *(uint32_t*)(dst + base2 + d) = pack_h2(c[mi][nt][2] * sc, c[mi][nt][3] * sc);
            }
        }
    } else {
        #pragma unroll
        for (int mi = 0; mi < 2; ++mi) {
            const int m1 = rbase + mi * 16;
            float* r1 = oplain + (size_t)m1 * EE;
            float* r2 = oplain + (size_t)(m1 + 8) * EE;
            #pragma unroll
            for (int nt = 0; nt < 8; ++nt) {
                const int col = n0 + wn * 64 + nt * 8 + cpair;
                const float b0 = bias[col], b1v = bias[col + 1];
                float2 v1 = make_float2(c[mi][nt][0] + b0, c[mi][nt][1] + b1v);
                float2 v2 = make_float2(c[mi][nt][2] + b0, c[mi][nt][3] + b1v);
                *(float2*)(r1 + col) = v1;
                *(float2*)(r2 + col) = v2;
            }
        }
    }
}

// ---------------------------------------------------------------------------
// Tensor-core causal flash attention: 2 CTAs/SM, 3-stage KV ring,
// single barrier per tile (loads issued before compute).
// S = Qh.Kh; O = Ph.Vh.  Epilogue: plain fp16 ctx.
// ---------------------------------------------------------------------------
#define AP 72
#define SM_Q 0
#define QARR (128 * AP * 2)
#define SM_STAGE QARR
#define KVARR (64 * AP * 2)
#define STAGE_SZ (2 * KVARR)
#define SM_MASK (SM_STAGE + 3 * STAGE_SZ)
#define SM_TOTAL (SM_MASK + 3 * 256)

__global__ __launch_bounds__(256, 2)
void attn_mma(const __half* __restrict__ qh,
              const __half* __restrict__ kh, const __half* __restrict__ vh,
              const float* __restrict__ amask,
              __half* __restrict__ chi)
{
    extern __shared__ char sm[];
    const uint32_t sbase = smem_u32(sm);
    const int tid = threadIdx.x;
    const int w = tid >> 5, lane = tid & 31;
    const int bh = blockIdx.x;
    const int b_ = bh >> 4, h = bh & 15;
    const int qt = 15 - blockIdx.y;
    const int q0 = qt * 128;
    const int last = 2 * qt + 1;

    const int a_row = lane & 15;
    const int a_col = (lane >> 4) << 3;
    const int b_row = ((lane >> 4) << 3) + (lane & 7);
    const int b_col = ((lane >> 3) & 1) << 3;
    const int v_key = (lane & 7) + (((lane >> 3) & 1) << 3);
    const int v_d   = (lane >> 4) << 3;

    const size_t gbase = (size_t)bh * TT * DD;

    auto load_q = [&]() {
        #pragma unroll
        for (int half = 0; half < 4; ++half) {
            int loc = half * 256 + tid;
            int r = loc >> 3, seg = loc & 7;
            const __half* src = qh + gbase + (size_t)(q0 + r) * DD + seg * 8;
            uint32_t dst = sbase + SM_Q + (uint32_t)(r * AP + seg * 8) * 2;
            CP_ASYNC16(dst, src);
        }
    };
    auto load_kv = [&](int buf, int kt) {
        const int s0 = kt * 64;
        #pragma unroll
        for (int arr = 0; arr < 2; ++arr) {
            const __half* src0 = arr ? vh : kh;
            #pragma unroll
            for (int half = 0; half < 2; ++half) {
                int loc = half * 256 + tid;
                int r = loc >> 3, seg = loc & 7;
                const __half* src = src0 + gbase + (size_t)(s0 + r) * DD + seg * 8;
                uint32_t dst = sbase + SM_STAGE + buf * STAGE_SZ + arr * KVARR
                             + (uint32_t)(r * AP + seg * 8) * 2;
                CP_ASYNC16(dst, src);
            }
        }
        if (tid < 16) {
            const float* msrc = amask + (size_t)b_ * TT + s0 + tid * 4;
            uint32_t mdst = sbase + SM_MASK + buf * 256 + tid * 16;
            CP_ASYNC16(mdst, msrc);
        }
        CP_COMMIT();
    };

    load_q();
    load_kv(0, 0);      // group 0 includes Q
    load_kv(1, 1);
    CP_WAIT(1);
    __syncthreads();

    uint32_t qa_h[4][4];
    #pragma unroll
    for (int ks = 0; ks < 4; ++ks) {
        uint32_t off = (uint32_t)((w * 16 + a_row) * AP + ks * 16 + a_col) * 2;
        LDSM4(qa_h[ks], sbase + SM_Q + off);
    }

    float o[8][4] = {};
    float m0r = -1e30f, m1r = -1e30f, l0 = 0.f, l1 = 0.f;
    const int row0 = q0 + w * 16 + (lane >> 2);
    const int wrow_hi = q0 + w * 16 + 15;

    for (int kt = 0; kt <= last; ++kt) {
        if (kt > 0) {
            if (kt < last) CP_WAIT(1);
            else           CP_WAIT(0);
            __syncthreads();
        }
        // issue loads for kt+2 (buffer (kt+2)%3 last read at kt-1)
        if (kt + 2 <= last) load_kv((kt + 2) % 3, kt + 2);

        const int buf = kt % 3;
        const int s0 = kt * 64;
        const bool active = (s0 <= wrow_hi);

        if (active) {
            const uint32_t kb = sbase + SM_STAGE + buf * STAGE_SZ;
            // ---- S = Qh.Kh ----
            float c[8][4] = {};
            #pragma unroll
            for (int ks = 0; ks < 4; ++ks) {
                #pragma unroll
                for (int hf = 0; hf < 2; ++hf) {
                    uint32_t kf[2][4];
                    #pragma unroll
                    for (int j = 0; j < 2; ++j) {
                        uint32_t off = (uint32_t)(((hf * 2 + j) * 16 + b_row) * AP
                                                  + ks * 16 + b_col) * 2;
                        LDSM4(kf[j], kb + off);
                    }
                    #pragma unroll
                    for (int t = 0; t < 4; ++t) {
                        const int nt = hf * 4 + t;
                        const int j = t >> 1, q = (t & 1) * 2;
                        MMA16816(c[nt], qa_h[ks], kf[j][q], kf[j][q + 1]);
                    }
                }
            }
            // ---- mask + causal ----
            const float* mk = (const float*)(sm + SM_MASK + buf * 256);
            const bool dg = (s0 + 63) > (q0 + w * 16);
            #pragma unroll
            for (int nt = 0; nt < 8; ++nt) {
                const int cl = nt * 8 + (lane & 3) * 2;
                const float mv0 = mk[cl], mv1 = mk[cl + 1];
                const float ma0 = (1.0f - mv0) * -1e30f;
                const float ma1 = (1.0f - mv1) * -1e30f;
                c[nt][0] += ma0; c[nt][1] += ma1;
                c[nt][2] += ma0; c[nt][3] += ma1;
                if (dg) {
                    const int cg = s0 + cl;
                    if (cg     > row0)     c[nt][0] = -1e30f;
                    if (cg + 1 > row0)     c[nt][1] = -1e30f;
                    if (cg     > row0 + 8) c[nt][2] = -1e30f;
                    if (cg + 1 > row0 + 8) c[nt][3] = -1e30f;
                }
            }
            // ---- online softmax ----
            float t0 = -1e30f, t1 = -1e30f;
            #pragma unroll
            for (int nt = 0; nt < 8; ++nt) {
                t0 = fmaxf(t0, fmaxf(c[nt][0], c[nt][1]));
                t1 = fmaxf(t1, fmaxf(c[nt][2], c[nt][3]));
            }
            t0 = fmaxf(t0, __shfl_xor_sync(0xffffffffu, t0, 1));
            t0 = fmaxf(t0, __shfl_xor_sync(0xffffffffu, t0, 2));
            t1 = fmaxf(t1, __shfl_xor_sync(0xffffffffu, t1, 1));
            t1 = fmaxf(t1, __shfl_xor_sync(0xffffffffu, t1, 2));
            const float mn0 = fmaxf(m0r, t0), mn1 = fmaxf(m1r, t1);
            const float cor0 = exp2fast(m0r - mn0), cor1 = exp2fast(m1r - mn1);
            m0r = mn0; m1r = mn1;
            l0 *= cor0; l1 *= cor1;
            #pragma unroll
            for (int nt = 0; nt < 8; ++nt) {
                o[nt][0] *= cor0; o[nt][1] *= cor0;
                o[nt][2] *= cor1; o[nt][3] *= cor1;
            }
            // ---- P = exp2(S - m), O += Ph.Vh ----
            float s0sum = 0.f, s1sum = 0.f;
            #pragma unroll
            for (int ks = 0; ks < 4; ++ks) {
                uint32_t pa[4];
                #pragma unroll
                for (int t = 0; t < 2; ++t) {
                    const int nt = ks * 2 + t;
                    const float p0 = exp2fast(c[nt][0] - mn0);
                    const float p1 = exp2fast(c[nt][1] - mn0);
                    const float p2 = exp2fast(c[nt][2] - mn1);
                    const float p3 = exp2fast(c[nt][3] - mn1);
                    s0sum += p0 + p1; s1sum += p2 + p3;
                    pa[t * 2]     = pack_h2(p0, p1);
                    pa[t * 2 + 1] = pack_h2(p2, p3);
                }
                #pragma unroll
                for (int hf = 0; hf < 2; ++hf) {
                    uint32_t vf[2][4];
                    #pragma unroll
                    for (int j = 0; j < 2; ++j) {
                        uint32_t off = (uint32_t)((ks * 16 + v_key) * AP
                                                  + (hf * 2 + j) * 16 + v_d) * 2;
                        LDSM4T(vf[j], kb + KVARR + off);
                    }
                    #pragma unroll
                    for (int t = 0; t < 4; ++t) {
                        const int nt = hf * 4 + t;
                        const int j = t >> 1, q = (t & 1) * 2;
                        MMA16816(o[nt], pa, vf[j][q], vf[j][q + 1]);
                    }
                }
            }
            s0sum += __shfl_xor_sync(0xffffffffu, s0sum, 1);
            s0sum += __shfl_xor_sync(0xffffffffu, s0sum, 2);
            s1sum += __shfl_xor_sync(0xffffffffu, s1sum, 1);
            s1sum += __shfl_xor_sync(0xffffffffu, s1sum, 2);
            l0 += s0sum; l1 += s1sum;
        }
    }

    // ---- normalize + store fp16 ctx [B,T,E] ----
    const float inv0 = 1.0f / l0, inv1 = 1.0f / l1;
    const int cpair = (lane & 3) * 2;
    const size_t r1 = ((size_t)b_ * TT + row0) * EE + h * 64;
    const size_t r2 = ((size_t)b_ * TT + row0 + 8) * EE + h * 64;
    #pragma unroll
    for (int nt = 0; nt < 8; ++nt) {
        const int d = nt * 8 + cpair;
        *(uint32_t*)(chi + r1 + d) = pack_h2(o[nt][0] * inv0, o[nt][1] * inv0);
        *(uint32_t*)(chi + r2 + d) = pack_h2(o[nt][2] * inv1, o[nt][3] * inv1);
    }
}

// ---------------------------------------------------------------------------
// Launch
// ---------------------------------------------------------------------------
extern "C" void kernel_launch(void* const* d_in, const int* in_sizes, int n_in,
                              void* d_out, int out_size)
{
    const float* x     = (const float*)d_in[0];
    const float* amask = (const float*)d_in[1];
    const float* Wq    = (const float*)d_in[2];
    const float* Wk    = (const float*)d_in[3];
    const float* Wv    = (const float*)d_in[4];
    const float* Wo    = (const float*)d_in[5];
    const float* bo    = (const float*)d_in[6];
    float* out = (float*)d_out;

    __half *xhi, *wth, *woh, *chi;
    __half *qh, *kh, *vh;
    cudaGetSymbolAddress((void**)&xhi, g_xhi);
    cudaGetSymbolAddress((void**)&wth, g_wth);
    cudaGetSymbolAddress((void**)&woh, g_woh);
    cudaGetSymbolAddress((void**)&chi, g_chi);
    cudaGetSymbolAddress((void**)&qh,  g_qh);
    cudaGetSymbolAddress((void**)&kh,  g_kh);
    cudaGetSymbolAddress((void**)&vh,  g_vh);

    cudaFuncSetAttribute(mma_gemm<0>, cudaFuncAttributeMaxDynamicSharedMemorySize,
                         NSTAGE * STAGE_BYTES);
    cudaFuncSetAttribute(mma_gemm<1>, cudaFuncAttributeMaxDynamicSharedMemorySize,
                         NSTAGE * STAGE_BYTES);
    cudaFuncSetAttribute(attn_mma, cudaFuncAttributeMaxDynamicSharedMemorySize,
                         SM_TOTAL);

    conv_h<<<(BT * EE / 4) / 256, 256>>>(x, xhi, BT * EE / 4);
    prep_wt<<<768, 256>>>(Wq, Wk, Wv, wth);
    conv_h<<<(EE * EE / 4) / 256, 256>>>(Wo, woh, EE * EE / 4);

    {   // QKV projection (1-pass)
        dim3 grid(NQKV / 128, BT / 128);
        mma_gemm<0><<<grid, 256, NSTAGE * STAGE_BYTES>>>(xhi, wth, nullptr,
                                                         qh, kh, vh, nullptr);
    }
    {   // attention (1-pass) -> fp16 ctx
        dim3 grid(BB * HH, TT / 128);
        attn_mma<<<grid, 256, SM_TOTAL>>>(qh, kh, vh, amask, chi);
    }
    {   // output projection (1-pass) + bias
        dim3 grid(EE / 128, BT / 128);
        mma_gemm<1><<<grid, 256, NSTAGE * STAGE_BYTES>>>(chi, woh, bo,
                                                         nullptr, nullptr, nullptr,
                                                         out);
    }
}

// round 17
// speedup vs baseline: 2.5291x; 1.0155x over previous
#include <cuda_runtime.h>
#include <cuda_fp16.h>
#include <math_constants.h>
#include <cstdint>

// Problem constants
#define BB 4
#define TT 2048
#define EE 1024
#define HH 16
#define DD 64
#define BT (BB*TT)          // 8192
#define NQKV 3072

#define L2E 1.44269504f
#define SCALE_Q (0.125f * L2E)    // fold 1/sqrt(D) and log2(e) into q

// ---------------------------------------------------------------------------
// Scratch (allocation-free rule: __device__ globals)
// ---------------------------------------------------------------------------
__device__ __align__(16) __half g_xhi[(size_t)BT*EE];
__device__ __align__(16) __half g_wth[(size_t)NQKV*EE];
__device__ __align__(16) __half g_woh[(size_t)EE*EE];
__device__ __align__(16) __half g_chi[(size_t)BT*EE];     // attn out (fp16)

// fp16 q/k/v in [B,H,T,D]
__device__ __align__(16) __half g_qh[(size_t)BB*HH*TT*DD];
__device__ __align__(16) __half g_kh[(size_t)BB*HH*TT*DD];
__device__ __align__(16) __half g_vh[(size_t)BB*HH*TT*DD];

// ---------------------------------------------------------------------------
// Helpers (base sm_103 ISA: mma.sync / ldmatrix / cp.async)
// ---------------------------------------------------------------------------
__device__ __forceinline__ uint32_t smem_u32(const void* p) {
    uint32_t a;
    asm("{ .reg .u64 t; cvta.to.shared.u64 t, %1; cvt.u32.u64 %0, t; }"
        : "=r"(a) : "l"(p));
    return a;
}

#define LDSM4(r, addr) \
    asm volatile("ldmatrix.sync.aligned.m8n8.x4.shared.b16 {%0,%1,%2,%3}, [%4];" \
        : "=r"((r)[0]), "=r"((r)[1]), "=r"((r)[2]), "=r"((r)[3]) : "r"(addr))

#define LDSM4T(r, addr) \
    asm volatile("ldmatrix.sync.aligned.m8n8.x4.trans.shared.b16 {%0,%1,%2,%3}, [%4];" \
        : "=r"((r)[0]), "=r"((r)[1]), "=r"((r)[2]), "=r"((r)[3]) : "r"(addr))

#define MMA16816(c, a, b0, b1) \
    asm volatile("mma.sync.aligned.m16n8k16.row.col.f32.f16.f16.f32 " \
        "{%0,%1,%2,%3}, {%4,%5,%6,%7}, {%8,%9}, {%0,%1,%2,%3};" \
        : "+f"((c)[0]), "+f"((c)[1]), "+f"((c)[2]), "+f"((c)[3]) \
        : "r"((a)[0]), "r"((a)[1]), "r"((a)[2]), "r"((a)[3]), "r"(b0), "r"(b1))

#define CP_ASYNC16(dst, src) \
    asm volatile("cp.async.cg.shared.global [%0], [%1], 16;" :: "r"(dst), "l"(src))
#define CP_COMMIT() asm volatile("cp.async.commit_group;" ::: "memory")
#define CP_WAIT(n)  asm volatile("cp.async.wait_group %0;" :: "n"(n) : "memory")

__device__ __forceinline__ uint32_t pack_h2(float a, float b) {
    __half2 H = __halves2half2(__float2half_rn(a), __float2half_rn(b));
    return *(uint32_t*)&H;
}

// fast exp2 on the FMA pipe (degree-7, rel err ~1e-6)
__device__ __forceinline__ float exp2fast(float x) {
    x = fmaxf(x, -125.0f);
    int n = __float2int_rd(x);
    float f = x - (float)n;
    float p = 1.3570247e-5f;
    p = fmaf(p, f, 1.5353362e-4f);
    p = fmaf(p, f, 1.3398874e-3f);
    p = fmaf(p, f, 9.6184374e-3f);
    p = fmaf(p, f, 5.5503325e-2f);
    p = fmaf(p, f, 2.4022648e-1f);
    p = fmaf(p, f, 6.9314720e-1f);
    p = fmaf(p, f, 1.0f);
    return p * __int_as_float((n + 127) << 23);
}

// ---------------------------------------------------------------------------
// Merged prep: one launch.
//   blocks [0, 8192)         : x fp32 -> fp16
//   blocks [8192, 9216)      : Wo fp32 -> fp16
//   blocks [9216, 9984)      : qkv weight transpose W[h][e][d] -> Wt[n][e]
// ---------------------------------------------------------------------------
#define XBLK 8192
#define WOBLK 1024
#define PREP_GRID (XBLK + WOBLK + 768)

__global__ __launch_bounds__(256) void prep_all(
    const float* __restrict__ x,
    const float* __restrict__ Wq, const float* __restrict__ Wk,
    const float* __restrict__ Wv, const float* __restrict__ Wo,
    __half* __restrict__ xhi, __half* __restrict__ woh,
    __half* __restrict__ th)
{
    __shared__ float ts[64][65];
    const int b = blockIdx.x;
    const int tid = threadIdx.x;

    if (b < XBLK + WOBLK) {
        const float* s = (b < XBLK) ? x : Wo;
        __half* d = (b < XBLK) ? xhi : woh;
        const int i = ((b < XBLK) ? b : (b - XBLK)) * 256 + tid;
        float4 v = ((const float4*)s)[i];
        ((uint32_t*)d)[i * 2 + 0] = pack_h2(v.x, v.y);
        ((uint32_t*)d)[i * 2 + 1] = pack_h2(v.z, v.w);
        return;
    }

    const int bx = b - XBLK - WOBLK;
    const int mi = bx >> 8;
    const int rem = bx & 255;
    const int h = rem >> 4;
    const int e0 = (rem & 15) * 64;
    const float* src = (mi == 0 ? Wq : (mi == 1 ? Wk : Wv)) + (size_t)h * EE * DD;

    #pragma unroll
    for (int i = 0; i < 4; ++i) {
        int idx = tid + i * 256;
        int ei = idx >> 4, d4 = idx & 15;
        float4 v = ((const float4*)(src + (size_t)(e0 + ei) * DD))[d4];
        ts[ei][d4 * 4 + 0] = v.x; ts[ei][d4 * 4 + 1] = v.y;
        ts[ei][d4 * 4 + 2] = v.z; ts[ei][d4 * 4 + 3] = v.w;
    }
    __syncthreads();

    const int d = tid >> 2, seg = tid & 3;
    const size_t row = ((size_t)mi * 1024 + h * 64 + d) * EE + e0 + seg * 16;
    alignas(16) __half hb[16];
    #pragma unroll
    for (int i = 0; i < 16; ++i)
        hb[i] = __float2half_rn(ts[seg * 16 + i][d]);
    *(uint4*)(th + row)     = *(const uint4*)(hb);
    *(uint4*)(th + row + 8) = *(const uint4*)(hb + 8);
}

// ---------------------------------------------------------------------------
// HMMA fp16 GEMM (1-pass), 128Mx128N block, warp 32x64, 2 CTAs/SM.
// K-chunk 64 (16 chunks), 3-stage ring, single barrier per chunk,
// loads issued before compute.
// MODE 0 (qkv): -> fp16 q/k/v (SCALE_Q folded into q)
// MODE 1 (out): -> fp32 + bias
// ---------------------------------------------------------------------------
#define GP 72
#define G_ELEMS (128 * GP)                 // 9216 per array
#define STAGE_BYTES (2 * G_ELEMS * 2)      // A + B = 36864
#define NSTAGE 3

template <int MODE>
__global__ __launch_bounds__(256, 2)
void mma_gemm(const __half* __restrict__ Ah, const __half* __restrict__ Bh,
              const float* __restrict__ bias,
              __half* __restrict__ qh, __half* __restrict__ kh,
              __half* __restrict__ vh,
              float* __restrict__ oplain)
{
    extern __shared__ char sm[];
    const uint32_t sbase = smem_u32(sm);
    const int tid = threadIdx.x;
    const int wid = tid >> 5, lane = tid & 31;
    const int wm = wid & 3, wn = wid >> 2;       // 4 M-warps x 2 N-warps
    const int n0 = blockIdx.x * 128;
    const int m0 = blockIdx.y * 128;

    const int a_row = lane & 15;
    const int a_col = (lane >> 4) << 3;
    const int b_row = ((lane >> 4) << 3) + (lane & 7);
    const int b_col = ((lane >> 3) & 1) << 3;

    float c[2][8][4] = {};    // warp tile 32x64

    const int lrow = tid >> 3, lseg = tid & 7;
    const __half* pA0 = Ah + (size_t)(m0 + lrow) * EE + lseg * 8;
    const __half* pB0 = Bh + (size_t)(n0 + lrow) * EE + lseg * 8;
    const uint32_t doff = (uint32_t)(lrow * GP + lseg * 8) * 2;

    auto stage_load = [&](uint32_t bufbase) {
        const uint32_t d0 = bufbase + doff;
        #pragma unroll
        for (int i = 0; i < 4; ++i)
            CP_ASYNC16(d0 + (uint32_t)(i * 32 * GP) * 2, pA0 + (size_t)(i * 32) * EE);
        const uint32_t b0 = d0 + G_ELEMS * 2;
        #pragma unroll
        for (int i = 0; i < 4; ++i)
            CP_ASYNC16(b0 + (uint32_t)(i * 32 * GP) * 2, pB0 + (size_t)(i * 32) * EE);
        CP_COMMIT();
        pA0 += 64; pB0 += 64;
    };

    stage_load(sbase);
    stage_load(sbase + STAGE_BYTES);

    for (int ch = 0; ch < 16; ++ch) {
        if (ch < 15) CP_WAIT(1);
        else         CP_WAIT(0);
        __syncthreads();
        if (ch + 2 < 16) stage_load(sbase + ((ch + 2) % NSTAGE) * STAGE_BYTES);

        const uint32_t sb  = sbase + (ch % NSTAGE) * STAGE_BYTES;
        const uint32_t sAh = sb;
        const uint32_t sBh = sb + G_ELEMS * 2;

        #pragma unroll
        for (int ks = 0; ks < 4; ++ks) {
            uint32_t ah[2][4];
            #pragma unroll
            for (int mi = 0; mi < 2; ++mi) {
                uint32_t off = (uint32_t)((wm * 32 + mi * 16 + a_row) * GP
                                          + ks * 16 + a_col) * 2;
                LDSM4(ah[mi], sAh + off);
            }
            #pragma unroll
            for (int jp = 0; jp < 4; ++jp) {
                uint32_t bb[4];
                uint32_t off = (uint32_t)((wn * 64 + jp * 16 + b_row) * GP
                                          + ks * 16 + b_col) * 2;
                LDSM4(bb, sBh + off);
                #pragma unroll
                for (int mi = 0; mi < 2; ++mi)
                    #pragma unroll
                    for (int t = 0; t < 2; ++t)
                        MMA16816(c[mi][jp * 2 + t], ah[mi], bb[t * 2], bb[t * 2 + 1]);
            }
        }
    }

    const int rbase = m0 + wm * 32 + (lane >> 2);
    const int cpair = (lane & 3) * 2;

    if (MODE == 0) {
        const int which = n0 >> 10;
        __half* dst = (which == 0) ? qh : (which == 1) ? kh : vh;
        const float sc = (which == 0) ? SCALE_Q : 1.0f;
        const int h = ((n0 & 1023) >> 6) + wn;
        #pragma unroll
        for (int mi = 0; mi < 2; ++mi) {
            const int m1 = rbase + mi * 16;
            const int m2 = m1 + 8;
            const size_t base1 = (((size_t)(m1 >> 11) * HH + h) * TT + (m1 & 2047)) * DD;
            const size_t base2 = (((size_t)(m2 >> 11) * HH + h) * TT + (m2 & 2047)) * DD;
            #pragma unroll
            for (int nt = 0; nt < 8; ++nt) {
                const int d = nt * 8 + cpair;
                *(uint32_t*)(dst + base1 + d) = pack_h2(c[mi][nt][0] * sc, c[mi][nt][1] * sc);
                *(uint32_t*)(dst + base2 + d) = pack_h2(c[mi][nt][2] * sc, c[mi][nt][3] * sc);
            }
        }
    } else {
        #pragma unroll
        for (int mi = 0; mi < 2; ++mi) {
            const int m1 = rbase + mi * 16;
            float* r1 = oplain + (size_t)m1 * EE;
            float* r2 = oplain + (size_t)(m1 + 8) * EE;
            #pragma unroll
            for (int nt = 0; nt < 8; ++nt) {
                const int col = n0 + wn * 64 + nt * 8 + cpair;
                const float b0 = bias[col], b1v = bias[col + 1];
                float2 v1 = make_float2(c[mi][nt][0] + b0, c[mi][nt][1] + b1v);
                float2 v2 = make_float2(c[mi][nt][2] + b0, c[mi][nt][3] + b1v);
                *(float2*)(r1 + col) = v1;
                *(float2*)(r2 + col) = v2;
            }
        }
    }
}

// ---------------------------------------------------------------------------
// Tensor-core causal flash attention: 2 CTAs/SM.
// 128-key stages (2 x 64-key subtiles), 2-stage ring, ONE wait+barrier per
// stage (loads for kt2+1 issued before compute of kt2).
// S = Qh.Kh; O = Ph.Vh.  Epilogue: plain fp16 ctx.
// ---------------------------------------------------------------------------
#define AP 72
#define SM_Q 0
#define QARR (128 * AP * 2)
#define SM_STAGE QARR
#define KVARR2 (128 * AP * 2)              // 128 key rows per stage
#define STAGE_SZ (2 * KVARR2)              // K + V = 36864
#define SM_MASK (SM_STAGE + 2 * STAGE_SZ)
#define SM_TOTAL (SM_MASK + 2 * 512)

__global__ __launch_bounds__(256, 2)
void attn_mma(const __half* __restrict__ qh,
              const __half* __restrict__ kh, const __half* __restrict__ vh,
              const float* __restrict__ amask,
              __half* __restrict__ chi)
{
    extern __shared__ char sm[];
    const uint32_t sbase = smem_u32(sm);
    const int tid = threadIdx.x;
    const int w = tid >> 5, lane = tid & 31;
    const int bh = blockIdx.x;
    const int b_ = bh >> 4, h = bh & 15;
    const int qt = 15 - blockIdx.y;
    const int q0 = qt * 128;
    const int last2 = qt;                  // 128-key blocks 0..qt

    const int a_row = lane & 15;
    const int a_col = (lane >> 4) << 3;
    const int b_row = ((lane >> 4) << 3) + (lane & 7);
    const int b_col = ((lane >> 3) & 1) << 3;
    const int v_key = (lane & 7) + (((lane >> 3) & 1) << 3);
    const int v_d   = (lane >> 4) << 3;

    const size_t gbase = (size_t)bh * TT * DD;

    auto load_q = [&]() {
        #pragma unroll
        for (int half = 0; half < 4; ++half) {
            int loc = half * 256 + tid;
            int r = loc >> 3, seg = loc & 7;
            const __half* src = qh + gbase + (size_t)(q0 + r) * DD + seg * 8;
            uint32_t dst = sbase + SM_Q + (uint32_t)(r * AP + seg * 8) * 2;
            CP_ASYNC16(dst, src);
        }
    };
    // load 128 keys of K and V into stage buf
    auto load_kv = [&](int buf, int kt2) {
        const int s0 = kt2 * 128;
        #pragma unroll
        for (int arr = 0; arr < 2; ++arr) {
            const __half* src0 = arr ? vh : kh;
            #pragma unroll
            for (int half = 0; half < 4; ++half) {
                int loc = half * 256 + tid;
                int r = loc >> 3, seg = loc & 7;
                const __half* src = src0 + gbase + (size_t)(s0 + r) * DD + seg * 8;
                uint32_t dst = sbase + SM_STAGE + buf * STAGE_SZ + arr * KVARR2
                             + (uint32_t)(r * AP + seg * 8) * 2;
                CP_ASYNC16(dst, src);
            }
        }
        if (tid < 32) {
            const float* msrc = amask + (size_t)b_ * TT + s0 + tid * 4;
            uint32_t mdst = sbase + SM_MASK + buf * 512 + tid * 16;
            CP_ASYNC16(mdst, msrc);
        }
        CP_COMMIT();
    };

    load_q();
    load_kv(0, 0);      // one group: Q + KV block 0

    uint32_t qa_h[4][4];
    bool qloaded = false;

    float o[8][4] = {};
    float m0r = -1e30f, m1r = -1e30f, l0 = 0.f, l1 = 0.f;
    const int row0 = q0 + w * 16 + (lane >> 2);
    const int wrow_hi = q0 + w * 16 + 15;

    for (int kt2 = 0; kt2 <= last2; ++kt2) {
        CP_WAIT(0);
        __syncthreads();
        // issue next block now; buffer (kt2+1)&1 last read at kt2-1 (barrier-ordered)
        if (kt2 + 1 <= last2) load_kv((kt2 + 1) & 1, kt2 + 1);

        if (!qloaded) {
            #pragma unroll
            for (int ks = 0; ks < 4; ++ks) {
                uint32_t off = (uint32_t)((w * 16 + a_row) * AP + ks * 16 + a_col) * 2;
                LDSM4(qa_h[ks], sbase + SM_Q + off);
            }
            qloaded = true;
        }

        const uint32_t stg = sbase + SM_STAGE + (kt2 & 1) * STAGE_SZ;
        const float* mkbase = (const float*)(sm + SM_MASK + (kt2 & 1) * 512);

        #pragma unroll
        for (int sub = 0; sub < 2; ++sub) {
            const int s0 = kt2 * 128 + sub * 64;
            if (s0 > wrow_hi) continue;
            const int rowoff = sub * 64;

            // ---- S = Qh.Kh ----
            float c[8][4] = {};
            #pragma unroll
            for (int ks = 0; ks < 4; ++ks) {
                #pragma unroll
                for (int hf = 0; hf < 2; ++hf) {
                    uint32_t kf[2][4];
                    #pragma unroll
                    for (int j = 0; j < 2; ++j) {
                        uint32_t off = (uint32_t)((rowoff + (hf * 2 + j) * 16 + b_row) * AP
                                                  + ks * 16 + b_col) * 2;
                        LDSM4(kf[j], stg + off);
                    }
                    #pragma unroll
                    for (int t = 0; t < 4; ++t) {
                        const int nt = hf * 4 + t;
                        const int j = t >> 1, q = (t & 1) * 2;
                        MMA16816(c[nt], qa_h[ks], kf[j][q], kf[j][q + 1]);
                    }
                }
            }
            // ---- mask + causal ----
            const float* mk = mkbase + sub * 64;
            const bool dg = (s0 + 63) > (q0 + w * 16);
            #pragma unroll
            for (int nt = 0; nt < 8; ++nt) {
                const int cl = nt * 8 + (lane & 3) * 2;
                const float mv0 = mk[cl], mv1 = mk[cl + 1];
                const float ma0 = (1.0f - mv0) * -1e30f;
                const float ma1 = (1.0f - mv1) * -1e30f;
                c[nt][0] += ma0; c[nt][1] += ma1;
                c[nt][2] += ma0; c[nt][3] += ma1;
                if (dg) {
                    const int cg = s0 + cl;
                    if (cg     > row0)     c[nt][0] = -1e30f;
                    if (cg + 1 > row0)     c[nt][1] = -1e30f;
                    if (cg     > row0 + 8) c[nt][2] = -1e30f;
                    if (cg + 1 > row0 + 8) c[nt][3] = -1e30f;
                }
            }
            // ---- online softmax ----
            float t0 = -1e30f, t1 = -1e30f;
            #pragma unroll
            for (int nt = 0; nt < 8; ++nt) {
                t0 = fmaxf(t0, fmaxf(c[nt][0], c[nt][1]));
                t1 = fmaxf(t1, fmaxf(c[nt][2], c[nt][3]));
            }
            t0 = fmaxf(t0, __shfl_xor_sync(0xffffffffu, t0, 1));
            t0 = fmaxf(t0, __shfl_xor_sync(0xffffffffu, t0, 2));
            t1 = fmaxf(t1, __shfl_xor_sync(0xffffffffu, t1, 1));
            t1 = fmaxf(t1, __shfl_xor_sync(0xffffffffu, t1, 2));
            const float mn0 = fmaxf(m0r, t0), mn1 = fmaxf(m1r, t1);
            const float cor0 = exp2fast(m0r - mn0), cor1 = exp2fast(m1r - mn1);
            m0r = mn0; m1r = mn1;
            l0 *= cor0; l1 *= cor1;
            #pragma unroll
            for (int nt = 0; nt < 8; ++nt) {
                o[nt][0] *= cor0; o[nt][1] *= cor0;
                o[nt][2] *= cor1; o[nt][3] *= cor1;
            }
            // ---- P = exp2(S - m), O += Ph.Vh ----
            float s0sum = 0.f, s1sum = 0.f;
            #pragma unroll
            for (int ks = 0; ks < 4; ++ks) {
                uint32_t pa[4];
                #pragma unroll
                for (int t = 0; t < 2; ++t) {
                    const int nt = ks * 2 + t;
                    const float p0 = exp2fast(c[nt][0] - mn0);
                    const float p1 = exp2fast(c[nt][1] - mn0);
                    const float p2 = exp2fast(c[nt][2] - mn1);
                    const float p3 = exp2fast(c[nt][3] - mn1);
                    s0sum += p0 + p1; s1sum += p2 + p3;
                    pa[t * 2]     = pack_h2(p0, p1);
                    pa[t * 2 + 1] = pack_h2(p2, p3);
                }
                #pragma unroll
                for (int hf = 0; hf < 2; ++hf) {
                    uint32_t vf[2][4];
                    #pragma unroll
                    for (int j = 0; j < 2; ++j) {
                        uint32_t off = (uint32_t)((rowoff + ks * 16 + v_key) * AP
                                                  + (hf * 2 + j) * 16 + v_d) * 2;
                        LDSM4T(vf[j], stg + KVARR2 + off);
                    }
                    #pragma unroll
                    for (int t = 0; t < 4; ++t) {
                        const int nt = hf * 4 + t;
                        const int j = t >> 1, q = (t & 1) * 2;
                        MMA16816(o[nt], pa, vf[j][q], vf[j][q + 1]);
                    }
                }
            }
            s0sum += __shfl_xor_sync(0xffffffffu, s0sum, 1);
            s0sum += __shfl_xor_sync(0xffffffffu, s0sum, 2);
            s1sum += __shfl_xor_sync(0xffffffffu, s1sum, 1);
            s1sum += __shfl_xor_sync(0xffffffffu, s1sum, 2);
            l0 += s0sum; l1 += s1sum;
        }
    }

    // ---- normalize + store fp16 ctx [B,T,E] ----
    const float inv0 = 1.0f / l0, inv1 = 1.0f / l1;
    const int cpair = (lane & 3) * 2;
    const size_t r1 = ((size_t)b_ * TT + row0) * EE + h * 64;
    const size_t r2 = ((size_t)b_ * TT + row0 + 8) * EE + h * 64;
    #pragma unroll
    for (int nt = 0; nt < 8; ++nt) {
        const int d = nt * 8 + cpair;
        *(uint32_t*)(chi + r1 + d) = pack_h2(o[nt][0] * inv0, o[nt][1] * inv0);
        *(uint32_t*)(chi + r2 + d) = pack_h2(o[nt][2] * inv1, o[nt][3] * inv1);
    }
}

// ---------------------------------------------------------------------------
// Launch
// ---------------------------------------------------------------------------
extern "C" void kernel_launch(void* const* d_in, const int* in_sizes, int n_in,
                              void* d_out, int out_size)
{
    const float* x     = (const float*)d_in[0];
    const float* amask = (const float*)d_in[1];
    const float* Wq    = (const float*)d_in[2];
    const float* Wk    = (const float*)d_in[3];
    const float* Wv    = (const float*)d_in[4];
    const float* Wo    = (const float*)d_in[5];
    const float* bo    = (const float*)d_in[6];
    float* out = (float*)d_out;

    __half *xhi, *wth, *woh, *chi;
    __half *qh, *kh, *vh;
    cudaGetSymbolAddress((void**)&xhi, g_xhi);
    cudaGetSymbolAddress((void**)&wth, g_wth);
    cudaGetSymbolAddress((void**)&woh, g_woh);
    cudaGetSymbolAddress((void**)&chi, g_chi);
    cudaGetSymbolAddress((void**)&qh,  g_qh);
    cudaGetSymbolAddress((void**)&kh,  g_kh);
    cudaGetSymbolAddress((void**)&vh,  g_vh);

    cudaFuncSetAttribute(mma_gemm<0>, cudaFuncAttributeMaxDynamicSharedMemorySize,
                         NSTAGE * STAGE_BYTES);
    cudaFuncSetAttribute(mma_gemm<1>, cudaFuncAttributeMaxDynamicSharedMemorySize,
                         NSTAGE * STAGE_BYTES);
    cudaFuncSetAttribute(attn_mma, cudaFuncAttributeMaxDynamicSharedMemorySize,
                         SM_TOTAL);

    prep_all<<<PREP_GRID, 256>>>(x, Wq, Wk, Wv, Wo, xhi, woh, wth);

    {   // QKV projection (1-pass)
        dim3 grid(NQKV / 128, BT / 128);
        mma_gemm<0><<<grid, 256, NSTAGE * STAGE_BYTES>>>(xhi, wth, nullptr,
                                                         qh, kh, vh, nullptr);
    }
    {   // attention (1-pass) -> fp16 ctx
        dim3 grid(BB * HH, TT / 128);
        attn_mma<<<grid, 256, SM_TOTAL>>>(qh, kh, vh, amask, chi);
    }
    {   // output projection (1-pass) + bias
        dim3 grid(EE / 128, BT / 128);
        mma_gemm<1><<<grid, 256, NSTAGE * STAGE_BYTES>>>(chi, woh, bo,
                                                         nullptr, nullptr, nullptr,
                                                         out);
    }
}